// round 1
// baseline (speedup 1.0000x reference)
#include <cuda_runtime.h>
#include <math.h>

// Problem constants
#define HH 64
#define WW 64
#define NN 4096            // H*W
#define CC 256
#define NHEADS 8
#define HDIM 32

// ---------------- scratch (device globals; no allocation allowed) ----------
__device__ float g_part[8 * 2 * NN];     // per-channel-group partial offset sums
__device__ float g_ixy[2 * NN];          // ix, iy (pixel-space sample coords)
__device__ float g_xs[CC * NN];          // x_sampled
__device__ float g_q[CC * NN];
__device__ float g_k[CC * NN];
__device__ float g_v[CC * NN];
__device__ float g_ao[CC * NN];          // attention output before wo

// ---------------------------------------------------------------------------
// Kernel 1: multi-scale depthwise conv -> relu -> offset projection (partial)
// grid (16, 8) x 256 threads. Block (bx, bz): pixels bx*256.., channels bz*32..
// ---------------------------------------------------------------------------
__global__ __launch_bounds__(256)
void conv_offset_kernel(const float* __restrict__ x,
                        const float* __restrict__ ow,
                        const float* __restrict__ w3,
                        const float* __restrict__ w5,
                        const float* __restrict__ w7,
                        const float* __restrict__ wproj)
{
    int p  = blockIdx.x * 256 + threadIdx.x;   // pixel id
    int cz = blockIdx.y * 32;
    int py = p >> 6, px = p & 63;
    float ow0 = ow[0], ow1 = ow[1], ow2 = ow[2];

    float a0 = 0.f, a1 = 0.f;
    for (int c = cz; c < cz + 32; c++) {
        const float* xc = x + c * NN;
        float feat = 0.f;
#pragma unroll
        for (int j = 0; j < 7; j++) {
            int yy = py + j - 3;
            bool yok = (yy >= 0) & (yy < HH);
#pragma unroll
            for (int i = 0; i < 7; i++) {
                int xx = px + i - 3;
                // combined weight (uniform across threads -> broadcast loads)
                float wsum = __ldg(&w7[c * 49 + j * 7 + i]) * ow2;
                if (j >= 1 && j <= 5 && i >= 1 && i <= 5)
                    wsum += __ldg(&w5[c * 25 + (j - 1) * 5 + (i - 1)]) * ow1;
                if (j >= 2 && j <= 4 && i >= 2 && i <= 4)
                    wsum += __ldg(&w3[c * 9 + (j - 2) * 3 + (i - 2)]) * ow0;
                float v = (yok && xx >= 0 && xx < WW) ? xc[yy * WW + xx] : 0.f;
                feat += v * wsum;
            }
        }
        feat = fmaxf(feat, 0.f);
        a0 += feat * __ldg(&wproj[c]);           // w_offproj[0][c] -> y offset
        a1 += feat * __ldg(&wproj[CC + c]);      // w_offproj[1][c] -> x offset
    }
    g_part[(blockIdx.y * 2 + 0) * NN + p] = a0;
    g_part[(blockIdx.y * 2 + 1) * NN + p] = a1;
}

// ---------------------------------------------------------------------------
// Kernel 2: reduce partials, tanh, build sample coordinates (pixel space)
// ---------------------------------------------------------------------------
__global__ __launch_bounds__(256)
void grid_kernel()
{
    int p = blockIdx.x * 256 + threadIdx.x;
    int py = p >> 6, px = p & 63;
    float offy = 0.f, offx = 0.f;
#pragma unroll
    for (int g = 0; g < 8; g++) {
        offy += g_part[(g * 2 + 0) * NN + p];
        offx += g_part[(g * 2 + 1) * NN + p];
    }
    float refy = ((py + 0.5f) / 63.0f) * 2.0f - 1.0f;
    float refx = ((px + 0.5f) / 63.0f) * 2.0f - 1.0f;
    float gy = fminf(fmaxf(refy + tanhf(offy) * 2.0f, -1.0f), 1.0f);
    float gx = fminf(fmaxf(refx + tanhf(offx) * 2.0f, -1.0f), 1.0f);
    g_ixy[p]      = (gx + 1.0f) * 0.5f * 63.0f;   // ix
    g_ixy[NN + p] = (gy + 1.0f) * 0.5f * 63.0f;   // iy
}

// ---------------------------------------------------------------------------
// Kernel 3: bilinear grid sample.  grid (16, 256) x 256: (pixel, channel)
// ---------------------------------------------------------------------------
__global__ __launch_bounds__(256)
void sample_kernel(const float* __restrict__ x)
{
    int p = blockIdx.x * 256 + threadIdx.x;
    int c = blockIdx.y;
    float ix = g_ixy[p], iy = g_ixy[NN + p];
    float x0f = floorf(ix), y0f = floorf(iy);
    float fx = ix - x0f, fy = iy - y0f;
    int x0 = min(max((int)x0f, 0), WW - 1);
    int x1 = min(x0 + 1, WW - 1);
    int y0 = min(max((int)y0f, 0), HH - 1);
    int y1 = min(y0 + 1, HH - 1);
    const float* xc = x + c * NN;
    float v00 = xc[y0 * WW + x0], v01 = xc[y0 * WW + x1];
    float v10 = xc[y1 * WW + x0], v11 = xc[y1 * WW + x1];
    g_xs[c * NN + p] = v00 * (1.f - fx) * (1.f - fy) + v01 * fx * (1.f - fy)
                     + v10 * (1.f - fx) * fy + v11 * fx * fy;
}

// ---------------------------------------------------------------------------
// Kernel 4: SGEMM  C[256,4096] = A[256,256] * B[256,4096]
// 64x64 tile, BK=16, 256 threads, 4x4 microtile.
// bsrc: 0 = Bext, 1 = g_xs, 2 = g_ao ; cdst: 0=g_q 1=g_k 2=g_v 3=Cext
// ---------------------------------------------------------------------------
__global__ __launch_bounds__(256)
void sgemm_k(const float* __restrict__ A, int bsrc, int cdst,
             const float* __restrict__ Bext, float* __restrict__ Cext)
{
    const float* B = (bsrc == 0) ? Bext : (bsrc == 1) ? g_xs : g_ao;
    float* C = (cdst == 0) ? g_q : (cdst == 1) ? g_k : (cdst == 2) ? g_v : Cext;

    __shared__ float As[16][68];   // [k][m], padded
    __shared__ float Bs[16][64];   // [k][n]

    int n0 = blockIdx.x * 64, m0 = blockIdx.y * 64;
    int t = threadIdx.x;
    int tx = t & 15, ty = t >> 4;

    float acc[4][4];
#pragma unroll
    for (int i = 0; i < 4; i++)
#pragma unroll
        for (int j = 0; j < 4; j++) acc[i][j] = 0.f;

    for (int kk = 0; kk < 256; kk += 16) {
        __syncthreads();
#pragma unroll
        for (int idx = t; idx < 1024; idx += 256) {
            int k = idx & 15, mm = idx >> 4;
            As[k][mm] = A[(m0 + mm) * 256 + kk + k];
        }
#pragma unroll
        for (int idx = t; idx < 1024; idx += 256) {
            int n = idx & 63, k2 = idx >> 6;
            Bs[k2][n] = B[(kk + k2) * NN + n0 + n];
        }
        __syncthreads();
#pragma unroll
        for (int k = 0; k < 16; k++) {
            float4 a = *(const float4*)&As[k][ty * 4];
            float4 b = *(const float4*)&Bs[k][tx * 4];
            float av[4] = {a.x, a.y, a.z, a.w};
            float bv[4] = {b.x, b.y, b.z, b.w};
#pragma unroll
            for (int i = 0; i < 4; i++)
#pragma unroll
                for (int j = 0; j < 4; j++)
                    acc[i][j] += av[i] * bv[j];
        }
    }
#pragma unroll
    for (int i = 0; i < 4; i++) {
        float4 o = make_float4(acc[i][0], acc[i][1], acc[i][2], acc[i][3]);
        *(float4*)&C[(m0 + ty * 4 + i) * NN + n0 + tx * 4] = o;
    }
}

// ---------------------------------------------------------------------------
// Kernel 5: flash attention with Manhattan-decay bias (computed inline)
// grid (64 query-blocks, 8 heads) x 256 threads (8 warps, 8 rows/warp).
// ---------------------------------------------------------------------------
__global__ __launch_bounds__(256)
void flash_kernel(const float* __restrict__ beta_p)
{
    __shared__ float Qs[64][33];   // [row][d]
    __shared__ float Ks[32][65];   // [d][col]
    __shared__ float Vs[32][65];   // [d][col]
    __shared__ float Ps[64][65];   // [row][col], per-warp private rows

    int qb = blockIdx.x, h = blockIdx.y;
    int t = threadIdx.x, w = t >> 5, lane = t & 31;
    int n0 = qb * 64;
    int lr0 = w * 8;

    float invb = 1.0f / (fabsf(beta_p[0]) + 1e-6f);
    const float scale = 0.17677669529663687f;   // 32^-0.5

    const float* gq = g_q + h * HDIM * NN;
    const float* gk = g_k + h * HDIM * NN;
    const float* gv = g_v + h * HDIM * NN;

    // load Q tile (coalesced along n)
    for (int idx = t; idx < 64 * HDIM; idx += 256) {
        int d = idx >> 6, r = idx & 63;
        Qs[r][d] = gq[d * NN + n0 + r];
    }

    float acc[8], m[8], l[8];
    int qy[8], qx[8];
#pragma unroll
    for (int j = 0; j < 8; j++) {
        acc[j] = 0.f; m[j] = -1e30f; l[j] = 0.f;
        int nq = n0 + lr0 + j;
        qy[j] = nq >> 6; qx[j] = nq & 63;
    }

    for (int kb = 0; kb < 64; kb++) {
        __syncthreads();
        for (int idx = t; idx < 64 * HDIM; idx += 256) {
            int d = idx >> 6, c = idx & 63;
            Ks[d][c] = gk[d * NN + kb * 64 + c];
            Vs[d][c] = gv[d * NN + kb * 64 + c];
        }
        __syncthreads();

        // ---- S = Q K (8 rows jointly, 2 cols per lane) ----
        float s0[8], s1[8];
#pragma unroll
        for (int j = 0; j < 8; j++) { s0[j] = 0.f; s1[j] = 0.f; }
#pragma unroll
        for (int d = 0; d < HDIM; d++) {
            float k0 = Ks[d][lane];
            float k1 = Ks[d][lane + 32];
#pragma unroll
            for (int j = 0; j < 8; j++) {
                float q = Qs[lr0 + j][d];
                s0[j] += q * k0;
                s1[j] += q * k1;
            }
        }

        int nk0 = kb * 64 + lane, nk1 = nk0 + 32;
        int ky0 = nk0 >> 6, kx0 = nk0 & 63;
        int ky1 = nk1 >> 6, kx1 = nk1 & 63;

        // ---- online softmax per row ----
#pragma unroll
        for (int j = 0; j < 8; j++) {
            float b0 = __expf(-(float)(abs(qy[j] - ky0) + abs(qx[j] - kx0)) * invb);
            float b1 = __expf(-(float)(abs(qy[j] - ky1) + abs(qx[j] - kx1)) * invb);
            float v0 = s0[j] * scale + b0;
            float v1 = s1[j] * scale + b1;
            float mloc = fmaxf(v0, v1);
#pragma unroll
            for (int o = 16; o > 0; o >>= 1)
                mloc = fmaxf(mloc, __shfl_xor_sync(0xffffffffu, mloc, o));
            float mn  = fmaxf(m[j], mloc);
            float fac = __expf(m[j] - mn);
            float p0 = __expf(v0 - mn);
            float p1 = __expf(v1 - mn);
            float ps = p0 + p1;
#pragma unroll
            for (int o = 16; o > 0; o >>= 1)
                ps += __shfl_xor_sync(0xffffffffu, ps, o);
            l[j] = l[j] * fac + ps;
            m[j] = mn;
            acc[j] *= fac;
            Ps[lr0 + j][lane] = p0;
            Ps[lr0 + j][lane + 32] = p1;
        }
        __syncwarp();

        // ---- PV: acc[j] (dim = lane) += sum_c P[row,c] * V[lane,c] ----
#pragma unroll 4
        for (int c = 0; c < 64; c++) {
            float v = Vs[lane][c];
#pragma unroll
            for (int j = 0; j < 8; j++)
                acc[j] += Ps[lr0 + j][c] * v;
        }
    }

    // stage normalized output through smem for coalesced global writes
    __syncthreads();
#pragma unroll
    for (int j = 0; j < 8; j++)
        Ps[lr0 + j][lane] = acc[j] / l[j];
    __syncthreads();
    float* go = g_ao + h * HDIM * NN;
    for (int idx = t; idx < 64 * HDIM; idx += 256) {
        int d = idx >> 6, r = idx & 63;
        go[d * NN + n0 + r] = Ps[r][d];
    }
}

// ---------------------------------------------------------------------------
extern "C" void kernel_launch(void* const* d_in, const int* in_sizes, int n_in,
                              void* d_out, int out_size)
{
    const float* x   = (const float*)d_in[0];
    const float* ow  = (const float*)d_in[1];
    const float* w3  = (const float*)d_in[2];
    const float* w5  = (const float*)d_in[3];
    const float* w7  = (const float*)d_in[4];
    const float* wop = (const float*)d_in[5];
    const float* wq  = (const float*)d_in[6];
    const float* wk  = (const float*)d_in[7];
    const float* wv  = (const float*)d_in[8];
    const float* wo  = (const float*)d_in[9];
    const float* beta = (const float*)d_in[10];
    float* out = (float*)d_out;

    conv_offset_kernel<<<dim3(16, 8), 256>>>(x, ow, w3, w5, w7, wop);
    grid_kernel<<<16, 256>>>();
    sample_kernel<<<dim3(16, 256), 256>>>(x);

    sgemm_k<<<dim3(64, 4), 256>>>(wq, 0, 0, x, nullptr);       // q = wq @ x
    sgemm_k<<<dim3(64, 4), 256>>>(wk, 1, 1, nullptr, nullptr); // k = wk @ xs
    sgemm_k<<<dim3(64, 4), 256>>>(wv, 1, 2, nullptr, nullptr); // v = wv @ xs

    flash_kernel<<<dim3(64, 8), 256>>>(beta);

    sgemm_k<<<dim3(64, 4), 256>>>(wo, 2, 3, nullptr, out);     // out = wo @ ao
}

// round 2
// speedup vs baseline: 1.8635x; 1.8635x over previous
#include <cuda_runtime.h>
#include <math.h>
#include <stdint.h>

// Problem constants
#define HH 64
#define WW 64
#define NN 4096            // H*W
#define CC 256
#define NHEADS 8
#define HDIM 32

// ---------------- scratch (device globals; no allocation allowed) ----------
__device__ float g_part[8 * 2 * NN];     // per-channel-group partial offset sums
__device__ float g_ixy[2 * NN];          // ix, iy (pixel-space sample coords)
__device__ float g_xs[CC * NN];          // x_sampled
__device__ float g_q[CC * NN];
__device__ float g_k[CC * NN];
__device__ float g_v[CC * NN];
__device__ float g_ao[CC * NN];          // attention output before wo

// ---------------------------------------------------------------------------
// Kernel 1: multi-scale depthwise conv -> relu -> offset projection (partial)
// ---------------------------------------------------------------------------
__global__ __launch_bounds__(256)
void conv_offset_kernel(const float* __restrict__ x,
                        const float* __restrict__ ow,
                        const float* __restrict__ w3,
                        const float* __restrict__ w5,
                        const float* __restrict__ w7,
                        const float* __restrict__ wproj)
{
    int p  = blockIdx.x * 256 + threadIdx.x;   // pixel id
    int cz = blockIdx.y * 32;
    int py = p >> 6, px = p & 63;
    float ow0 = ow[0], ow1 = ow[1], ow2 = ow[2];

    float a0 = 0.f, a1 = 0.f;
    for (int c = cz; c < cz + 32; c++) {
        const float* xc = x + c * NN;
        float feat = 0.f;
#pragma unroll
        for (int j = 0; j < 7; j++) {
            int yy = py + j - 3;
            bool yok = (yy >= 0) & (yy < HH);
#pragma unroll
            for (int i = 0; i < 7; i++) {
                int xx = px + i - 3;
                float wsum = __ldg(&w7[c * 49 + j * 7 + i]) * ow2;
                if (j >= 1 && j <= 5 && i >= 1 && i <= 5)
                    wsum += __ldg(&w5[c * 25 + (j - 1) * 5 + (i - 1)]) * ow1;
                if (j >= 2 && j <= 4 && i >= 2 && i <= 4)
                    wsum += __ldg(&w3[c * 9 + (j - 2) * 3 + (i - 2)]) * ow0;
                float v = (yok && xx >= 0 && xx < WW) ? xc[yy * WW + xx] : 0.f;
                feat += v * wsum;
            }
        }
        feat = fmaxf(feat, 0.f);
        a0 += feat * __ldg(&wproj[c]);
        a1 += feat * __ldg(&wproj[CC + c]);
    }
    g_part[(blockIdx.y * 2 + 0) * NN + p] = a0;
    g_part[(blockIdx.y * 2 + 1) * NN + p] = a1;
}

// ---------------------------------------------------------------------------
// Kernel 2: reduce partials, tanh, build sample coordinates (pixel space)
// ---------------------------------------------------------------------------
__global__ __launch_bounds__(256)
void grid_kernel()
{
    int p = blockIdx.x * 256 + threadIdx.x;
    int py = p >> 6, px = p & 63;
    float offy = 0.f, offx = 0.f;
#pragma unroll
    for (int g = 0; g < 8; g++) {
        offy += g_part[(g * 2 + 0) * NN + p];
        offx += g_part[(g * 2 + 1) * NN + p];
    }
    float refy = ((py + 0.5f) / 63.0f) * 2.0f - 1.0f;
    float refx = ((px + 0.5f) / 63.0f) * 2.0f - 1.0f;
    float gy = fminf(fmaxf(refy + tanhf(offy) * 2.0f, -1.0f), 1.0f);
    float gx = fminf(fmaxf(refx + tanhf(offx) * 2.0f, -1.0f), 1.0f);
    g_ixy[p]      = (gx + 1.0f) * 0.5f * 63.0f;   // ix
    g_ixy[NN + p] = (gy + 1.0f) * 0.5f * 63.0f;   // iy
}

// ---------------------------------------------------------------------------
// Kernel 3: bilinear grid sample
// ---------------------------------------------------------------------------
__global__ __launch_bounds__(256)
void sample_kernel(const float* __restrict__ x)
{
    int p = blockIdx.x * 256 + threadIdx.x;
    int c = blockIdx.y;
    float ix = g_ixy[p], iy = g_ixy[NN + p];
    float x0f = floorf(ix), y0f = floorf(iy);
    float fx = ix - x0f, fy = iy - y0f;
    int x0 = min(max((int)x0f, 0), WW - 1);
    int x1 = min(x0 + 1, WW - 1);
    int y0 = min(max((int)y0f, 0), HH - 1);
    int y1 = min(y0 + 1, HH - 1);
    const float* xc = x + c * NN;
    float v00 = xc[y0 * WW + x0], v01 = xc[y0 * WW + x1];
    float v10 = xc[y1 * WW + x0], v11 = xc[y1 * WW + x1];
    g_xs[c * NN + p] = v00 * (1.f - fx) * (1.f - fy) + v01 * fx * (1.f - fy)
                     + v10 * (1.f - fx) * fy + v11 * fx * fy;
}

// ---------------------------------------------------------------------------
// Kernel 4: SGEMM  C[256,4096] = A[256,256] * B[256,4096]
// ---------------------------------------------------------------------------
__global__ __launch_bounds__(256)
void sgemm_k(const float* __restrict__ A, int bsrc, int cdst,
             const float* __restrict__ Bext, float* __restrict__ Cext)
{
    const float* B = (bsrc == 0) ? Bext : (bsrc == 1) ? g_xs : g_ao;
    float* C = (cdst == 0) ? g_q : (cdst == 1) ? g_k : (cdst == 2) ? g_v : Cext;

    __shared__ float As[16][68];
    __shared__ float Bs[16][64];

    int n0 = blockIdx.x * 64, m0 = blockIdx.y * 64;
    int t = threadIdx.x;
    int tx = t & 15, ty = t >> 4;

    float acc[4][4];
#pragma unroll
    for (int i = 0; i < 4; i++)
#pragma unroll
        for (int j = 0; j < 4; j++) acc[i][j] = 0.f;

    for (int kk = 0; kk < 256; kk += 16) {
        __syncthreads();
#pragma unroll
        for (int idx = t; idx < 1024; idx += 256) {
            int k = idx & 15, mm = idx >> 4;
            As[k][mm] = A[(m0 + mm) * 256 + kk + k];
        }
#pragma unroll
        for (int idx = t; idx < 1024; idx += 256) {
            int n = idx & 63, k2 = idx >> 6;
            Bs[k2][n] = B[(kk + k2) * NN + n0 + n];
        }
        __syncthreads();
#pragma unroll
        for (int k = 0; k < 16; k++) {
            float4 a = *(const float4*)&As[k][ty * 4];
            float4 b = *(const float4*)&Bs[k][tx * 4];
            float av[4] = {a.x, a.y, a.z, a.w};
            float bv[4] = {b.x, b.y, b.z, b.w};
#pragma unroll
            for (int i = 0; i < 4; i++)
#pragma unroll
                for (int j = 0; j < 4; j++)
                    acc[i][j] += av[i] * bv[j];
        }
    }
#pragma unroll
    for (int i = 0; i < 4; i++) {
        float4 o = make_float4(acc[i][0], acc[i][1], acc[i][2], acc[i][3]);
        *(float4*)&C[(m0 + ty * 4 + i) * NN + n0 + tx * 4] = o;
    }
}

// ---------------------------------------------------------------------------
// Kernel 5: tensor-core flash attention (tf32 mma.sync) + decay LUT
// grid (64 q-blocks, 8 heads) x 256 threads (8 warps).
// warp w: rows (w&3)*16..+16, key-column half (w>>2)*32 of each 64-key block.
// Split-key online softmax; two halves merged at the end.
// ---------------------------------------------------------------------------
__device__ __forceinline__ float tf32r(float x) {
    asm("cvt.rna.tf32.f32 %0, %0;" : "+f"(x));
    return x;
}

__device__ __forceinline__ void mma_tf32(float c[4], const uint32_t a[4],
                                         uint32_t b0, uint32_t b1) {
    asm volatile(
        "mma.sync.aligned.m16n8k8.row.col.f32.tf32.tf32.f32 "
        "{%0,%1,%2,%3},{%4,%5,%6,%7},{%8,%9},{%0,%1,%2,%3};"
        : "+f"(c[0]), "+f"(c[1]), "+f"(c[2]), "+f"(c[3])
        : "r"(a[0]), "r"(a[1]), "r"(a[2]), "r"(a[3]), "r"(b0), "r"(b1));
}

__global__ __launch_bounds__(256)
void flash_tc(const float* __restrict__ beta_p)
{
    __shared__ float Ks[32][68];   // [d][col], tf32; frag reads conflict-free
    __shared__ float Vs[64][36];   // [m][d],  tf32; frag reads conflict-free
    __shared__ float Ps[64][68];   // P scratch; reused for O merge
    __shared__ float Lut[128];     // exp(-dist/|beta|)
    __shared__ float Msm[64], Lsm[64];

    int t = threadIdx.x, w = t >> 5, lane = t & 31;
    int mg = (w & 3) * 16;         // warp's row offset within the 64-row tile
    int ch = w >> 2;               // key-column half (0 or 1)
    int cb = ch * 32;
    int n0 = blockIdx.x * 64;
    int h  = blockIdx.y;
    int g  = lane >> 2, kq = lane & 3;

    float invb = 1.0f / (fabsf(beta_p[0]) + 1e-6f);
    const float scale = 0.17677669529663687f;   // 32^-0.5
    if (t < 127) Lut[t] = __expf(-(float)t * invb);

    const float* gq = g_q + h * HDIM * NN;
    const float* gk = g_k + h * HDIM * NN;
    const float* gv = g_v + h * HDIM * NN;

    int row0 = n0 + mg + g;
    int row1 = row0 + 8;
    int qy0 = row0 >> 6, qx0 = row0 & 63;
    int qy1 = row1 >> 6, qx1 = row1 & 63;

    // Q fragments, held in registers the whole kernel (16 regs)
    uint32_t qa[4][4];
#pragma unroll
    for (int kt = 0; kt < 4; kt++) {
        int d0 = kt * 8 + kq;
        qa[kt][0] = __float_as_uint(tf32r(gq[d0 * NN + row0]));
        qa[kt][1] = __float_as_uint(tf32r(gq[d0 * NN + row1]));
        qa[kt][2] = __float_as_uint(tf32r(gq[(d0 + 4) * NN + row0]));
        qa[kt][3] = __float_as_uint(tf32r(gq[(d0 + 4) * NN + row1]));
    }

    float o[4][4];
#pragma unroll
    for (int i = 0; i < 4; i++)
#pragma unroll
        for (int j = 0; j < 4; j++) o[i][j] = 0.f;
    float m0 = -1e30f, m1 = -1e30f, l0 = 0.f, l1 = 0.f;

    for (int kb = 0; kb < 64; kb++) {
        __syncthreads();
        for (int idx = t; idx < 2048; idx += 256) {
            int d = idx >> 6, c = idx & 63;
            Ks[d][c] = tf32r(gk[d * NN + kb * 64 + c]);
            Vs[c][d] = tf32r(gv[d * NN + kb * 64 + c]);
        }
        __syncthreads();

        // ---- S = Q K^T on this warp's 16x32 tile ----
        float s[4][4];
#pragma unroll
        for (int i = 0; i < 4; i++)
#pragma unroll
            for (int j = 0; j < 4; j++) s[i][j] = 0.f;
#pragma unroll
        for (int kt = 0; kt < 4; kt++) {
#pragma unroll
            for (int nt = 0; nt < 4; nt++) {
                uint32_t b0 = __float_as_uint(Ks[kt * 8 + kq][cb + nt * 8 + g]);
                uint32_t b1 = __float_as_uint(Ks[kt * 8 + kq + 4][cb + nt * 8 + g]);
                mma_tf32(s[nt], qa[kt], b0, b1);
            }
        }

        // ---- bias via LUT + online softmax (rows g and g+8) ----
        float mn0 = m0, mn1 = m1;
#pragma unroll
        for (int nt = 0; nt < 4; nt++) {
#pragma unroll
            for (int e = 0; e < 2; e++) {
                int col = kb * 64 + cb + nt * 8 + 2 * kq + e;
                int ky = col >> 6, kx = col & 63;
                float b0v = Lut[abs(qy0 - ky) + abs(qx0 - kx)];
                float b1v = Lut[abs(qy1 - ky) + abs(qx1 - kx)];
                s[nt][e]     = s[nt][e]     * scale + b0v;
                s[nt][e + 2] = s[nt][e + 2] * scale + b1v;
                mn0 = fmaxf(mn0, s[nt][e]);
                mn1 = fmaxf(mn1, s[nt][e + 2]);
            }
        }
        mn0 = fmaxf(mn0, __shfl_xor_sync(0xffffffffu, mn0, 1));
        mn0 = fmaxf(mn0, __shfl_xor_sync(0xffffffffu, mn0, 2));
        mn1 = fmaxf(mn1, __shfl_xor_sync(0xffffffffu, mn1, 1));
        mn1 = fmaxf(mn1, __shfl_xor_sync(0xffffffffu, mn1, 2));

        float fac0 = __expf(m0 - mn0);
        float fac1 = __expf(m1 - mn1);
        m0 = mn0; m1 = mn1;

        float ls0 = 0.f, ls1 = 0.f;
#pragma unroll
        for (int nt = 0; nt < 4; nt++) {
#pragma unroll
            for (int e = 0; e < 2; e++) {
                float p0 = __expf(s[nt][e] - m0);
                float p1 = __expf(s[nt][e + 2] - m1);
                s[nt][e] = p0;  s[nt][e + 2] = p1;
                ls0 += p0;      ls1 += p1;
            }
        }
        ls0 += __shfl_xor_sync(0xffffffffu, ls0, 1);
        ls0 += __shfl_xor_sync(0xffffffffu, ls0, 2);
        ls1 += __shfl_xor_sync(0xffffffffu, ls1, 1);
        ls1 += __shfl_xor_sync(0xffffffffu, ls1, 2);
        l0 = l0 * fac0 + ls0;
        l1 = l1 * fac1 + ls1;

#pragma unroll
        for (int nt = 0; nt < 4; nt++) {
            o[nt][0] *= fac0; o[nt][1] *= fac0;
            o[nt][2] *= fac1; o[nt][3] *= fac1;
        }

        // ---- stage P through smem to re-shape into A fragments ----
#pragma unroll
        for (int nt = 0; nt < 4; nt++) {
            int c0 = cb + nt * 8 + 2 * kq;
            Ps[mg + g][c0]         = tf32r(s[nt][0]);
            Ps[mg + g][c0 + 1]     = tf32r(s[nt][1]);
            Ps[mg + g + 8][c0]     = tf32r(s[nt][2]);
            Ps[mg + g + 8][c0 + 1] = tf32r(s[nt][3]);
        }
        __syncwarp();

        // ---- O += P V ----
#pragma unroll
        for (int kt2 = 0; kt2 < 4; kt2++) {
            uint32_t a[4];
            a[0] = __float_as_uint(Ps[mg + g][cb + kt2 * 8 + kq]);
            a[1] = __float_as_uint(Ps[mg + g + 8][cb + kt2 * 8 + kq]);
            a[2] = __float_as_uint(Ps[mg + g][cb + kt2 * 8 + kq + 4]);
            a[3] = __float_as_uint(Ps[mg + g + 8][cb + kt2 * 8 + kq + 4]);
#pragma unroll
            for (int nt2 = 0; nt2 < 4; nt2++) {
                uint32_t b0 = __float_as_uint(Vs[cb + kt2 * 8 + kq][nt2 * 8 + g]);
                uint32_t b1 = __float_as_uint(Vs[cb + kt2 * 8 + kq + 4][nt2 * 8 + g]);
                mma_tf32(o[nt2], a, b0, b1);
            }
        }
    }

    // ---- merge the two key-halves (split-softmax combine) ----
    __syncthreads();
    if (ch == 1) {
        Msm[mg + g] = m0;  Msm[mg + g + 8] = m1;
        Lsm[mg + g] = l0;  Lsm[mg + g + 8] = l1;
#pragma unroll
        for (int nt = 0; nt < 4; nt++) {
            int d0 = nt * 8 + 2 * kq;
            Ps[mg + g][d0]         = o[nt][0];
            Ps[mg + g][d0 + 1]     = o[nt][1];
            Ps[mg + g + 8][d0]     = o[nt][2];
            Ps[mg + g + 8][d0 + 1] = o[nt][3];
        }
    }
    __syncthreads();
    if (ch == 0) {
        float mb0 = Msm[mg + g],     lb0 = Lsm[mg + g];
        float mb1 = Msm[mg + g + 8], lb1 = Lsm[mg + g + 8];
        float M0 = fmaxf(m0, mb0), M1 = fmaxf(m1, mb1);
        float fa0 = __expf(m0 - M0), fb0 = __expf(mb0 - M0);
        float fa1 = __expf(m1 - M1), fb1 = __expf(mb1 - M1);
        float L0 = l0 * fa0 + lb0 * fb0;
        float L1 = l1 * fa1 + lb1 * fb1;
        float iL0 = 1.0f / L0, iL1 = 1.0f / L1;
#pragma unroll
        for (int nt = 0; nt < 4; nt++) {
            int d0 = nt * 8 + 2 * kq;
            float ob0 = Ps[mg + g][d0],     ob1 = Ps[mg + g][d0 + 1];
            float ob2 = Ps[mg + g + 8][d0], ob3 = Ps[mg + g + 8][d0 + 1];
            Ps[mg + g][d0]         = (o[nt][0] * fa0 + ob0 * fb0) * iL0;
            Ps[mg + g][d0 + 1]     = (o[nt][1] * fa0 + ob1 * fb0) * iL0;
            Ps[mg + g + 8][d0]     = (o[nt][2] * fa1 + ob2 * fb1) * iL1;
            Ps[mg + g + 8][d0 + 1] = (o[nt][3] * fa1 + ob3 * fb1) * iL1;
        }
    }
    __syncthreads();

    // coalesced global write of the 64x32 output tile
    float* go = g_ao + h * HDIM * NN;
    for (int idx = t; idx < 2048; idx += 256) {
        int r = idx & 63, d = idx >> 6;
        go[d * NN + n0 + r] = Ps[r][d];
    }
}

// ---------------------------------------------------------------------------
extern "C" void kernel_launch(void* const* d_in, const int* in_sizes, int n_in,
                              void* d_out, int out_size)
{
    const float* x   = (const float*)d_in[0];
    const float* ow  = (const float*)d_in[1];
    const float* w3  = (const float*)d_in[2];
    const float* w5  = (const float*)d_in[3];
    const float* w7  = (const float*)d_in[4];
    const float* wop = (const float*)d_in[5];
    const float* wq  = (const float*)d_in[6];
    const float* wk  = (const float*)d_in[7];
    const float* wv  = (const float*)d_in[8];
    const float* wo  = (const float*)d_in[9];
    const float* beta = (const float*)d_in[10];
    float* out = (float*)d_out;

    conv_offset_kernel<<<dim3(16, 8), 256>>>(x, ow, w3, w5, w7, wop);
    grid_kernel<<<16, 256>>>();
    sample_kernel<<<dim3(16, 256), 256>>>(x);

    sgemm_k<<<dim3(64, 4), 256>>>(wq, 0, 0, x, nullptr);       // q = wq @ x
    sgemm_k<<<dim3(64, 4), 256>>>(wk, 1, 1, nullptr, nullptr); // k = wk @ xs
    sgemm_k<<<dim3(64, 4), 256>>>(wv, 1, 2, nullptr, nullptr); // v = wv @ xs

    flash_tc<<<dim3(64, 8), 256>>>(beta);

    sgemm_k<<<dim3(64, 4), 256>>>(wo, 2, 3, nullptr, out);     // out = wo @ ao
}

// round 3
// speedup vs baseline: 3.1030x; 1.6652x over previous
#include <cuda_runtime.h>
#include <math.h>
#include <stdint.h>

// Problem constants
#define HH 64
#define WW 64
#define NN 4096            // H*W
#define CC 256
#define NHEADS 8
#define HDIM 32

// ---------------- scratch (device globals; no allocation allowed) ----------
__device__ float g_part[8 * 2 * NN];
__device__ float g_ixy[2 * NN];
__device__ float g_xs[CC * NN];
__device__ float g_q[CC * NN];
__device__ float g_k[CC * NN];
__device__ float g_v[CC * NN];
__device__ float g_ao[CC * NN];

__device__ __forceinline__ float tf32r(float x) {
    asm("cvt.rna.tf32.f32 %0, %0;" : "+f"(x));
    return x;
}
__device__ __forceinline__ float4 tf32r4(float4 v) {
    v.x = tf32r(v.x); v.y = tf32r(v.y); v.z = tf32r(v.z); v.w = tf32r(v.w);
    return v;
}
__device__ __forceinline__ void mma_tf32(float c[4], const uint32_t a[4],
                                         uint32_t b0, uint32_t b1) {
    asm volatile(
        "mma.sync.aligned.m16n8k8.row.col.f32.tf32.tf32.f32 "
        "{%0,%1,%2,%3},{%4,%5,%6,%7},{%8,%9},{%0,%1,%2,%3};"
        : "+f"(c[0]), "+f"(c[1]), "+f"(c[2]), "+f"(c[3])
        : "r"(a[0]), "r"(a[1]), "r"(a[2]), "r"(a[3]), "r"(b0), "r"(b1));
}

// ---------------------------------------------------------------------------
// Kernel 1: multi-scale depthwise conv -> relu -> offset projection (partial)
// grid (16, 8) x 256. In-block weight combine into smem.
// ---------------------------------------------------------------------------
__global__ __launch_bounds__(256)
void conv_offset_kernel(const float* __restrict__ x,
                        const float* __restrict__ ow,
                        const float* __restrict__ w3,
                        const float* __restrict__ w5,
                        const float* __restrict__ w7,
                        const float* __restrict__ wproj)
{
    __shared__ float swc[32 * 49];
    __shared__ float swp[2][32];
    int t = threadIdx.x;
    int cz = blockIdx.y * 32;
    float ow0 = ow[0], ow1 = ow[1], ow2 = ow[2];

    for (int idx = t; idx < 32 * 49; idx += 256) {
        int c = idx / 49, ji = idx % 49;
        int j = ji / 7, i = ji % 7;
        float v = w7[(cz + c) * 49 + ji] * ow2;
        if (j >= 1 && j <= 5 && i >= 1 && i <= 5)
            v += w5[(cz + c) * 25 + (j - 1) * 5 + (i - 1)] * ow1;
        if (j >= 2 && j <= 4 && i >= 2 && i <= 4)
            v += w3[(cz + c) * 9 + (j - 2) * 3 + (i - 2)] * ow0;
        swc[idx] = v;
    }
    if (t < 32) {
        swp[0][t] = wproj[cz + t];
        swp[1][t] = wproj[CC + cz + t];
    }
    __syncthreads();

    int p = blockIdx.x * 256 + t;
    int py = p >> 6, px = p & 63;

    float a0 = 0.f, a1 = 0.f;
    for (int c = 0; c < 32; c++) {
        const float* xc = x + (cz + c) * NN;
        const float* wc = swc + c * 49;
        float feat = 0.f;
#pragma unroll
        for (int j = 0; j < 7; j++) {
            int yy = py + j - 3;
            bool yok = (yy >= 0) & (yy < HH);
#pragma unroll
            for (int i = 0; i < 7; i++) {
                int xx = px + i - 3;
                float v = (yok && xx >= 0 && xx < WW) ? xc[yy * WW + xx] : 0.f;
                feat += v * wc[j * 7 + i];
            }
        }
        feat = fmaxf(feat, 0.f);
        a0 += feat * swp[0][c];
        a1 += feat * swp[1][c];
    }
    g_part[(blockIdx.y * 2 + 0) * NN + p] = a0;
    g_part[(blockIdx.y * 2 + 1) * NN + p] = a1;
}

// ---------------------------------------------------------------------------
// Kernel 2: reduce partials, tanh, build sample coordinates
// ---------------------------------------------------------------------------
__global__ __launch_bounds__(256)
void grid_kernel()
{
    int p = blockIdx.x * 256 + threadIdx.x;
    int py = p >> 6, px = p & 63;
    float offy = 0.f, offx = 0.f;
#pragma unroll
    for (int g = 0; g < 8; g++) {
        offy += g_part[(g * 2 + 0) * NN + p];
        offx += g_part[(g * 2 + 1) * NN + p];
    }
    float refy = ((py + 0.5f) / 63.0f) * 2.0f - 1.0f;
    float refx = ((px + 0.5f) / 63.0f) * 2.0f - 1.0f;
    float gy = fminf(fmaxf(refy + tanhf(offy) * 2.0f, -1.0f), 1.0f);
    float gx = fminf(fmaxf(refx + tanhf(offx) * 2.0f, -1.0f), 1.0f);
    g_ixy[p]      = (gx + 1.0f) * 0.5f * 63.0f;
    g_ixy[NN + p] = (gy + 1.0f) * 0.5f * 63.0f;
}

// ---------------------------------------------------------------------------
// Kernel 3: bilinear grid sample
// ---------------------------------------------------------------------------
__global__ __launch_bounds__(256)
void sample_kernel(const float* __restrict__ x)
{
    int p = blockIdx.x * 256 + threadIdx.x;
    int c = blockIdx.y;
    float ix = g_ixy[p], iy = g_ixy[NN + p];
    float x0f = floorf(ix), y0f = floorf(iy);
    float fx = ix - x0f, fy = iy - y0f;
    int x0 = min(max((int)x0f, 0), WW - 1);
    int x1 = min(x0 + 1, WW - 1);
    int y0 = min(max((int)y0f, 0), HH - 1);
    int y1 = min(y0 + 1, HH - 1);
    const float* xc = x + c * NN;
    float v00 = xc[y0 * WW + x0], v01 = xc[y0 * WW + x1];
    float v10 = xc[y1 * WW + x0], v11 = xc[y1 * WW + x1];
    g_xs[c * NN + p] = v00 * (1.f - fx) * (1.f - fy) + v01 * fx * (1.f - fy)
                     + v10 * (1.f - fx) * fy + v11 * fx * fy;
}

// ---------------------------------------------------------------------------
// Kernel 4: tf32 tensor-core GEMM  C[256,4096] = A[256,256] * B[256,4096]
// BM=64, BN=64, BK=32; 256 threads = 8 warps (4 m x 2 n), warp = m16 x n32.
// Double-buffered smem, single sync per k-iter.
// mode 0: A=Aw, B=Bext, C=g_q
// mode 1: A = (z? A1 : Aw), B=g_xs, C = (z? g_v : g_k)
// mode 2: A=Aw, B=g_ao, C=Cext
// ---------------------------------------------------------------------------
__global__ __launch_bounds__(256)
void tcgemm(const float* __restrict__ Aw, const float* __restrict__ A1,
            int mode, const float* __restrict__ Bext, float* __restrict__ Cext)
{
    const float* A; const float* B; float* C;
    if (mode == 0)      { A = Aw; B = Bext; C = g_q; }
    else if (mode == 1) { A = blockIdx.z ? A1 : Aw; B = g_xs;
                          C = blockIdx.z ? g_v : g_k; }
    else                { A = Aw; B = g_ao; C = Cext; }

    __shared__ float As[2][64][36];   // [m][k], pad 36 -> frag banks 4g+kq
    __shared__ float Bs[2][32][72];   // [k][n], pad 72 -> frag banks 8kq+g

    int t = threadIdx.x, w = t >> 5, lane = t & 31;
    int g = lane >> 2, kq = lane & 3;
    int mg = (w >> 1) * 16, nc = (w & 1) * 32;
    int m0 = blockIdx.y * 64, n0 = blockIdx.x * 64;

    float acc[4][4];
#pragma unroll
    for (int i = 0; i < 4; i++)
#pragma unroll
        for (int j = 0; j < 4; j++) acc[i][j] = 0.f;

    // fill index maps
    int am[2], ak;  ak = (t & 7) * 4;
    am[0] = t >> 3; am[1] = (t >> 3) + 32;
    int bk[2], bn;  bn = (t & 15) * 4;
    bk[0] = t >> 4; bk[1] = (t >> 4) + 16;

    float4 ra[2], rb[2];
#pragma unroll
    for (int j = 0; j < 2; j++) {
        ra[j] = tf32r4(*(const float4*)&A[(m0 + am[j]) * 256 + ak]);
        rb[j] = tf32r4(*(const float4*)&B[bk[j] * NN + n0 + bn]);
    }

    for (int ki = 0; ki < 8; ki++) {
        int b = ki & 1;
#pragma unroll
        for (int j = 0; j < 2; j++) {
            *(float4*)&As[b][am[j]][ak] = ra[j];
            *(float4*)&Bs[b][bk[j]][bn] = rb[j];
        }
        __syncthreads();
        if (ki < 7) {
            int k0 = (ki + 1) * 32;
#pragma unroll
            for (int j = 0; j < 2; j++) {
                ra[j] = tf32r4(*(const float4*)&A[(m0 + am[j]) * 256 + k0 + ak]);
                rb[j] = tf32r4(*(const float4*)&B[(k0 + bk[j]) * NN + n0 + bn]);
            }
        }
#pragma unroll
        for (int kt = 0; kt < 4; kt++) {
            uint32_t a[4];
            a[0] = __float_as_uint(As[b][mg + g][kt * 8 + kq]);
            a[1] = __float_as_uint(As[b][mg + g + 8][kt * 8 + kq]);
            a[2] = __float_as_uint(As[b][mg + g][kt * 8 + kq + 4]);
            a[3] = __float_as_uint(As[b][mg + g + 8][kt * 8 + kq + 4]);
#pragma unroll
            for (int nt = 0; nt < 4; nt++) {
                uint32_t b0 = __float_as_uint(Bs[b][kt * 8 + kq][nc + nt * 8 + g]);
                uint32_t b1 = __float_as_uint(Bs[b][kt * 8 + kq + 4][nc + nt * 8 + g]);
                mma_tf32(acc[nt], a, b0, b1);
            }
        }
    }

#pragma unroll
    for (int nt = 0; nt < 4; nt++) {
        int col = n0 + nc + nt * 8 + 2 * kq;
        *(float2*)&C[(m0 + mg + g) * NN + col]     = make_float2(acc[nt][0], acc[nt][1]);
        *(float2*)&C[(m0 + mg + g + 8) * NN + col] = make_float2(acc[nt][2], acc[nt][3]);
    }
}

// ---------------------------------------------------------------------------
// Kernel 5: tensor-core flash attention v2
// grid (64 q-blocks, 8 heads) x 128 threads (4 warps).
// warp: 32 rows (two m16 tiles) x 32-key half; split-K merged at end.
// K and V both stored [d][c]; double-buffered, one sync per key-block.
// ---------------------------------------------------------------------------
__global__ __launch_bounds__(128)
void flash_tc2(const float* __restrict__ beta_p)
{
    __shared__ float Ks[2][32][68];
    __shared__ float Vs[2][32][68];
    __shared__ float Ps[64][68];
    __shared__ float Lut[128];
    __shared__ float Msm[64], Lsm[64];

    int t = threadIdx.x, w = t >> 5, lane = t & 31;
    int g = lane >> 2, kq = lane & 3;
    int mg = (w & 1) * 32;          // row group
    int ch = w >> 1;                // key-column half
    int cb = ch * 32;
    int n0 = blockIdx.x * 64;
    int h  = blockIdx.y;

    float invb = 1.0f / (fabsf(beta_p[0]) + 1e-6f);
    const float scale = 0.17677669529663687f;
    if (t < 127) Lut[t] = __expf(-(float)t * invb);

    const float* gq = g_q + h * HDIM * NN;
    const float* gk = g_k + h * HDIM * NN;
    const float* gv = g_v + h * HDIM * NN;

    // rows: [rt*2 + half]
    int qy[4], qx[4];
#pragma unroll
    for (int rt = 0; rt < 2; rt++) {
#pragma unroll
        for (int hf = 0; hf < 2; hf++) {
            int r = n0 + mg + rt * 16 + hf * 8 + g;
            qy[rt * 2 + hf] = r >> 6;
            qx[rt * 2 + hf] = r & 63;
        }
    }

    // Q fragments (persistent)
    uint32_t qa[2][4][4];
#pragma unroll
    for (int rt = 0; rt < 2; rt++) {
        int base = n0 + mg + rt * 16 + g;
#pragma unroll
        for (int kt = 0; kt < 4; kt++) {
            qa[rt][kt][0] = __float_as_uint(tf32r(gq[(kt * 8 + kq) * NN + base]));
            qa[rt][kt][1] = __float_as_uint(tf32r(gq[(kt * 8 + kq) * NN + base + 8]));
            qa[rt][kt][2] = __float_as_uint(tf32r(gq[(kt * 8 + kq + 4) * NN + base]));
            qa[rt][kt][3] = __float_as_uint(tf32r(gq[(kt * 8 + kq + 4) * NN + base + 8]));
        }
    }

    float o[2][4][4];
#pragma unroll
    for (int rt = 0; rt < 2; rt++)
#pragma unroll
        for (int i = 0; i < 4; i++)
#pragma unroll
            for (int j = 0; j < 4; j++) o[rt][i][j] = 0.f;
    float m[2][2] = {{-1e30f, -1e30f}, {-1e30f, -1e30f}};
    float l[2][2] = {{0.f, 0.f}, {0.f, 0.f}};

    // fill index map: per j (0..3): d = (t>>4) + 8j, c = (t&15)*4
    int fd = t >> 4, fc = (t & 15) * 4;

    float4 rk[4], rv[4];
#pragma unroll
    for (int j = 0; j < 4; j++) {
        rk[j] = tf32r4(*(const float4*)&gk[(fd + 8 * j) * NN + fc]);
        rv[j] = tf32r4(*(const float4*)&gv[(fd + 8 * j) * NN + fc]);
    }

    for (int kb = 0; kb < 64; kb++) {
        int b = kb & 1;
#pragma unroll
        for (int j = 0; j < 4; j++) {
            *(float4*)&Ks[b][fd + 8 * j][fc] = rk[j];
            *(float4*)&Vs[b][fd + 8 * j][fc] = rv[j];
        }
        __syncthreads();
        if (kb < 63) {
            int c0 = (kb + 1) * 64;
#pragma unroll
            for (int j = 0; j < 4; j++) {
                rk[j] = tf32r4(*(const float4*)&gk[(fd + 8 * j) * NN + c0 + fc]);
                rv[j] = tf32r4(*(const float4*)&gv[(fd + 8 * j) * NN + c0 + fc]);
            }
        }

        // ---- S = Q K^T : two 16-row tiles share B fragments ----
        float s[2][4][4];
#pragma unroll
        for (int rt = 0; rt < 2; rt++)
#pragma unroll
            for (int i = 0; i < 4; i++)
#pragma unroll
                for (int j = 0; j < 4; j++) s[rt][i][j] = 0.f;
#pragma unroll
        for (int kt = 0; kt < 4; kt++) {
#pragma unroll
            for (int nt = 0; nt < 4; nt++) {
                uint32_t b0 = __float_as_uint(Ks[b][kt * 8 + kq][cb + nt * 8 + g]);
                uint32_t b1 = __float_as_uint(Ks[b][kt * 8 + kq + 4][cb + nt * 8 + g]);
                mma_tf32(s[0][nt], qa[0][kt], b0, b1);
                mma_tf32(s[1][nt], qa[1][kt], b0, b1);
            }
        }

        // ---- bias + online softmax per row tile ----
#pragma unroll
        for (int rt = 0; rt < 2; rt++) {
            float mn0 = m[rt][0], mn1 = m[rt][1];
#pragma unroll
            for (int nt = 0; nt < 4; nt++) {
#pragma unroll
                for (int e = 0; e < 2; e++) {
                    int col = kb * 64 + cb + nt * 8 + 2 * kq + e;
                    int ky = col >> 6, kx = col & 63;
                    float b0v = Lut[abs(qy[rt * 2] - ky) + abs(qx[rt * 2] - kx)];
                    float b1v = Lut[abs(qy[rt * 2 + 1] - ky) + abs(qx[rt * 2 + 1] - kx)];
                    s[rt][nt][e]     = s[rt][nt][e]     * scale + b0v;
                    s[rt][nt][e + 2] = s[rt][nt][e + 2] * scale + b1v;
                    mn0 = fmaxf(mn0, s[rt][nt][e]);
                    mn1 = fmaxf(mn1, s[rt][nt][e + 2]);
                }
            }
            mn0 = fmaxf(mn0, __shfl_xor_sync(0xffffffffu, mn0, 1));
            mn0 = fmaxf(mn0, __shfl_xor_sync(0xffffffffu, mn0, 2));
            mn1 = fmaxf(mn1, __shfl_xor_sync(0xffffffffu, mn1, 1));
            mn1 = fmaxf(mn1, __shfl_xor_sync(0xffffffffu, mn1, 2));

            float fac0 = __expf(m[rt][0] - mn0);
            float fac1 = __expf(m[rt][1] - mn1);
            m[rt][0] = mn0; m[rt][1] = mn1;

            float ls0 = 0.f, ls1 = 0.f;
#pragma unroll
            for (int nt = 0; nt < 4; nt++) {
#pragma unroll
                for (int e = 0; e < 2; e++) {
                    float p0 = __expf(s[rt][nt][e]     - mn0);
                    float p1 = __expf(s[rt][nt][e + 2] - mn1);
                    s[rt][nt][e] = p0;  s[rt][nt][e + 2] = p1;
                    ls0 += p0;          ls1 += p1;
                }
            }
            ls0 += __shfl_xor_sync(0xffffffffu, ls0, 1);
            ls0 += __shfl_xor_sync(0xffffffffu, ls0, 2);
            ls1 += __shfl_xor_sync(0xffffffffu, ls1, 1);
            ls1 += __shfl_xor_sync(0xffffffffu, ls1, 2);
            l[rt][0] = l[rt][0] * fac0 + ls0;
            l[rt][1] = l[rt][1] * fac1 + ls1;

#pragma unroll
            for (int nt = 0; nt < 4; nt++) {
                o[rt][nt][0] *= fac0; o[rt][nt][1] *= fac0;
                o[rt][nt][2] *= fac1; o[rt][nt][3] *= fac1;
            }

            int rb_ = mg + rt * 16;
#pragma unroll
            for (int nt = 0; nt < 4; nt++) {
                int c0 = cb + nt * 8 + 2 * kq;
                Ps[rb_ + g][c0]         = tf32r(s[rt][nt][0]);
                Ps[rb_ + g][c0 + 1]     = tf32r(s[rt][nt][1]);
                Ps[rb_ + g + 8][c0]     = tf32r(s[rt][nt][2]);
                Ps[rb_ + g + 8][c0 + 1] = tf32r(s[rt][nt][3]);
            }
        }
        __syncwarp();

        // ---- O += P V  (B frags V[d][c] shared across row tiles) ----
#pragma unroll
        for (int kt2 = 0; kt2 < 4; kt2++) {
            uint32_t a0[4], a1[4];
            a0[0] = __float_as_uint(Ps[mg + g][cb + kt2 * 8 + kq]);
            a0[1] = __float_as_uint(Ps[mg + g + 8][cb + kt2 * 8 + kq]);
            a0[2] = __float_as_uint(Ps[mg + g][cb + kt2 * 8 + kq + 4]);
            a0[3] = __float_as_uint(Ps[mg + g + 8][cb + kt2 * 8 + kq + 4]);
            a1[0] = __float_as_uint(Ps[mg + 16 + g][cb + kt2 * 8 + kq]);
            a1[1] = __float_as_uint(Ps[mg + 16 + g + 8][cb + kt2 * 8 + kq]);
            a1[2] = __float_as_uint(Ps[mg + 16 + g][cb + kt2 * 8 + kq + 4]);
            a1[3] = __float_as_uint(Ps[mg + 16 + g + 8][cb + kt2 * 8 + kq + 4]);
#pragma unroll
            for (int nt2 = 0; nt2 < 4; nt2++) {
                uint32_t b0 = __float_as_uint(Vs[b][nt2 * 8 + g][cb + kt2 * 8 + kq]);
                uint32_t b1 = __float_as_uint(Vs[b][nt2 * 8 + g][cb + kt2 * 8 + kq + 4]);
                mma_tf32(o[0][nt2], a0, b0, b1);
                mma_tf32(o[1][nt2], a1, b0, b1);
            }
        }
    }

    // ---- merge split-K halves ----
    __syncthreads();
    if (ch == 1) {
#pragma unroll
        for (int rt = 0; rt < 2; rt++) {
            int rb_ = mg + rt * 16;
            Msm[rb_ + g] = m[rt][0];  Msm[rb_ + g + 8] = m[rt][1];
            Lsm[rb_ + g] = l[rt][0];  Lsm[rb_ + g + 8] = l[rt][1];
#pragma unroll
            for (int nt = 0; nt < 4; nt++) {
                int d0 = nt * 8 + 2 * kq;
                Ps[rb_ + g][d0]         = o[rt][nt][0];
                Ps[rb_ + g][d0 + 1]     = o[rt][nt][1];
                Ps[rb_ + g + 8][d0]     = o[rt][nt][2];
                Ps[rb_ + g + 8][d0 + 1] = o[rt][nt][3];
            }
        }
    }
    __syncthreads();
    if (ch == 0) {
#pragma unroll
        for (int rt = 0; rt < 2; rt++) {
            int rb_ = mg + rt * 16;
            float mb0 = Msm[rb_ + g],     lb0 = Lsm[rb_ + g];
            float mb1 = Msm[rb_ + g + 8], lb1 = Lsm[rb_ + g + 8];
            float M0 = fmaxf(m[rt][0], mb0), M1 = fmaxf(m[rt][1], mb1);
            float fa0 = __expf(m[rt][0] - M0), fb0 = __expf(mb0 - M0);
            float fa1 = __expf(m[rt][1] - M1), fb1 = __expf(mb1 - M1);
            float iL0 = 1.0f / (l[rt][0] * fa0 + lb0 * fb0);
            float iL1 = 1.0f / (l[rt][1] * fa1 + lb1 * fb1);
#pragma unroll
            for (int nt = 0; nt < 4; nt++) {
                int d0 = nt * 8 + 2 * kq;
                float ob0 = Ps[rb_ + g][d0],     ob1 = Ps[rb_ + g][d0 + 1];
                float ob2 = Ps[rb_ + g + 8][d0], ob3 = Ps[rb_ + g + 8][d0 + 1];
                Ps[rb_ + g][d0]         = (o[rt][nt][0] * fa0 + ob0 * fb0) * iL0;
                Ps[rb_ + g][d0 + 1]     = (o[rt][nt][1] * fa0 + ob1 * fb0) * iL0;
                Ps[rb_ + g + 8][d0]     = (o[rt][nt][2] * fa1 + ob2 * fb1) * iL1;
                Ps[rb_ + g + 8][d0 + 1] = (o[rt][nt][3] * fa1 + ob3 * fb1) * iL1;
            }
        }
    }
    __syncthreads();

    float* go = g_ao + h * HDIM * NN;
    for (int idx = t; idx < 2048; idx += 128) {
        int r = idx & 63, d = idx >> 6;
        go[d * NN + n0 + r] = Ps[r][d];
    }
}

// ---------------------------------------------------------------------------
extern "C" void kernel_launch(void* const* d_in, const int* in_sizes, int n_in,
                              void* d_out, int out_size)
{
    const float* x   = (const float*)d_in[0];
    const float* ow  = (const float*)d_in[1];
    const float* w3  = (const float*)d_in[2];
    const float* w5  = (const float*)d_in[3];
    const float* w7  = (const float*)d_in[4];
    const float* wop = (const float*)d_in[5];
    const float* wq  = (const float*)d_in[6];
    const float* wk  = (const float*)d_in[7];
    const float* wv  = (const float*)d_in[8];
    const float* wo  = (const float*)d_in[9];
    const float* beta = (const float*)d_in[10];
    float* out = (float*)d_out;

    conv_offset_kernel<<<dim3(16, 8), 256>>>(x, ow, w3, w5, w7, wop);   // 1
    grid_kernel<<<16, 256>>>();                                         // 2
    sample_kernel<<<dim3(16, 256), 256>>>(x);                           // 3

    tcgemm<<<dim3(64, 4), 256>>>(wq, nullptr, 0, x, nullptr);           // 4: q
    tcgemm<<<dim3(64, 4, 2), 256>>>(wk, wv, 1, nullptr, nullptr);       // 5: k,v

    flash_tc2<<<dim3(64, 8), 128>>>(beta);                              // 6 (profiled)

    tcgemm<<<dim3(64, 4), 256>>>(wo, nullptr, 2, nullptr, out);         // 7: out
}

// round 4
// speedup vs baseline: 3.5011x; 1.1283x over previous
#include <cuda_runtime.h>
#include <math.h>
#include <stdint.h>

// Problem constants
#define HH 64
#define WW 64
#define NN 4096            // H*W
#define CC 256
#define NHEADS 8
#define HDIM 32

// ---------------- scratch (device globals; no allocation allowed) ----------
__device__ float g_part[8 * 2 * NN];
__device__ float g_ixy[2 * NN];
__device__ float g_xs[CC * NN];
__device__ float g_q[CC * NN];   // pre-rounded to tf32
__device__ float g_k[CC * NN];   // pre-rounded to tf32
__device__ float g_v[CC * NN];   // pre-rounded to tf32
__device__ float g_ao[CC * NN];

__device__ __forceinline__ float tf32r(float x) {
    asm("cvt.rna.tf32.f32 %0, %0;" : "+f"(x));
    return x;
}
__device__ __forceinline__ float4 tf32r4(float4 v) {
    v.x = tf32r(v.x); v.y = tf32r(v.y); v.z = tf32r(v.z); v.w = tf32r(v.w);
    return v;
}
__device__ __forceinline__ float ex2f(float x) {
    float y;
    asm("ex2.approx.ftz.f32 %0, %1;" : "=f"(y) : "f"(x));
    return y;
}
__device__ __forceinline__ void mma_tf32(float c[4], const uint32_t a[4],
                                         uint32_t b0, uint32_t b1) {
    asm volatile(
        "mma.sync.aligned.m16n8k8.row.col.f32.tf32.tf32.f32 "
        "{%0,%1,%2,%3},{%4,%5,%6,%7},{%8,%9},{%0,%1,%2,%3};"
        : "+f"(c[0]), "+f"(c[1]), "+f"(c[2]), "+f"(c[3])
        : "r"(a[0]), "r"(a[1]), "r"(a[2]), "r"(a[3]), "r"(b0), "r"(b1));
}
#define CP16(dst, src) \
    asm volatile("cp.async.ca.shared.global [%0], [%1], 16;" \
                 :: "r"(dst), "l"(src))
#define CP_COMMIT() asm volatile("cp.async.commit_group;")
#define CP_WAIT1()  asm volatile("cp.async.wait_group 1;")
#define CP_WAIT0()  asm volatile("cp.async.wait_group 0;")

// ---------------------------------------------------------------------------
// Kernel 1: multi-scale depthwise conv -> relu -> offset projection (partial)
// ---------------------------------------------------------------------------
__global__ __launch_bounds__(256)
void conv_offset_kernel(const float* __restrict__ x,
                        const float* __restrict__ ow,
                        const float* __restrict__ w3,
                        const float* __restrict__ w5,
                        const float* __restrict__ w7,
                        const float* __restrict__ wproj)
{
    __shared__ float swc[32 * 49];
    __shared__ float swp[2][32];
    int t = threadIdx.x;
    int cz = blockIdx.y * 32;
    float ow0 = ow[0], ow1 = ow[1], ow2 = ow[2];

    for (int idx = t; idx < 32 * 49; idx += 256) {
        int c = idx / 49, ji = idx % 49;
        int j = ji / 7, i = ji % 7;
        float v = w7[(cz + c) * 49 + ji] * ow2;
        if (j >= 1 && j <= 5 && i >= 1 && i <= 5)
            v += w5[(cz + c) * 25 + (j - 1) * 5 + (i - 1)] * ow1;
        if (j >= 2 && j <= 4 && i >= 2 && i <= 4)
            v += w3[(cz + c) * 9 + (j - 2) * 3 + (i - 2)] * ow0;
        swc[idx] = v;
    }
    if (t < 32) {
        swp[0][t] = wproj[cz + t];
        swp[1][t] = wproj[CC + cz + t];
    }
    __syncthreads();

    int p = blockIdx.x * 256 + t;
    int py = p >> 6, px = p & 63;

    float a0 = 0.f, a1 = 0.f;
    for (int c = 0; c < 32; c++) {
        const float* xc = x + (cz + c) * NN;
        const float* wc = swc + c * 49;
        float feat = 0.f;
#pragma unroll
        for (int j = 0; j < 7; j++) {
            int yy = py + j - 3;
            bool yok = (yy >= 0) & (yy < HH);
#pragma unroll
            for (int i = 0; i < 7; i++) {
                int xx = px + i - 3;
                float v = (yok && xx >= 0 && xx < WW) ? xc[yy * WW + xx] : 0.f;
                feat += v * wc[j * 7 + i];
            }
        }
        feat = fmaxf(feat, 0.f);
        a0 += feat * swp[0][c];
        a1 += feat * swp[1][c];
    }
    g_part[(blockIdx.y * 2 + 0) * NN + p] = a0;
    g_part[(blockIdx.y * 2 + 1) * NN + p] = a1;
}

// ---------------------------------------------------------------------------
// Kernel 2: reduce partials, tanh, build sample coordinates
// ---------------------------------------------------------------------------
__global__ __launch_bounds__(256)
void grid_kernel()
{
    int p = blockIdx.x * 256 + threadIdx.x;
    int py = p >> 6, px = p & 63;
    float offy = 0.f, offx = 0.f;
#pragma unroll
    for (int g = 0; g < 8; g++) {
        offy += g_part[(g * 2 + 0) * NN + p];
        offx += g_part[(g * 2 + 1) * NN + p];
    }
    float refy = ((py + 0.5f) / 63.0f) * 2.0f - 1.0f;
    float refx = ((px + 0.5f) / 63.0f) * 2.0f - 1.0f;
    float gy = fminf(fmaxf(refy + tanhf(offy) * 2.0f, -1.0f), 1.0f);
    float gx = fminf(fmaxf(refx + tanhf(offx) * 2.0f, -1.0f), 1.0f);
    g_ixy[p]      = (gx + 1.0f) * 0.5f * 63.0f;
    g_ixy[NN + p] = (gy + 1.0f) * 0.5f * 63.0f;
}

// ---------------------------------------------------------------------------
// Kernel 3: bilinear grid sample
// ---------------------------------------------------------------------------
__global__ __launch_bounds__(256)
void sample_kernel(const float* __restrict__ x)
{
    int p = blockIdx.x * 256 + threadIdx.x;
    int c = blockIdx.y;
    float ix = g_ixy[p], iy = g_ixy[NN + p];
    float x0f = floorf(ix), y0f = floorf(iy);
    float fx = ix - x0f, fy = iy - y0f;
    int x0 = min(max((int)x0f, 0), WW - 1);
    int x1 = min(x0 + 1, WW - 1);
    int y0 = min(max((int)y0f, 0), HH - 1);
    int y1 = min(y0 + 1, HH - 1);
    const float* xc = x + c * NN;
    float v00 = xc[y0 * WW + x0], v01 = xc[y0 * WW + x1];
    float v10 = xc[y1 * WW + x0], v11 = xc[y1 * WW + x1];
    g_xs[c * NN + p] = v00 * (1.f - fx) * (1.f - fy) + v01 * fx * (1.f - fy)
                     + v10 * (1.f - fx) * fy + v11 * fx * fy;
}

// ---------------------------------------------------------------------------
// Kernel 4: tf32 tensor-core GEMM  C[256,4096] = A[256,256] * B[256,4096]
// mode 0: A=Aw, B=Bext, C=g_q  (rounded epilogue)
// mode 1: A=(z?A1:Aw), B=g_xs, C=(z?g_v:g_k)  (rounded epilogue)
// mode 2: A=Aw, B=g_ao, C=Cext (raw epilogue)
// ---------------------------------------------------------------------------
__global__ __launch_bounds__(256)
void tcgemm(const float* __restrict__ Aw, const float* __restrict__ A1,
            int mode, const float* __restrict__ Bext, float* __restrict__ Cext)
{
    const float* A; const float* B; float* C; bool rnd;
    if (mode == 0)      { A = Aw; B = Bext; C = g_q; rnd = true; }
    else if (mode == 1) { A = blockIdx.z ? A1 : Aw; B = g_xs;
                          C = blockIdx.z ? g_v : g_k; rnd = true; }
    else                { A = Aw; B = g_ao; C = Cext; rnd = false; }

    __shared__ float As[2][64][36];
    __shared__ float Bs[2][32][72];

    int t = threadIdx.x, w = t >> 5, lane = t & 31;
    int g = lane >> 2, kq = lane & 3;
    int mg = (w >> 1) * 16, nc = (w & 1) * 32;
    int m0 = blockIdx.y * 64, n0 = blockIdx.x * 64;

    float acc[4][4];
#pragma unroll
    for (int i = 0; i < 4; i++)
#pragma unroll
        for (int j = 0; j < 4; j++) acc[i][j] = 0.f;

    int am[2], ak;  ak = (t & 7) * 4;
    am[0] = t >> 3; am[1] = (t >> 3) + 32;
    int bk[2], bn;  bn = (t & 15) * 4;
    bk[0] = t >> 4; bk[1] = (t >> 4) + 16;

    float4 ra[2], rb[2];
#pragma unroll
    for (int j = 0; j < 2; j++) {
        ra[j] = tf32r4(*(const float4*)&A[(m0 + am[j]) * 256 + ak]);
        rb[j] = tf32r4(*(const float4*)&B[bk[j] * NN + n0 + bn]);
    }

    for (int ki = 0; ki < 8; ki++) {
        int b = ki & 1;
#pragma unroll
        for (int j = 0; j < 2; j++) {
            *(float4*)&As[b][am[j]][ak] = ra[j];
            *(float4*)&Bs[b][bk[j]][bn] = rb[j];
        }
        __syncthreads();
        if (ki < 7) {
            int k0 = (ki + 1) * 32;
#pragma unroll
            for (int j = 0; j < 2; j++) {
                ra[j] = tf32r4(*(const float4*)&A[(m0 + am[j]) * 256 + k0 + ak]);
                rb[j] = tf32r4(*(const float4*)&B[(k0 + bk[j]) * NN + n0 + bn]);
            }
        }
#pragma unroll
        for (int kt = 0; kt < 4; kt++) {
            uint32_t a[4];
            a[0] = __float_as_uint(As[b][mg + g][kt * 8 + kq]);
            a[1] = __float_as_uint(As[b][mg + g + 8][kt * 8 + kq]);
            a[2] = __float_as_uint(As[b][mg + g][kt * 8 + kq + 4]);
            a[3] = __float_as_uint(As[b][mg + g + 8][kt * 8 + kq + 4]);
#pragma unroll
            for (int nt = 0; nt < 4; nt++) {
                uint32_t b0 = __float_as_uint(Bs[b][kt * 8 + kq][nc + nt * 8 + g]);
                uint32_t b1 = __float_as_uint(Bs[b][kt * 8 + kq + 4][nc + nt * 8 + g]);
                mma_tf32(acc[nt], a, b0, b1);
            }
        }
    }

    if (rnd) {
#pragma unroll
        for (int i = 0; i < 4; i++)
#pragma unroll
            for (int j = 0; j < 4; j++) acc[i][j] = tf32r(acc[i][j]);
    }
#pragma unroll
    for (int nt = 0; nt < 4; nt++) {
        int col = n0 + nc + nt * 8 + 2 * kq;
        *(float2*)&C[(m0 + mg + g) * NN + col]     = make_float2(acc[nt][0], acc[nt][1]);
        *(float2*)&C[(m0 + mg + g + 8) * NN + col] = make_float2(acc[nt][2], acc[nt][3]);
    }
}

// ---------------------------------------------------------------------------
// Kernel 5: tensor-core flash attention v4
// 128 threads (4 warps); warp = 32 rows x 32-key half; split-K merged at end.
// cp.async 2-stage K/V pipeline; inputs pre-rounded tf32; base-2 softmax.
// ---------------------------------------------------------------------------
__global__ __launch_bounds__(128, 3)
void flash_tc2(const float* __restrict__ beta_p)
{
    __shared__ float Ks[2][32][68];
    __shared__ float Vs[2][32][68];
    __shared__ float Ps[64][68];
    __shared__ float Lut[128];      // exp(-d/|beta|) * log2(e)
    __shared__ float Msm[64], Lsm[64];

    int t = threadIdx.x, w = t >> 5, lane = t & 31;
    int g = lane >> 2, kq = lane & 3;
    int mg = (w & 1) * 32;
    int ch = w >> 1;
    int cb = ch * 32;
    int n0 = blockIdx.x * 64;
    int h  = blockIdx.y;

    const float LOG2E = 1.4426950408889634f;
    float invb = 1.0f / (fabsf(beta_p[0]) + 1e-6f);
    const float scale2 = 0.17677669529663687f * LOG2E;  // 32^-0.5 * log2e
    if (t < 127) Lut[t] = __expf(-(float)t * invb) * LOG2E;

    const float* gq = g_q + h * HDIM * NN;
    const float* gk = g_k + h * HDIM * NN;
    const float* gv = g_v + h * HDIM * NN;

    int qy[4], qx[4];
#pragma unroll
    for (int rt = 0; rt < 2; rt++)
#pragma unroll
        for (int hf = 0; hf < 2; hf++) {
            int r = n0 + mg + rt * 16 + hf * 8 + g;
            qy[rt * 2 + hf] = r >> 6;
            qx[rt * 2 + hf] = r & 63;
        }

    // Q fragments (pre-rounded in gmem)
    uint32_t qa[2][4][4];
#pragma unroll
    for (int rt = 0; rt < 2; rt++) {
        int base = n0 + mg + rt * 16 + g;
#pragma unroll
        for (int kt = 0; kt < 4; kt++) {
            qa[rt][kt][0] = __float_as_uint(gq[(kt * 8 + kq) * NN + base]);
            qa[rt][kt][1] = __float_as_uint(gq[(kt * 8 + kq) * NN + base + 8]);
            qa[rt][kt][2] = __float_as_uint(gq[(kt * 8 + kq + 4) * NN + base]);
            qa[rt][kt][3] = __float_as_uint(gq[(kt * 8 + kq + 4) * NN + base + 8]);
        }
    }

    float o[2][4][4];
#pragma unroll
    for (int rt = 0; rt < 2; rt++)
#pragma unroll
        for (int i = 0; i < 4; i++)
#pragma unroll
            for (int j = 0; j < 4; j++) o[rt][i][j] = 0.f;
    float m[2][2] = {{-1e30f, -1e30f}, {-1e30f, -1e30f}};
    float l[2][2] = {{0.f, 0.f}, {0.f, 0.f}};

    // cp.async fill mapping: 128 threads, d = (t>>4)+8j (j<4 covers 32? no:
    // fd in 0..7, j in 0..3 -> d = fd + 8j covers 0..31; c = (t&15)*4
    int fd = t >> 4, fc = (t & 15) * 4;

    // prefetch stage 0
    {
#pragma unroll
        for (int j = 0; j < 4; j++) {
            int d = fd + 8 * j;
            unsigned kd = (unsigned)__cvta_generic_to_shared(&Ks[0][d][fc]);
            unsigned vd = (unsigned)__cvta_generic_to_shared(&Vs[0][d][fc]);
            CP16(kd, &gk[d * NN + fc]);
            CP16(vd, &gv[d * NN + fc]);
        }
        CP_COMMIT();
    }

    for (int kb = 0; kb < 64; kb++) {
        int st = kb & 1;
        if (kb < 63) {
            int c0 = (kb + 1) * 64;
            int sn = st ^ 1;
#pragma unroll
            for (int j = 0; j < 4; j++) {
                int d = fd + 8 * j;
                unsigned kd = (unsigned)__cvta_generic_to_shared(&Ks[sn][d][fc]);
                unsigned vd = (unsigned)__cvta_generic_to_shared(&Vs[sn][d][fc]);
                CP16(kd, &gk[d * NN + c0 + fc]);
                CP16(vd, &gv[d * NN + c0 + fc]);
            }
            CP_COMMIT();
            CP_WAIT1();
        } else {
            CP_WAIT0();
        }
        __syncthreads();

        // ---- S = Q K^T ----
        float s[2][4][4];
#pragma unroll
        for (int rt = 0; rt < 2; rt++)
#pragma unroll
            for (int i = 0; i < 4; i++)
#pragma unroll
                for (int j = 0; j < 4; j++) s[rt][i][j] = 0.f;
#pragma unroll
        for (int kt = 0; kt < 4; kt++) {
#pragma unroll
            for (int nt = 0; nt < 4; nt++) {
                uint32_t b0 = __float_as_uint(Ks[st][kt * 8 + kq][cb + nt * 8 + g]);
                uint32_t b1 = __float_as_uint(Ks[st][kt * 8 + kq + 4][cb + nt * 8 + g]);
                mma_tf32(s[0][nt], qa[0][kt], b0, b1);
                mma_tf32(s[1][nt], qa[1][kt], b0, b1);
            }
        }

        // ---- bias + online softmax (base-2 domain) ----
#pragma unroll
        for (int rt = 0; rt < 2; rt++) {
            float mn0 = m[rt][0], mn1 = m[rt][1];
#pragma unroll
            for (int nt = 0; nt < 4; nt++) {
#pragma unroll
                for (int e = 0; e < 2; e++) {
                    int col = kb * 64 + cb + nt * 8 + 2 * kq + e;
                    int ky = col >> 6, kx = col & 63;
                    float b0v = Lut[abs(qy[rt * 2] - ky) + abs(qx[rt * 2] - kx)];
                    float b1v = Lut[abs(qy[rt * 2 + 1] - ky) + abs(qx[rt * 2 + 1] - kx)];
                    s[rt][nt][e]     = s[rt][nt][e]     * scale2 + b0v;
                    s[rt][nt][e + 2] = s[rt][nt][e + 2] * scale2 + b1v;
                    mn0 = fmaxf(mn0, s[rt][nt][e]);
                    mn1 = fmaxf(mn1, s[rt][nt][e + 2]);
                }
            }
            mn0 = fmaxf(mn0, __shfl_xor_sync(0xffffffffu, mn0, 1));
            mn0 = fmaxf(mn0, __shfl_xor_sync(0xffffffffu, mn0, 2));
            mn1 = fmaxf(mn1, __shfl_xor_sync(0xffffffffu, mn1, 1));
            mn1 = fmaxf(mn1, __shfl_xor_sync(0xffffffffu, mn1, 2));

            float fac0 = ex2f(m[rt][0] - mn0);
            float fac1 = ex2f(m[rt][1] - mn1);
            m[rt][0] = mn0; m[rt][1] = mn1;

            float ls0 = 0.f, ls1 = 0.f;
#pragma unroll
            for (int nt = 0; nt < 4; nt++) {
#pragma unroll
                for (int e = 0; e < 2; e++) {
                    float p0 = ex2f(s[rt][nt][e]     - mn0);
                    float p1 = ex2f(s[rt][nt][e + 2] - mn1);
                    s[rt][nt][e] = p0;  s[rt][nt][e + 2] = p1;
                    ls0 += p0;          ls1 += p1;
                }
            }
            ls0 += __shfl_xor_sync(0xffffffffu, ls0, 1);
            ls0 += __shfl_xor_sync(0xffffffffu, ls0, 2);
            ls1 += __shfl_xor_sync(0xffffffffu, ls1, 1);
            ls1 += __shfl_xor_sync(0xffffffffu, ls1, 2);
            l[rt][0] = l[rt][0] * fac0 + ls0;
            l[rt][1] = l[rt][1] * fac1 + ls1;

#pragma unroll
            for (int nt = 0; nt < 4; nt++) {
                o[rt][nt][0] *= fac0; o[rt][nt][1] *= fac0;
                o[rt][nt][2] *= fac1; o[rt][nt][3] *= fac1;
            }

            int rb_ = mg + rt * 16;
#pragma unroll
            for (int nt = 0; nt < 4; nt++) {
                int c0 = cb + nt * 8 + 2 * kq;
                Ps[rb_ + g][c0]         = tf32r(s[rt][nt][0]);
                Ps[rb_ + g][c0 + 1]     = tf32r(s[rt][nt][1]);
                Ps[rb_ + g + 8][c0]     = tf32r(s[rt][nt][2]);
                Ps[rb_ + g + 8][c0 + 1] = tf32r(s[rt][nt][3]);
            }
        }
        __syncwarp();

        // ---- O += P V ----
#pragma unroll
        for (int kt2 = 0; kt2 < 4; kt2++) {
            uint32_t a0[4], a1[4];
            a0[0] = __float_as_uint(Ps[mg + g][cb + kt2 * 8 + kq]);
            a0[1] = __float_as_uint(Ps[mg + g + 8][cb + kt2 * 8 + kq]);
            a0[2] = __float_as_uint(Ps[mg + g][cb + kt2 * 8 + kq + 4]);
            a0[3] = __float_as_uint(Ps[mg + g + 8][cb + kt2 * 8 + kq + 4]);
            a1[0] = __float_as_uint(Ps[mg + 16 + g][cb + kt2 * 8 + kq]);
            a1[1] = __float_as_uint(Ps[mg + 16 + g + 8][cb + kt2 * 8 + kq]);
            a1[2] = __float_as_uint(Ps[mg + 16 + g][cb + kt2 * 8 + kq + 4]);
            a1[3] = __float_as_uint(Ps[mg + 16 + g + 8][cb + kt2 * 8 + kq + 4]);
#pragma unroll
            for (int nt2 = 0; nt2 < 4; nt2++) {
                uint32_t b0 = __float_as_uint(Vs[st][nt2 * 8 + g][cb + kt2 * 8 + kq]);
                uint32_t b1 = __float_as_uint(Vs[st][nt2 * 8 + g][cb + kt2 * 8 + kq + 4]);
                mma_tf32(o[0][nt2], a0, b0, b1);
                mma_tf32(o[1][nt2], a1, b0, b1);
            }
        }
        __syncthreads();   // protect stage st before it is refilled next iter
    }

    // ---- merge split-K halves ----
    if (ch == 1) {
#pragma unroll
        for (int rt = 0; rt < 2; rt++) {
            int rb_ = mg + rt * 16;
            Msm[rb_ + g] = m[rt][0];  Msm[rb_ + g + 8] = m[rt][1];
            Lsm[rb_ + g] = l[rt][0];  Lsm[rb_ + g + 8] = l[rt][1];
#pragma unroll
            for (int nt = 0; nt < 4; nt++) {
                int d0 = nt * 8 + 2 * kq;
                Ps[rb_ + g][d0]         = o[rt][nt][0];
                Ps[rb_ + g][d0 + 1]     = o[rt][nt][1];
                Ps[rb_ + g + 8][d0]     = o[rt][nt][2];
                Ps[rb_ + g + 8][d0 + 1] = o[rt][nt][3];
            }
        }
    }
    __syncthreads();
    if (ch == 0) {
#pragma unroll
        for (int rt = 0; rt < 2; rt++) {
            int rb_ = mg + rt * 16;
            float mb0 = Msm[rb_ + g],     lb0 = Lsm[rb_ + g];
            float mb1 = Msm[rb_ + g + 8], lb1 = Lsm[rb_ + g + 8];
            float M0 = fmaxf(m[rt][0], mb0), M1 = fmaxf(m[rt][1], mb1);
            float fa0 = ex2f(m[rt][0] - M0), fb0 = ex2f(mb0 - M0);
            float fa1 = ex2f(m[rt][1] - M1), fb1 = ex2f(mb1 - M1);
            float iL0 = 1.0f / (l[rt][0] * fa0 + lb0 * fb0);
            float iL1 = 1.0f / (l[rt][1] * fa1 + lb1 * fb1);
#pragma unroll
            for (int nt = 0; nt < 4; nt++) {
                int d0 = nt * 8 + 2 * kq;
                float ob0 = Ps[rb_ + g][d0],     ob1 = Ps[rb_ + g][d0 + 1];
                float ob2 = Ps[rb_ + g + 8][d0], ob3 = Ps[rb_ + g + 8][d0 + 1];
                Ps[rb_ + g][d0]         = (o[rt][nt][0] * fa0 + ob0 * fb0) * iL0;
                Ps[rb_ + g][d0 + 1]     = (o[rt][nt][1] * fa0 + ob1 * fb0) * iL0;
                Ps[rb_ + g + 8][d0]     = (o[rt][nt][2] * fa1 + ob2 * fb1) * iL1;
                Ps[rb_ + g + 8][d0 + 1] = (o[rt][nt][3] * fa1 + ob3 * fb1) * iL1;
            }
        }
    }
    __syncthreads();

    float* go = g_ao + h * HDIM * NN;
    for (int idx = t; idx < 2048; idx += 128) {
        int r = idx & 63, d = idx >> 6;
        go[d * NN + n0 + r] = Ps[r][d];
    }
}

// ---------------------------------------------------------------------------
extern "C" void kernel_launch(void* const* d_in, const int* in_sizes, int n_in,
                              void* d_out, int out_size)
{
    const float* x   = (const float*)d_in[0];
    const float* ow  = (const float*)d_in[1];
    const float* w3  = (const float*)d_in[2];
    const float* w5  = (const float*)d_in[3];
    const float* w7  = (const float*)d_in[4];
    const float* wop = (const float*)d_in[5];
    const float* wq  = (const float*)d_in[6];
    const float* wk  = (const float*)d_in[7];
    const float* wv  = (const float*)d_in[8];
    const float* wo  = (const float*)d_in[9];
    const float* beta = (const float*)d_in[10];
    float* out = (float*)d_out;

    conv_offset_kernel<<<dim3(16, 8), 256>>>(x, ow, w3, w5, w7, wop);   // 1
    grid_kernel<<<16, 256>>>();                                         // 2
    sample_kernel<<<dim3(16, 256), 256>>>(x);                           // 3

    tcgemm<<<dim3(64, 4), 256>>>(wq, nullptr, 0, x, nullptr);           // 4: q
    tcgemm<<<dim3(64, 4, 2), 256>>>(wk, wv, 1, nullptr, nullptr);       // 5: k,v

    flash_tc2<<<dim3(64, 8), 128>>>(beta);                              // 6 (profiled)

    tcgemm<<<dim3(64, 4), 256>>>(wo, nullptr, 2, nullptr, out);         // 7: out
}

// round 5
// speedup vs baseline: 3.5856x; 1.0241x over previous
#include <cuda_runtime.h>
#include <math.h>
#include <stdint.h>

// Problem constants
#define HH 64
#define WW 64
#define NN 4096            // H*W
#define CC 256
#define NHEADS 8
#define HDIM 32

// ---------------- scratch (device globals; no allocation allowed) ----------
__device__ float g_part[8 * 2 * NN];
__device__ float g_ixy[2 * NN];
__device__ float g_xs[CC * NN];
__device__ float g_q[CC * NN];   // pre-rounded to tf32
__device__ float g_k[CC * NN];   // pre-rounded to tf32
__device__ float g_v[CC * NN];   // pre-rounded to tf32
__device__ float g_ao[CC * NN];

__device__ __forceinline__ float tf32r(float x) {
    asm("cvt.rna.tf32.f32 %0, %0;" : "+f"(x));
    return x;
}
__device__ __forceinline__ float4 tf32r4(float4 v) {
    v.x = tf32r(v.x); v.y = tf32r(v.y); v.z = tf32r(v.z); v.w = tf32r(v.w);
    return v;
}
__device__ __forceinline__ float ex2f(float x) {
    float y;
    asm("ex2.approx.ftz.f32 %0, %1;" : "=f"(y) : "f"(x));
    return y;
}
__device__ __forceinline__ void mma_tf32(float c[4], const uint32_t a[4],
                                         uint32_t b0, uint32_t b1) {
    asm volatile(
        "mma.sync.aligned.m16n8k8.row.col.f32.tf32.tf32.f32 "
        "{%0,%1,%2,%3},{%4,%5,%6,%7},{%8,%9},{%0,%1,%2,%3};"
        : "+f"(c[0]), "+f"(c[1]), "+f"(c[2]), "+f"(c[3])
        : "r"(a[0]), "r"(a[1]), "r"(a[2]), "r"(a[3]), "r"(b0), "r"(b1));
}
#define CP16(dst, src) \
    asm volatile("cp.async.ca.shared.global [%0], [%1], 16;" \
                 :: "r"(dst), "l"(src))
#define CP_COMMIT() asm volatile("cp.async.commit_group;")
#define CP_WAIT1()  asm volatile("cp.async.wait_group 1;")
#define CP_WAIT0()  asm volatile("cp.async.wait_group 0;")

// ---------------------------------------------------------------------------
// Kernel 1: multi-scale depthwise conv -> relu -> offset projection (partial)
// ---------------------------------------------------------------------------
__global__ __launch_bounds__(256)
void conv_offset_kernel(const float* __restrict__ x,
                        const float* __restrict__ ow,
                        const float* __restrict__ w3,
                        const float* __restrict__ w5,
                        const float* __restrict__ w7,
                        const float* __restrict__ wproj)
{
    __shared__ float swc[32 * 49];
    __shared__ float swp[2][32];
    int t = threadIdx.x;
    int cz = blockIdx.y * 32;
    float ow0 = ow[0], ow1 = ow[1], ow2 = ow[2];

    for (int idx = t; idx < 32 * 49; idx += 256) {
        int c = idx / 49, ji = idx % 49;
        int j = ji / 7, i = ji % 7;
        float v = w7[(cz + c) * 49 + ji] * ow2;
        if (j >= 1 && j <= 5 && i >= 1 && i <= 5)
            v += w5[(cz + c) * 25 + (j - 1) * 5 + (i - 1)] * ow1;
        if (j >= 2 && j <= 4 && i >= 2 && i <= 4)
            v += w3[(cz + c) * 9 + (j - 2) * 3 + (i - 2)] * ow0;
        swc[idx] = v;
    }
    if (t < 32) {
        swp[0][t] = wproj[cz + t];
        swp[1][t] = wproj[CC + cz + t];
    }
    __syncthreads();

    int p = blockIdx.x * 256 + t;
    int py = p >> 6, px = p & 63;

    float a0 = 0.f, a1 = 0.f;
    for (int c = 0; c < 32; c++) {
        const float* xc = x + (cz + c) * NN;
        const float* wc = swc + c * 49;
        float feat = 0.f;
#pragma unroll
        for (int j = 0; j < 7; j++) {
            int yy = py + j - 3;
            bool yok = (yy >= 0) & (yy < HH);
#pragma unroll
            for (int i = 0; i < 7; i++) {
                int xx = px + i - 3;
                float v = (yok && xx >= 0 && xx < WW) ? xc[yy * WW + xx] : 0.f;
                feat += v * wc[j * 7 + i];
            }
        }
        feat = fmaxf(feat, 0.f);
        a0 += feat * swp[0][c];
        a1 += feat * swp[1][c];
    }
    g_part[(blockIdx.y * 2 + 0) * NN + p] = a0;
    g_part[(blockIdx.y * 2 + 1) * NN + p] = a1;
}

// ---------------------------------------------------------------------------
// Kernel 2: reduce partials, tanh, build sample coordinates
// ---------------------------------------------------------------------------
__global__ __launch_bounds__(256)
void grid_kernel()
{
    int p = blockIdx.x * 256 + threadIdx.x;
    int py = p >> 6, px = p & 63;
    float offy = 0.f, offx = 0.f;
#pragma unroll
    for (int g = 0; g < 8; g++) {
        offy += g_part[(g * 2 + 0) * NN + p];
        offx += g_part[(g * 2 + 1) * NN + p];
    }
    float refy = ((py + 0.5f) / 63.0f) * 2.0f - 1.0f;
    float refx = ((px + 0.5f) / 63.0f) * 2.0f - 1.0f;
    float gy = fminf(fmaxf(refy + tanhf(offy) * 2.0f, -1.0f), 1.0f);
    float gx = fminf(fmaxf(refx + tanhf(offx) * 2.0f, -1.0f), 1.0f);
    g_ixy[p]      = (gx + 1.0f) * 0.5f * 63.0f;
    g_ixy[NN + p] = (gy + 1.0f) * 0.5f * 63.0f;
}

// ---------------------------------------------------------------------------
// Kernel 3: bilinear grid sample
// ---------------------------------------------------------------------------
__global__ __launch_bounds__(256)
void sample_kernel(const float* __restrict__ x)
{
    int p = blockIdx.x * 256 + threadIdx.x;
    int c = blockIdx.y;
    float ix = g_ixy[p], iy = g_ixy[NN + p];
    float x0f = floorf(ix), y0f = floorf(iy);
    float fx = ix - x0f, fy = iy - y0f;
    int x0 = min(max((int)x0f, 0), WW - 1);
    int x1 = min(x0 + 1, WW - 1);
    int y0 = min(max((int)y0f, 0), HH - 1);
    int y1 = min(y0 + 1, HH - 1);
    const float* xc = x + c * NN;
    float v00 = xc[y0 * WW + x0], v01 = xc[y0 * WW + x1];
    float v10 = xc[y1 * WW + x0], v11 = xc[y1 * WW + x1];
    g_xs[c * NN + p] = v00 * (1.f - fx) * (1.f - fy) + v01 * fx * (1.f - fy)
                     + v10 * (1.f - fx) * fy + v11 * fx * fy;
}

// ---------------------------------------------------------------------------
// Kernel 4: tf32 tensor-core GEMM  C[256,4096] = A[256,256] * B[256,4096]
// ---------------------------------------------------------------------------
__global__ __launch_bounds__(256)
void tcgemm(const float* __restrict__ Aw, const float* __restrict__ A1,
            int mode, const float* __restrict__ Bext, float* __restrict__ Cext)
{
    const float* A; const float* B; float* C; bool rnd;
    if (mode == 0)      { A = Aw; B = Bext; C = g_q; rnd = true; }
    else if (mode == 1) { A = blockIdx.z ? A1 : Aw; B = g_xs;
                          C = blockIdx.z ? g_v : g_k; rnd = true; }
    else                { A = Aw; B = g_ao; C = Cext; rnd = false; }

    __shared__ float As[2][64][36];
    __shared__ float Bs[2][32][72];

    int t = threadIdx.x, w = t >> 5, lane = t & 31;
    int g = lane >> 2, kq = lane & 3;
    int mg = (w >> 1) * 16, nc = (w & 1) * 32;
    int m0 = blockIdx.y * 64, n0 = blockIdx.x * 64;

    float acc[4][4];
#pragma unroll
    for (int i = 0; i < 4; i++)
#pragma unroll
        for (int j = 0; j < 4; j++) acc[i][j] = 0.f;

    int am[2], ak;  ak = (t & 7) * 4;
    am[0] = t >> 3; am[1] = (t >> 3) + 32;
    int bk[2], bn;  bn = (t & 15) * 4;
    bk[0] = t >> 4; bk[1] = (t >> 4) + 16;

    float4 ra[2], rb[2];
#pragma unroll
    for (int j = 0; j < 2; j++) {
        ra[j] = tf32r4(*(const float4*)&A[(m0 + am[j]) * 256 + ak]);
        rb[j] = tf32r4(*(const float4*)&B[bk[j] * NN + n0 + bn]);
    }

    for (int ki = 0; ki < 8; ki++) {
        int b = ki & 1;
#pragma unroll
        for (int j = 0; j < 2; j++) {
            *(float4*)&As[b][am[j]][ak] = ra[j];
            *(float4*)&Bs[b][bk[j]][bn] = rb[j];
        }
        __syncthreads();
        if (ki < 7) {
            int k0 = (ki + 1) * 32;
#pragma unroll
            for (int j = 0; j < 2; j++) {
                ra[j] = tf32r4(*(const float4*)&A[(m0 + am[j]) * 256 + k0 + ak]);
                rb[j] = tf32r4(*(const float4*)&B[(k0 + bk[j]) * NN + n0 + bn]);
            }
        }
#pragma unroll
        for (int kt = 0; kt < 4; kt++) {
            uint32_t a[4];
            a[0] = __float_as_uint(As[b][mg + g][kt * 8 + kq]);
            a[1] = __float_as_uint(As[b][mg + g + 8][kt * 8 + kq]);
            a[2] = __float_as_uint(As[b][mg + g][kt * 8 + kq + 4]);
            a[3] = __float_as_uint(As[b][mg + g + 8][kt * 8 + kq + 4]);
#pragma unroll
            for (int nt = 0; nt < 4; nt++) {
                uint32_t b0 = __float_as_uint(Bs[b][kt * 8 + kq][nc + nt * 8 + g]);
                uint32_t b1 = __float_as_uint(Bs[b][kt * 8 + kq + 4][nc + nt * 8 + g]);
                mma_tf32(acc[nt], a, b0, b1);
            }
        }
    }

    if (rnd) {
#pragma unroll
        for (int i = 0; i < 4; i++)
#pragma unroll
            for (int j = 0; j < 4; j++) acc[i][j] = tf32r(acc[i][j]);
    }
#pragma unroll
    for (int nt = 0; nt < 4; nt++) {
        int col = n0 + nc + nt * 8 + 2 * kq;
        *(float2*)&C[(m0 + mg + g) * NN + col]     = make_float2(acc[nt][0], acc[nt][1]);
        *(float2*)&C[(m0 + mg + g + 8) * NN + col] = make_float2(acc[nt][2], acc[nt][3]);
    }
}

// ---------------------------------------------------------------------------
// Kernel 5: flash attention v5 — BM=128, 8 warps, 3-stage cp.async,
// ONE __syncthreads per key-block. Dynamic smem (~90 KB).
// warp w: rows (w&3)*32 (two m16 tiles), key-col half (w>>2)*32.
// ---------------------------------------------------------------------------
#define KS_OFF  0            // [3][32][68]
#define VS_OFF  6528         // [3][32][68]
#define PS_OFF  13056        // per warp [32][36]
#define LUT_OFF 22272
#define MSM_OFF 22400
#define LSM_OFF 22528
#define FLASH_SMEM_FLOATS 22656

__global__ __launch_bounds__(256, 2)
void flash_tc5(const float* __restrict__ beta_p)
{
    extern __shared__ float sm[];
    float* Lut = sm + LUT_OFF;
    float* Msm = sm + MSM_OFF;
    float* Lsm = sm + LSM_OFF;

    int t = threadIdx.x, w = t >> 5, lane = t & 31;
    int g = lane >> 2, kq = lane & 3;
    int mg = (w & 3) * 32;          // warp row offset in 128-row tile
    int ch = w >> 2;                // key-column half
    int cb = ch * 32;
    int n0 = blockIdx.x * 128;
    int h  = blockIdx.y;

    float* Pw = sm + PS_OFF + w * (32 * 36);

    const float LOG2E = 1.4426950408889634f;
    float invb = 1.0f / (fabsf(beta_p[0]) + 1e-6f);
    const float scale2 = 0.17677669529663687f * LOG2E;
    if (t < 127) Lut[t] = __expf(-(float)t * invb) * LOG2E;

    const float* gq = g_q + h * HDIM * NN;
    const float* gk = g_k + h * HDIM * NN;
    const float* gv = g_v + h * HDIM * NN;

    int qy[4], qx[4];
#pragma unroll
    for (int rt = 0; rt < 2; rt++)
#pragma unroll
        for (int hf = 0; hf < 2; hf++) {
            int r = n0 + mg + rt * 16 + hf * 8 + g;
            qy[rt * 2 + hf] = r >> 6;
            qx[rt * 2 + hf] = r & 63;
        }

    // Q fragments (pre-rounded tf32 in gmem)
    uint32_t qa[2][4][4];
#pragma unroll
    for (int rt = 0; rt < 2; rt++) {
        int base = n0 + mg + rt * 16 + g;
#pragma unroll
        for (int kt = 0; kt < 4; kt++) {
            qa[rt][kt][0] = __float_as_uint(gq[(kt * 8 + kq) * NN + base]);
            qa[rt][kt][1] = __float_as_uint(gq[(kt * 8 + kq) * NN + base + 8]);
            qa[rt][kt][2] = __float_as_uint(gq[(kt * 8 + kq + 4) * NN + base]);
            qa[rt][kt][3] = __float_as_uint(gq[(kt * 8 + kq + 4) * NN + base + 8]);
        }
    }

    float o[2][4][4];
#pragma unroll
    for (int rt = 0; rt < 2; rt++)
#pragma unroll
        for (int i = 0; i < 4; i++)
#pragma unroll
            for (int j = 0; j < 4; j++) o[rt][i][j] = 0.f;
    float m[2][2] = {{-1e30f, -1e30f}, {-1e30f, -1e30f}};
    float l[2][2] = {{0.f, 0.f}, {0.f, 0.f}};

    // fill mapping: 512 float4 per matrix per stage, 2 per thread
    int id0 = t, id1 = t + 256;
    int d0f = id0 >> 4, c0f = (id0 & 15) << 2;
    int d1f = id1 >> 4, c1f = (id1 & 15) << 2;

#define PREFETCH(stage, kcol)                                                  \
    do {                                                                       \
        float* kbase = sm + KS_OFF + (stage) * 2176;                           \
        float* vbase = sm + VS_OFF + (stage) * 2176;                           \
        unsigned k0 = (unsigned)__cvta_generic_to_shared(&kbase[d0f * 68 + c0f]); \
        unsigned k1 = (unsigned)__cvta_generic_to_shared(&kbase[d1f * 68 + c1f]); \
        unsigned v0 = (unsigned)__cvta_generic_to_shared(&vbase[d0f * 68 + c0f]); \
        unsigned v1 = (unsigned)__cvta_generic_to_shared(&vbase[d1f * 68 + c1f]); \
        CP16(k0, &gk[d0f * NN + (kcol) + c0f]);                                \
        CP16(k1, &gk[d1f * NN + (kcol) + c1f]);                                \
        CP16(v0, &gv[d0f * NN + (kcol) + c0f]);                                \
        CP16(v1, &gv[d1f * NN + (kcol) + c1f]);                                \
    } while (0)

    PREFETCH(0, 0);   CP_COMMIT();
    PREFETCH(1, 64);  CP_COMMIT();

    for (int kb = 0; kb < 64; kb++) {
        int st = kb - (kb / 3) * 3;   // kb % 3
        if (kb < 63) CP_WAIT1(); else CP_WAIT0();
        __syncthreads();
        if (kb < 62) {
            int st2 = kb + 2; st2 -= (st2 / 3) * 3;
            PREFETCH(st2, (kb + 2) * 64);
            CP_COMMIT();
        }

        const float* Ksb = sm + KS_OFF + st * 2176;
        const float* Vsb = sm + VS_OFF + st * 2176;

        // ---- S = Q K^T ----
        float s[2][4][4];
#pragma unroll
        for (int rt = 0; rt < 2; rt++)
#pragma unroll
            for (int i = 0; i < 4; i++)
#pragma unroll
                for (int j = 0; j < 4; j++) s[rt][i][j] = 0.f;
#pragma unroll
        for (int kt = 0; kt < 4; kt++) {
#pragma unroll
            for (int nt = 0; nt < 4; nt++) {
                uint32_t b0 = __float_as_uint(Ksb[(kt * 8 + kq) * 68 + cb + nt * 8 + g]);
                uint32_t b1 = __float_as_uint(Ksb[(kt * 8 + kq + 4) * 68 + cb + nt * 8 + g]);
                mma_tf32(s[0][nt], qa[0][kt], b0, b1);
                mma_tf32(s[1][nt], qa[1][kt], b0, b1);
            }
        }

        // ---- bias + online softmax (base-2) ----
#pragma unroll
        for (int rt = 0; rt < 2; rt++) {
            float mn0 = m[rt][0], mn1 = m[rt][1];
#pragma unroll
            for (int nt = 0; nt < 4; nt++) {
#pragma unroll
                for (int e = 0; e < 2; e++) {
                    int col = kb * 64 + cb + nt * 8 + 2 * kq + e;
                    int ky = col >> 6, kx = col & 63;
                    float b0v = Lut[abs(qy[rt * 2] - ky) + abs(qx[rt * 2] - kx)];
                    float b1v = Lut[abs(qy[rt * 2 + 1] - ky) + abs(qx[rt * 2 + 1] - kx)];
                    s[rt][nt][e]     = s[rt][nt][e]     * scale2 + b0v;
                    s[rt][nt][e + 2] = s[rt][nt][e + 2] * scale2 + b1v;
                    mn0 = fmaxf(mn0, s[rt][nt][e]);
                    mn1 = fmaxf(mn1, s[rt][nt][e + 2]);
                }
            }
            mn0 = fmaxf(mn0, __shfl_xor_sync(0xffffffffu, mn0, 1));
            mn0 = fmaxf(mn0, __shfl_xor_sync(0xffffffffu, mn0, 2));
            mn1 = fmaxf(mn1, __shfl_xor_sync(0xffffffffu, mn1, 1));
            mn1 = fmaxf(mn1, __shfl_xor_sync(0xffffffffu, mn1, 2));

            float fac0 = ex2f(m[rt][0] - mn0);
            float fac1 = ex2f(m[rt][1] - mn1);
            m[rt][0] = mn0; m[rt][1] = mn1;

            float ls0 = 0.f, ls1 = 0.f;
#pragma unroll
            for (int nt = 0; nt < 4; nt++) {
#pragma unroll
                for (int e = 0; e < 2; e++) {
                    float p0 = ex2f(s[rt][nt][e]     - mn0);
                    float p1 = ex2f(s[rt][nt][e + 2] - mn1);
                    s[rt][nt][e] = p0;  s[rt][nt][e + 2] = p1;
                    ls0 += p0;          ls1 += p1;
                }
            }
            ls0 += __shfl_xor_sync(0xffffffffu, ls0, 1);
            ls0 += __shfl_xor_sync(0xffffffffu, ls0, 2);
            ls1 += __shfl_xor_sync(0xffffffffu, ls1, 1);
            ls1 += __shfl_xor_sync(0xffffffffu, ls1, 2);
            l[rt][0] = l[rt][0] * fac0 + ls0;
            l[rt][1] = l[rt][1] * fac1 + ls1;

#pragma unroll
            for (int nt = 0; nt < 4; nt++) {
                o[rt][nt][0] *= fac0; o[rt][nt][1] *= fac0;
                o[rt][nt][2] *= fac1; o[rt][nt][3] *= fac1;
            }

            // stage P (local 32x32 tile, stride 36)
#pragma unroll
            for (int nt = 0; nt < 4; nt++) {
                int lc = nt * 8 + 2 * kq;
                Pw[(rt * 16 + g) * 36 + lc]     = tf32r(s[rt][nt][0]);
                Pw[(rt * 16 + g) * 36 + lc + 1] = tf32r(s[rt][nt][1]);
                Pw[(rt * 16 + g + 8) * 36 + lc]     = tf32r(s[rt][nt][2]);
                Pw[(rt * 16 + g + 8) * 36 + lc + 1] = tf32r(s[rt][nt][3]);
            }
        }
        __syncwarp();

        // ---- O += P V ----
#pragma unroll
        for (int kt2 = 0; kt2 < 4; kt2++) {
            uint32_t a0[4], a1[4];
            int lc = kt2 * 8 + kq;
            a0[0] = __float_as_uint(Pw[g * 36 + lc]);
            a0[1] = __float_as_uint(Pw[(g + 8) * 36 + lc]);
            a0[2] = __float_as_uint(Pw[g * 36 + lc + 4]);
            a0[3] = __float_as_uint(Pw[(g + 8) * 36 + lc + 4]);
            a1[0] = __float_as_uint(Pw[(16 + g) * 36 + lc]);
            a1[1] = __float_as_uint(Pw[(16 + g + 8) * 36 + lc]);
            a1[2] = __float_as_uint(Pw[(16 + g) * 36 + lc + 4]);
            a1[3] = __float_as_uint(Pw[(16 + g + 8) * 36 + lc + 4]);
#pragma unroll
            for (int nt2 = 0; nt2 < 4; nt2++) {
                uint32_t b0 = __float_as_uint(Vsb[(nt2 * 8 + g) * 68 + cb + kt2 * 8 + kq]);
                uint32_t b1 = __float_as_uint(Vsb[(nt2 * 8 + g) * 68 + cb + kt2 * 8 + kq + 4]);
                mma_tf32(o[0][nt2], a0, b0, b1);
                mma_tf32(o[1][nt2], a1, b0, b1);
            }
        }
    }

    // ---- merge split-K halves; Om reuses the Ps region [128][36] ----
    float* Om = sm + PS_OFF;
    __syncthreads();
    if (ch == 1) {
#pragma unroll
        for (int rt = 0; rt < 2; rt++) {
            int rb_ = mg + rt * 16;
            Msm[rb_ + g] = m[rt][0];  Msm[rb_ + g + 8] = m[rt][1];
            Lsm[rb_ + g] = l[rt][0];  Lsm[rb_ + g + 8] = l[rt][1];
#pragma unroll
            for (int nt = 0; nt < 4; nt++) {
                int d0 = nt * 8 + 2 * kq;
                Om[(rb_ + g) * 36 + d0]         = o[rt][nt][0];
                Om[(rb_ + g) * 36 + d0 + 1]     = o[rt][nt][1];
                Om[(rb_ + g + 8) * 36 + d0]     = o[rt][nt][2];
                Om[(rb_ + g + 8) * 36 + d0 + 1] = o[rt][nt][3];
            }
        }
    }
    __syncthreads();
    if (ch == 0) {
#pragma unroll
        for (int rt = 0; rt < 2; rt++) {
            int rb_ = mg + rt * 16;
            float mb0 = Msm[rb_ + g],     lb0 = Lsm[rb_ + g];
            float mb1 = Msm[rb_ + g + 8], lb1 = Lsm[rb_ + g + 8];
            float M0 = fmaxf(m[rt][0], mb0), M1 = fmaxf(m[rt][1], mb1);
            float fa0 = ex2f(m[rt][0] - M0), fb0 = ex2f(mb0 - M0);
            float fa1 = ex2f(m[rt][1] - M1), fb1 = ex2f(mb1 - M1);
            float iL0 = 1.0f / (l[rt][0] * fa0 + lb0 * fb0);
            float iL1 = 1.0f / (l[rt][1] * fa1 + lb1 * fb1);
#pragma unroll
            for (int nt = 0; nt < 4; nt++) {
                int d0 = nt * 8 + 2 * kq;
                float ob0 = Om[(rb_ + g) * 36 + d0];
                float ob1 = Om[(rb_ + g) * 36 + d0 + 1];
                float ob2 = Om[(rb_ + g + 8) * 36 + d0];
                float ob3 = Om[(rb_ + g + 8) * 36 + d0 + 1];
                Om[(rb_ + g) * 36 + d0]         = (o[rt][nt][0] * fa0 + ob0 * fb0) * iL0;
                Om[(rb_ + g) * 36 + d0 + 1]     = (o[rt][nt][1] * fa0 + ob1 * fb0) * iL0;
                Om[(rb_ + g + 8) * 36 + d0]     = (o[rt][nt][2] * fa1 + ob2 * fb1) * iL1;
                Om[(rb_ + g + 8) * 36 + d0 + 1] = (o[rt][nt][3] * fa1 + ob3 * fb1) * iL1;
            }
        }
    }
    __syncthreads();

    float* go = g_ao + h * HDIM * NN;
    for (int idx = t; idx < 4096; idx += 256) {
        int r = idx & 127, d = idx >> 7;
        go[d * NN + n0 + r] = Om[r * 36 + d];
    }
}

// ---------------------------------------------------------------------------
extern "C" void kernel_launch(void* const* d_in, const int* in_sizes, int n_in,
                              void* d_out, int out_size)
{
    const float* x   = (const float*)d_in[0];
    const float* ow  = (const float*)d_in[1];
    const float* w3  = (const float*)d_in[2];
    const float* w5  = (const float*)d_in[3];
    const float* w7  = (const float*)d_in[4];
    const float* wop = (const float*)d_in[5];
    const float* wq  = (const float*)d_in[6];
    const float* wk  = (const float*)d_in[7];
    const float* wv  = (const float*)d_in[8];
    const float* wo  = (const float*)d_in[9];
    const float* beta = (const float*)d_in[10];
    float* out = (float*)d_out;

    static int smem_set = 0;
    if (!smem_set) {
        cudaFuncSetAttribute(flash_tc5, cudaFuncAttributeMaxDynamicSharedMemorySize,
                             FLASH_SMEM_FLOATS * 4);
        smem_set = 1;
    }

    conv_offset_kernel<<<dim3(16, 8), 256>>>(x, ow, w3, w5, w7, wop);
    grid_kernel<<<16, 256>>>();
    sample_kernel<<<dim3(16, 256), 256>>>(x);

    tcgemm<<<dim3(64, 4), 256>>>(wq, nullptr, 0, x, nullptr);           // q
    tcgemm<<<dim3(64, 4, 2), 256>>>(wk, wv, 1, nullptr, nullptr);       // k,v

    flash_tc5<<<dim3(32, 8), 256, FLASH_SMEM_FLOATS * 4>>>(beta);

    tcgemm<<<dim3(64, 4), 256>>>(wo, nullptr, 2, nullptr, out);         // out
}

// round 6
// speedup vs baseline: 3.6653x; 1.0222x over previous
#include <cuda_runtime.h>
#include <math.h>
#include <stdint.h>

// Problem constants
#define HH 64
#define WW 64
#define NN 4096            // H*W
#define CC 256
#define NHEADS 8
#define HDIM 32

// ---------------- scratch (device globals; no allocation allowed) ----------
__device__ float g_part[8 * 2 * NN];
__device__ int   g_ctr[16];          // last-block counters (self-resetting)
__device__ float g_ixy[2 * NN];
__device__ float g_xs[CC * NN];
__device__ float g_q[CC * NN];   // pre-rounded to tf32
__device__ float g_k[CC * NN];   // pre-rounded to tf32
__device__ float g_v[CC * NN];   // pre-rounded to tf32
__device__ float g_ao[CC * NN];

__device__ __forceinline__ float tf32r(float x) {
    asm("cvt.rna.tf32.f32 %0, %0;" : "+f"(x));
    return x;
}
__device__ __forceinline__ float4 tf32r4(float4 v) {
    v.x = tf32r(v.x); v.y = tf32r(v.y); v.z = tf32r(v.z); v.w = tf32r(v.w);
    return v;
}
__device__ __forceinline__ float ex2f(float x) {
    float y;
    asm("ex2.approx.ftz.f32 %0, %1;" : "=f"(y) : "f"(x));
    return y;
}
__device__ __forceinline__ void mma_tf32(float c[4], const uint32_t a[4],
                                         uint32_t b0, uint32_t b1) {
    asm volatile(
        "mma.sync.aligned.m16n8k8.row.col.f32.tf32.tf32.f32 "
        "{%0,%1,%2,%3},{%4,%5,%6,%7},{%8,%9},{%0,%1,%2,%3};"
        : "+f"(c[0]), "+f"(c[1]), "+f"(c[2]), "+f"(c[3])
        : "r"(a[0]), "r"(a[1]), "r"(a[2]), "r"(a[3]), "r"(b0), "r"(b1));
}
#define CP16(dst, src) \
    asm volatile("cp.async.ca.shared.global [%0], [%1], 16;" \
                 :: "r"(dst), "l"(src))
#define CP_COMMIT() asm volatile("cp.async.commit_group;")
#define CP_WAIT1()  asm volatile("cp.async.wait_group 1;")
#define CP_WAIT0()  asm volatile("cp.async.wait_group 0;")

// ---------------------------------------------------------------------------
// Kernel 1: depthwise conv -> relu -> offset proj (partials), FUSED with the
// cross-group reduction + tanh + coord build (done by the last-arriving block
// per pixel chunk; deterministic fixed-order sum).
// grid (16, 8) x 256.
// ---------------------------------------------------------------------------
__global__ __launch_bounds__(256)
void conv_offset_fused(const float* __restrict__ x,
                       const float* __restrict__ ow,
                       const float* __restrict__ w3,
                       const float* __restrict__ w5,
                       const float* __restrict__ w7,
                       const float* __restrict__ wproj)
{
    __shared__ float swc[32 * 49];
    __shared__ float swp[2][32];
    __shared__ int isLast;
    int t = threadIdx.x;
    int cz = blockIdx.y * 32;
    float ow0 = ow[0], ow1 = ow[1], ow2 = ow[2];

    for (int idx = t; idx < 32 * 49; idx += 256) {
        int c = idx / 49, ji = idx % 49;
        int j = ji / 7, i = ji % 7;
        float v = w7[(cz + c) * 49 + ji] * ow2;
        if (j >= 1 && j <= 5 && i >= 1 && i <= 5)
            v += w5[(cz + c) * 25 + (j - 1) * 5 + (i - 1)] * ow1;
        if (j >= 2 && j <= 4 && i >= 2 && i <= 4)
            v += w3[(cz + c) * 9 + (j - 2) * 3 + (i - 2)] * ow0;
        swc[idx] = v;
    }
    if (t < 32) {
        swp[0][t] = wproj[cz + t];
        swp[1][t] = wproj[CC + cz + t];
    }
    __syncthreads();

    int p = blockIdx.x * 256 + t;
    int py = p >> 6, px = p & 63;

    float a0 = 0.f, a1 = 0.f;
    for (int c = 0; c < 32; c++) {
        const float* xc = x + (cz + c) * NN;
        const float* wc = swc + c * 49;
        float feat = 0.f;
#pragma unroll
        for (int j = 0; j < 7; j++) {
            int yy = py + j - 3;
            bool yok = (yy >= 0) & (yy < HH);
#pragma unroll
            for (int i = 0; i < 7; i++) {
                int xx = px + i - 3;
                float v = (yok && xx >= 0 && xx < WW) ? xc[yy * WW + xx] : 0.f;
                feat += v * wc[j * 7 + i];
            }
        }
        feat = fmaxf(feat, 0.f);
        a0 += feat * swp[0][c];
        a1 += feat * swp[1][c];
    }
    g_part[(blockIdx.y * 2 + 0) * NN + p] = a0;
    g_part[(blockIdx.y * 2 + 1) * NN + p] = a1;

    // ---- last block per pixel chunk reduces + builds coordinates ----
    __threadfence();
    if (t == 0) {
        int old = atomicAdd(&g_ctr[blockIdx.x], 1);
        isLast = (old == 7);
    }
    __syncthreads();
    if (isLast) {
        __threadfence();
        float offy = 0.f, offx = 0.f;
#pragma unroll
        for (int g = 0; g < 8; g++) {
            offy += g_part[(g * 2 + 0) * NN + p];
            offx += g_part[(g * 2 + 1) * NN + p];
        }
        float refy = ((py + 0.5f) / 63.0f) * 2.0f - 1.0f;
        float refx = ((px + 0.5f) / 63.0f) * 2.0f - 1.0f;
        float gy = fminf(fmaxf(refy + tanhf(offy) * 2.0f, -1.0f), 1.0f);
        float gx = fminf(fmaxf(refx + tanhf(offx) * 2.0f, -1.0f), 1.0f);
        g_ixy[p]      = (gx + 1.0f) * 0.5f * 63.0f;
        g_ixy[NN + p] = (gy + 1.0f) * 0.5f * 63.0f;
        if (t == 0) g_ctr[blockIdx.x] = 0;   // reset for next graph replay
    }
}

// ---------------------------------------------------------------------------
// Kernel 2: bilinear grid sample
// ---------------------------------------------------------------------------
__global__ __launch_bounds__(256)
void sample_kernel(const float* __restrict__ x)
{
    int p = blockIdx.x * 256 + threadIdx.x;
    int c = blockIdx.y;
    float ix = g_ixy[p], iy = g_ixy[NN + p];
    float x0f = floorf(ix), y0f = floorf(iy);
    float fx = ix - x0f, fy = iy - y0f;
    int x0 = min(max((int)x0f, 0), WW - 1);
    int x1 = min(x0 + 1, WW - 1);
    int y0 = min(max((int)y0f, 0), HH - 1);
    int y1 = min(y0 + 1, HH - 1);
    const float* xc = x + c * NN;
    float v00 = xc[y0 * WW + x0], v01 = xc[y0 * WW + x1];
    float v10 = xc[y1 * WW + x0], v11 = xc[y1 * WW + x1];
    g_xs[c * NN + p] = v00 * (1.f - fx) * (1.f - fy) + v01 * fx * (1.f - fy)
                     + v10 * (1.f - fx) * fy + v11 * fx * fy;
}

// ---------------------------------------------------------------------------
// Kernel 3: tf32 tensor-core GEMM  C[256,4096] = A[256,256] * B[256,4096]
// mode 3 (qkv): z=0: wq@x -> g_q; z=1: wk@xs -> g_k; z=2: wv@xs -> g_v
// mode 2 (out): wo@g_ao -> Cext (raw epilogue)
// ---------------------------------------------------------------------------
__global__ __launch_bounds__(256)
void tcgemm(const float* __restrict__ A0, const float* __restrict__ A1,
            const float* __restrict__ A2, int mode,
            const float* __restrict__ Bext, float* __restrict__ Cext)
{
    const float* A; const float* B; float* C; bool rnd;
    if (mode == 3) {
        int z = blockIdx.z;
        A = (z == 0) ? A0 : (z == 1) ? A1 : A2;
        B = (z == 0) ? Bext : g_xs;
        C = (z == 0) ? g_q : (z == 1) ? g_k : g_v;
        rnd = true;
    } else {
        A = A0; B = g_ao; C = Cext; rnd = false;
    }

    __shared__ float As[2][64][36];
    __shared__ float Bs[2][32][72];

    int t = threadIdx.x, w = t >> 5, lane = t & 31;
    int g = lane >> 2, kq = lane & 3;
    int mg = (w >> 1) * 16, nc = (w & 1) * 32;
    int m0 = blockIdx.y * 64, n0 = blockIdx.x * 64;

    float acc[4][4];
#pragma unroll
    for (int i = 0; i < 4; i++)
#pragma unroll
        for (int j = 0; j < 4; j++) acc[i][j] = 0.f;

    int am[2], ak;  ak = (t & 7) * 4;
    am[0] = t >> 3; am[1] = (t >> 3) + 32;
    int bk[2], bn;  bn = (t & 15) * 4;
    bk[0] = t >> 4; bk[1] = (t >> 4) + 16;

    float4 ra[2], rb[2];
#pragma unroll
    for (int j = 0; j < 2; j++) {
        ra[j] = tf32r4(*(const float4*)&A[(m0 + am[j]) * 256 + ak]);
        rb[j] = tf32r4(*(const float4*)&B[bk[j] * NN + n0 + bn]);
    }

    for (int ki = 0; ki < 8; ki++) {
        int b = ki & 1;
#pragma unroll
        for (int j = 0; j < 2; j++) {
            *(float4*)&As[b][am[j]][ak] = ra[j];
            *(float4*)&Bs[b][bk[j]][bn] = rb[j];
        }
        __syncthreads();
        if (ki < 7) {
            int k0 = (ki + 1) * 32;
#pragma unroll
            for (int j = 0; j < 2; j++) {
                ra[j] = tf32r4(*(const float4*)&A[(m0 + am[j]) * 256 + k0 + ak]);
                rb[j] = tf32r4(*(const float4*)&B[(k0 + bk[j]) * NN + n0 + bn]);
            }
        }
#pragma unroll
        for (int kt = 0; kt < 4; kt++) {
            uint32_t a[4];
            a[0] = __float_as_uint(As[b][mg + g][kt * 8 + kq]);
            a[1] = __float_as_uint(As[b][mg + g + 8][kt * 8 + kq]);
            a[2] = __float_as_uint(As[b][mg + g][kt * 8 + kq + 4]);
            a[3] = __float_as_uint(As[b][mg + g + 8][kt * 8 + kq + 4]);
#pragma unroll
            for (int nt = 0; nt < 4; nt++) {
                uint32_t b0 = __float_as_uint(Bs[b][kt * 8 + kq][nc + nt * 8 + g]);
                uint32_t b1 = __float_as_uint(Bs[b][kt * 8 + kq + 4][nc + nt * 8 + g]);
                mma_tf32(acc[nt], a, b0, b1);
            }
        }
    }

    if (rnd) {
#pragma unroll
        for (int i = 0; i < 4; i++)
#pragma unroll
            for (int j = 0; j < 4; j++) acc[i][j] = tf32r(acc[i][j]);
    }
#pragma unroll
    for (int nt = 0; nt < 4; nt++) {
        int col = n0 + nc + nt * 8 + 2 * kq;
        *(float2*)&C[(m0 + mg + g) * NN + col]     = make_float2(acc[nt][0], acc[nt][1]);
        *(float2*)&C[(m0 + mg + g + 8) * NN + col] = make_float2(acc[nt][2], acc[nt][3]);
    }
}

// ---------------------------------------------------------------------------
// Kernel 4: flash attention v6 — FIXED-MAX softmax (exact for bounded logits).
// No online max, no rescale, no in-loop reductions. BM=128, 8 warps,
// 3-stage cp.async, one __syncthreads per key-block.
// warp w: rows (w&3)*32 (two m16 tiles), key-col half (w>>2)*32.
// ---------------------------------------------------------------------------
#define KS_OFF  0            // [3][32][68]
#define VS_OFF  6528         // [3][32][68]
#define PS_OFF  13056        // per warp [32][36]
#define LUT_OFF 22272        // 128
#define LSM_OFF 22400        // 128
#define FLASH_SMEM_FLOATS 22528
#define M0BASE2 10.0f

__global__ __launch_bounds__(256, 2)
void flash_tc6(const float* __restrict__ beta_p)
{
    extern __shared__ float sm[];
    float* Lut = sm + LUT_OFF;
    float* Lsm = sm + LSM_OFF;

    int t = threadIdx.x, w = t >> 5, lane = t & 31;
    int g = lane >> 2, kq = lane & 3;
    int mg = (w & 3) * 32;
    int ch = w >> 2;
    int cb = ch * 32;
    int n0 = blockIdx.x * 128;
    int h  = blockIdx.y;

    float* Pw = sm + PS_OFF + w * (32 * 36);

    const float LOG2E = 1.4426950408889634f;
    float invb = 1.0f / (fabsf(beta_p[0]) + 1e-6f);
    const float scale2 = 0.17677669529663687f * LOG2E;
    // LUT holds decay*log2e - M0 (fixed max folded in)
    if (t < 127) Lut[t] = __expf(-(float)t * invb) * LOG2E - M0BASE2;

    const float* gq = g_q + h * HDIM * NN;
    const float* gk = g_k + h * HDIM * NN;
    const float* gv = g_v + h * HDIM * NN;

    int qy[4], qx[4];
#pragma unroll
    for (int rt = 0; rt < 2; rt++)
#pragma unroll
        for (int hf = 0; hf < 2; hf++) {
            int r = n0 + mg + rt * 16 + hf * 8 + g;
            qy[rt * 2 + hf] = r >> 6;
            qx[rt * 2 + hf] = r & 63;
        }

    uint32_t qa[2][4][4];
#pragma unroll
    for (int rt = 0; rt < 2; rt++) {
        int base = n0 + mg + rt * 16 + g;
#pragma unroll
        for (int kt = 0; kt < 4; kt++) {
            qa[rt][kt][0] = __float_as_uint(gq[(kt * 8 + kq) * NN + base]);
            qa[rt][kt][1] = __float_as_uint(gq[(kt * 8 + kq) * NN + base + 8]);
            qa[rt][kt][2] = __float_as_uint(gq[(kt * 8 + kq + 4) * NN + base]);
            qa[rt][kt][3] = __float_as_uint(gq[(kt * 8 + kq + 4) * NN + base + 8]);
        }
    }

    float o[2][4][4];
#pragma unroll
    for (int rt = 0; rt < 2; rt++)
#pragma unroll
        for (int i = 0; i < 4; i++)
#pragma unroll
            for (int j = 0; j < 4; j++) o[rt][i][j] = 0.f;
    float l[2][2] = {{0.f, 0.f}, {0.f, 0.f}};

    int id0 = t, id1 = t + 256;
    int d0f = id0 >> 4, c0f = (id0 & 15) << 2;
    int d1f = id1 >> 4, c1f = (id1 & 15) << 2;

#define PREFETCH(stage, kcol)                                                  \
    do {                                                                       \
        float* kbase = sm + KS_OFF + (stage) * 2176;                           \
        float* vbase = sm + VS_OFF + (stage) * 2176;                           \
        unsigned k0 = (unsigned)__cvta_generic_to_shared(&kbase[d0f * 68 + c0f]); \
        unsigned k1 = (unsigned)__cvta_generic_to_shared(&kbase[d1f * 68 + c1f]); \
        unsigned v0 = (unsigned)__cvta_generic_to_shared(&vbase[d0f * 68 + c0f]); \
        unsigned v1 = (unsigned)__cvta_generic_to_shared(&vbase[d1f * 68 + c1f]); \
        CP16(k0, &gk[d0f * NN + (kcol) + c0f]);                                \
        CP16(k1, &gk[d1f * NN + (kcol) + c1f]);                                \
        CP16(v0, &gv[d0f * NN + (kcol) + c0f]);                                \
        CP16(v1, &gv[d1f * NN + (kcol) + c1f]);                                \
    } while (0)

    PREFETCH(0, 0);   CP_COMMIT();
    PREFETCH(1, 64);  CP_COMMIT();

    for (int kb = 0; kb < 64; kb++) {
        int st = kb - (kb / 3) * 3;
        if (kb < 63) CP_WAIT1(); else CP_WAIT0();
        __syncthreads();
        if (kb < 62) {
            int st2 = kb + 2; st2 -= (st2 / 3) * 3;
            PREFETCH(st2, (kb + 2) * 64);
            CP_COMMIT();
        }

        const float* Ksb = sm + KS_OFF + st * 2176;
        const float* Vsb = sm + VS_OFF + st * 2176;

        // ---- S = Q K^T ----
        float s[2][4][4];
#pragma unroll
        for (int rt = 0; rt < 2; rt++)
#pragma unroll
            for (int i = 0; i < 4; i++)
#pragma unroll
                for (int j = 0; j < 4; j++) s[rt][i][j] = 0.f;
#pragma unroll
        for (int kt = 0; kt < 4; kt++) {
#pragma unroll
            for (int nt = 0; nt < 4; nt++) {
                uint32_t b0 = __float_as_uint(Ksb[(kt * 8 + kq) * 68 + cb + nt * 8 + g]);
                uint32_t b1 = __float_as_uint(Ksb[(kt * 8 + kq + 4) * 68 + cb + nt * 8 + g]);
                mma_tf32(s[0][nt], qa[0][kt], b0, b1);
                mma_tf32(s[1][nt], qa[1][kt], b0, b1);
            }
        }

        // ---- p = 2^(s*scale2 + LUT[dist]); accumulate l; stage P ----
#pragma unroll
        for (int rt = 0; rt < 2; rt++) {
#pragma unroll
            for (int nt = 0; nt < 4; nt++) {
#pragma unroll
                for (int e = 0; e < 2; e++) {
                    int col = kb * 64 + cb + nt * 8 + 2 * kq + e;
                    int ky = col >> 6, kx = col & 63;
                    float p0 = ex2f(s[rt][nt][e] * scale2
                                    + Lut[abs(qy[rt * 2] - ky) + abs(qx[rt * 2] - kx)]);
                    float p1 = ex2f(s[rt][nt][e + 2] * scale2
                                    + Lut[abs(qy[rt * 2 + 1] - ky) + abs(qx[rt * 2 + 1] - kx)]);
                    l[rt][0] += p0;
                    l[rt][1] += p1;
                    int lc = nt * 8 + 2 * kq + e;
                    Pw[(rt * 16 + g) * 36 + lc]     = tf32r(p0);
                    Pw[(rt * 16 + g + 8) * 36 + lc] = tf32r(p1);
                }
            }
        }
        __syncwarp();

        // ---- O += P V ----
#pragma unroll
        for (int kt2 = 0; kt2 < 4; kt2++) {
            uint32_t a0[4], a1[4];
            int lc = kt2 * 8 + kq;
            a0[0] = __float_as_uint(Pw[g * 36 + lc]);
            a0[1] = __float_as_uint(Pw[(g + 8) * 36 + lc]);
            a0[2] = __float_as_uint(Pw[g * 36 + lc + 4]);
            a0[3] = __float_as_uint(Pw[(g + 8) * 36 + lc + 4]);
            a1[0] = __float_as_uint(Pw[(16 + g) * 36 + lc]);
            a1[1] = __float_as_uint(Pw[(16 + g + 8) * 36 + lc]);
            a1[2] = __float_as_uint(Pw[(16 + g) * 36 + lc + 4]);
            a1[3] = __float_as_uint(Pw[(16 + g + 8) * 36 + lc + 4]);
#pragma unroll
            for (int nt2 = 0; nt2 < 4; nt2++) {
                uint32_t b0 = __float_as_uint(Vsb[(nt2 * 8 + g) * 68 + cb + kt2 * 8 + kq]);
                uint32_t b1 = __float_as_uint(Vsb[(nt2 * 8 + g) * 68 + cb + kt2 * 8 + kq + 4]);
                mma_tf32(o[0][nt2], a0, b0, b1);
                mma_tf32(o[1][nt2], a1, b0, b1);
            }
        }
    }

    // ---- reduce l over the 4 kq lanes (once) ----
#pragma unroll
    for (int rt = 0; rt < 2; rt++)
#pragma unroll
        for (int hf = 0; hf < 2; hf++) {
            l[rt][hf] += __shfl_xor_sync(0xffffffffu, l[rt][hf], 1);
            l[rt][hf] += __shfl_xor_sync(0xffffffffu, l[rt][hf], 2);
        }

    // ---- merge split-K halves: O = (O_a + O_b) / (l_a + l_b) ----
    float* Om = sm + PS_OFF;   // reuse [128][36]
    __syncthreads();
    if (ch == 1) {
#pragma unroll
        for (int rt = 0; rt < 2; rt++) {
            int rb_ = mg + rt * 16;
            Lsm[rb_ + g] = l[rt][0];  Lsm[rb_ + g + 8] = l[rt][1];
#pragma unroll
            for (int nt = 0; nt < 4; nt++) {
                int d0 = nt * 8 + 2 * kq;
                Om[(rb_ + g) * 36 + d0]         = o[rt][nt][0];
                Om[(rb_ + g) * 36 + d0 + 1]     = o[rt][nt][1];
                Om[(rb_ + g + 8) * 36 + d0]     = o[rt][nt][2];
                Om[(rb_ + g + 8) * 36 + d0 + 1] = o[rt][nt][3];
            }
        }
    }
    __syncthreads();
    if (ch == 0) {
#pragma unroll
        for (int rt = 0; rt < 2; rt++) {
            int rb_ = mg + rt * 16;
            float iL0 = 1.0f / (l[rt][0] + Lsm[rb_ + g]);
            float iL1 = 1.0f / (l[rt][1] + Lsm[rb_ + g + 8]);
#pragma unroll
            for (int nt = 0; nt < 4; nt++) {
                int d0 = nt * 8 + 2 * kq;
                Om[(rb_ + g) * 36 + d0]         = (o[rt][nt][0] + Om[(rb_ + g) * 36 + d0])     * iL0;
                Om[(rb_ + g) * 36 + d0 + 1]     = (o[rt][nt][1] + Om[(rb_ + g) * 36 + d0 + 1]) * iL0;
                Om[(rb_ + g + 8) * 36 + d0]     = (o[rt][nt][2] + Om[(rb_ + g + 8) * 36 + d0])     * iL1;
                Om[(rb_ + g + 8) * 36 + d0 + 1] = (o[rt][nt][3] + Om[(rb_ + g + 8) * 36 + d0 + 1]) * iL1;
            }
        }
    }
    __syncthreads();

    float* go = g_ao + h * HDIM * NN;
    for (int idx = t; idx < 4096; idx += 256) {
        int r = idx & 127, d = idx >> 7;
        go[d * NN + n0 + r] = Om[r * 36 + d];
    }
}

// ---------------------------------------------------------------------------
extern "C" void kernel_launch(void* const* d_in, const int* in_sizes, int n_in,
                              void* d_out, int out_size)
{
    const float* x   = (const float*)d_in[0];
    const float* ow  = (const float*)d_in[1];
    const float* w3  = (const float*)d_in[2];
    const float* w5  = (const float*)d_in[3];
    const float* w7  = (const float*)d_in[4];
    const float* wop = (const float*)d_in[5];
    const float* wq  = (const float*)d_in[6];
    const float* wk  = (const float*)d_in[7];
    const float* wv  = (const float*)d_in[8];
    const float* wo  = (const float*)d_in[9];
    const float* beta = (const float*)d_in[10];
    float* out = (float*)d_out;

    static int smem_set = 0;
    if (!smem_set) {
        cudaFuncSetAttribute(flash_tc6, cudaFuncAttributeMaxDynamicSharedMemorySize,
                             FLASH_SMEM_FLOATS * 4);
        smem_set = 1;
    }

    conv_offset_fused<<<dim3(16, 8), 256>>>(x, ow, w3, w5, w7, wop);    // 1
    sample_kernel<<<dim3(16, 256), 256>>>(x);                           // 2
    tcgemm<<<dim3(64, 4, 3), 256>>>(wq, wk, wv, 3, x, nullptr);         // 3: q,k,v
    flash_tc6<<<dim3(32, 8), 256, FLASH_SMEM_FLOATS * 4>>>(beta);       // 4 (profiled)
    tcgemm<<<dim3(64, 4, 1), 256>>>(wo, nullptr, nullptr, 2, nullptr, out); // 5
}

// round 7
// speedup vs baseline: 4.0221x; 1.0973x over previous
#include <cuda_runtime.h>
#include <math.h>
#include <stdint.h>

// Problem constants
#define HH 64
#define WW 64
#define NN 4096            // H*W
#define CC 256
#define NHEADS 8
#define HDIM 32

// ---------------- scratch (device globals; no allocation allowed) ----------
__device__ float g_part[8 * 2 * NN];
__device__ int   g_ctr[16];          // last-block counters (self-resetting)
__device__ float g_ixy[2 * NN];
__device__ float g_xs[CC * NN];
__device__ float g_q[CC * NN];   // pre-rounded to tf32
__device__ float g_k[CC * NN];   // pre-rounded to tf32
__device__ float g_v[CC * NN];   // pre-rounded to tf32
__device__ float g_ao[CC * NN];

__device__ __forceinline__ float tf32r(float x) {
    asm("cvt.rna.tf32.f32 %0, %0;" : "+f"(x));
    return x;
}
__device__ __forceinline__ float4 tf32r4(float4 v) {
    v.x = tf32r(v.x); v.y = tf32r(v.y); v.z = tf32r(v.z); v.w = tf32r(v.w);
    return v;
}
__device__ __forceinline__ float ex2f(float x) {
    float y;
    asm("ex2.approx.ftz.f32 %0, %1;" : "=f"(y) : "f"(x));
    return y;
}
__device__ __forceinline__ void mma_tf32(float c[4], const uint32_t a[4],
                                         uint32_t b0, uint32_t b1) {
    asm volatile(
        "mma.sync.aligned.m16n8k8.row.col.f32.tf32.tf32.f32 "
        "{%0,%1,%2,%3},{%4,%5,%6,%7},{%8,%9},{%0,%1,%2,%3};"
        : "+f"(c[0]), "+f"(c[1]), "+f"(c[2]), "+f"(c[3])
        : "r"(a[0]), "r"(a[1]), "r"(a[2]), "r"(a[3]), "r"(b0), "r"(b1));
}
#define CP16(dst, src) \
    asm volatile("cp.async.ca.shared.global [%0], [%1], 16;" \
                 :: "r"(dst), "l"(src))
#define CP_COMMIT() asm volatile("cp.async.commit_group;")
#define CP_WAIT1()  asm volatile("cp.async.wait_group 1;")
#define CP_WAIT0()  asm volatile("cp.async.wait_group 0;")

// ---------------------------------------------------------------------------
// Kernel 1: depthwise conv -> relu -> offset proj, fused reduction + coords
// ---------------------------------------------------------------------------
__global__ __launch_bounds__(256)
void conv_offset_fused(const float* __restrict__ x,
                       const float* __restrict__ ow,
                       const float* __restrict__ w3,
                       const float* __restrict__ w5,
                       const float* __restrict__ w7,
                       const float* __restrict__ wproj)
{
    __shared__ float swc[32 * 49];
    __shared__ float swp[2][32];
    __shared__ int isLast;
    int t = threadIdx.x;
    int cz = blockIdx.y * 32;
    float ow0 = ow[0], ow1 = ow[1], ow2 = ow[2];

    for (int idx = t; idx < 32 * 49; idx += 256) {
        int c = idx / 49, ji = idx % 49;
        int j = ji / 7, i = ji % 7;
        float v = w7[(cz + c) * 49 + ji] * ow2;
        if (j >= 1 && j <= 5 && i >= 1 && i <= 5)
            v += w5[(cz + c) * 25 + (j - 1) * 5 + (i - 1)] * ow1;
        if (j >= 2 && j <= 4 && i >= 2 && i <= 4)
            v += w3[(cz + c) * 9 + (j - 2) * 3 + (i - 2)] * ow0;
        swc[idx] = v;
    }
    if (t < 32) {
        swp[0][t] = wproj[cz + t];
        swp[1][t] = wproj[CC + cz + t];
    }
    __syncthreads();

    int p = blockIdx.x * 256 + t;
    int py = p >> 6, px = p & 63;

    float a0 = 0.f, a1 = 0.f;
    for (int c = 0; c < 32; c++) {
        const float* xc = x + (cz + c) * NN;
        const float* wc = swc + c * 49;
        float feat = 0.f;
#pragma unroll
        for (int j = 0; j < 7; j++) {
            int yy = py + j - 3;
            bool yok = (yy >= 0) & (yy < HH);
#pragma unroll
            for (int i = 0; i < 7; i++) {
                int xx = px + i - 3;
                float v = (yok && xx >= 0 && xx < WW) ? xc[yy * WW + xx] : 0.f;
                feat += v * wc[j * 7 + i];
            }
        }
        feat = fmaxf(feat, 0.f);
        a0 += feat * swp[0][c];
        a1 += feat * swp[1][c];
    }
    g_part[(blockIdx.y * 2 + 0) * NN + p] = a0;
    g_part[(blockIdx.y * 2 + 1) * NN + p] = a1;

    __threadfence();
    if (t == 0) {
        int old = atomicAdd(&g_ctr[blockIdx.x], 1);
        isLast = (old == 7);
    }
    __syncthreads();
    if (isLast) {
        __threadfence();
        float offy = 0.f, offx = 0.f;
#pragma unroll
        for (int g = 0; g < 8; g++) {
            offy += g_part[(g * 2 + 0) * NN + p];
            offx += g_part[(g * 2 + 1) * NN + p];
        }
        float refy = ((py + 0.5f) / 63.0f) * 2.0f - 1.0f;
        float refx = ((px + 0.5f) / 63.0f) * 2.0f - 1.0f;
        float gy = fminf(fmaxf(refy + tanhf(offy) * 2.0f, -1.0f), 1.0f);
        float gx = fminf(fmaxf(refx + tanhf(offx) * 2.0f, -1.0f), 1.0f);
        g_ixy[p]      = (gx + 1.0f) * 0.5f * 63.0f;
        g_ixy[NN + p] = (gy + 1.0f) * 0.5f * 63.0f;
        if (t == 0) g_ctr[blockIdx.x] = 0;
    }
}

// ---------------------------------------------------------------------------
// Kernel 2: bilinear grid sample
// ---------------------------------------------------------------------------
__global__ __launch_bounds__(256)
void sample_kernel(const float* __restrict__ x)
{
    int p = blockIdx.x * 256 + threadIdx.x;
    int c = blockIdx.y;
    float ix = g_ixy[p], iy = g_ixy[NN + p];
    float x0f = floorf(ix), y0f = floorf(iy);
    float fx = ix - x0f, fy = iy - y0f;
    int x0 = min(max((int)x0f, 0), WW - 1);
    int x1 = min(x0 + 1, WW - 1);
    int y0 = min(max((int)y0f, 0), HH - 1);
    int y1 = min(y0 + 1, HH - 1);
    const float* xc = x + c * NN;
    float v00 = xc[y0 * WW + x0], v01 = xc[y0 * WW + x1];
    float v10 = xc[y1 * WW + x0], v11 = xc[y1 * WW + x1];
    g_xs[c * NN + p] = v00 * (1.f - fx) * (1.f - fy) + v01 * fx * (1.f - fy)
                     + v10 * (1.f - fx) * fy + v11 * fx * fy;
}

// ---------------------------------------------------------------------------
// Kernel 3: tf32 tensor-core GEMM  C[256,4096] = A[256,256] * B[256,4096]
// ---------------------------------------------------------------------------
__global__ __launch_bounds__(256)
void tcgemm(const float* __restrict__ A0, const float* __restrict__ A1,
            const float* __restrict__ A2, int mode,
            const float* __restrict__ Bext, float* __restrict__ Cext)
{
    const float* A; const float* B; float* C; bool rnd;
    if (mode == 3) {
        int z = blockIdx.z;
        A = (z == 0) ? A0 : (z == 1) ? A1 : A2;
        B = (z == 0) ? Bext : g_xs;
        C = (z == 0) ? g_q : (z == 1) ? g_k : g_v;
        rnd = true;
    } else {
        A = A0; B = g_ao; C = Cext; rnd = false;
    }

    __shared__ float As[2][64][36];
    __shared__ float Bs[2][32][72];

    int t = threadIdx.x, w = t >> 5, lane = t & 31;
    int g = lane >> 2, kq = lane & 3;
    int mg = (w >> 1) * 16, nc = (w & 1) * 32;
    int m0 = blockIdx.y * 64, n0 = blockIdx.x * 64;

    float acc[4][4];
#pragma unroll
    for (int i = 0; i < 4; i++)
#pragma unroll
        for (int j = 0; j < 4; j++) acc[i][j] = 0.f;

    int am[2], ak;  ak = (t & 7) * 4;
    am[0] = t >> 3; am[1] = (t >> 3) + 32;
    int bk[2], bn;  bn = (t & 15) * 4;
    bk[0] = t >> 4; bk[1] = (t >> 4) + 16;

    float4 ra[2], rb[2];
#pragma unroll
    for (int j = 0; j < 2; j++) {
        ra[j] = tf32r4(*(const float4*)&A[(m0 + am[j]) * 256 + ak]);
        rb[j] = tf32r4(*(const float4*)&B[bk[j] * NN + n0 + bn]);
    }

    for (int ki = 0; ki < 8; ki++) {
        int b = ki & 1;
#pragma unroll
        for (int j = 0; j < 2; j++) {
            *(float4*)&As[b][am[j]][ak] = ra[j];
            *(float4*)&Bs[b][bk[j]][bn] = rb[j];
        }
        __syncthreads();
        if (ki < 7) {
            int k0 = (ki + 1) * 32;
#pragma unroll
            for (int j = 0; j < 2; j++) {
                ra[j] = tf32r4(*(const float4*)&A[(m0 + am[j]) * 256 + k0 + ak]);
                rb[j] = tf32r4(*(const float4*)&B[(k0 + bk[j]) * NN + n0 + bn]);
            }
        }
#pragma unroll
        for (int kt = 0; kt < 4; kt++) {
            uint32_t a[4];
            a[0] = __float_as_uint(As[b][mg + g][kt * 8 + kq]);
            a[1] = __float_as_uint(As[b][mg + g + 8][kt * 8 + kq]);
            a[2] = __float_as_uint(As[b][mg + g][kt * 8 + kq + 4]);
            a[3] = __float_as_uint(As[b][mg + g + 8][kt * 8 + kq + 4]);
#pragma unroll
            for (int nt = 0; nt < 4; nt++) {
                uint32_t b0 = __float_as_uint(Bs[b][kt * 8 + kq][nc + nt * 8 + g]);
                uint32_t b1 = __float_as_uint(Bs[b][kt * 8 + kq + 4][nc + nt * 8 + g]);
                mma_tf32(acc[nt], a, b0, b1);
            }
        }
    }

    if (rnd) {
#pragma unroll
        for (int i = 0; i < 4; i++)
#pragma unroll
            for (int j = 0; j < 4; j++) acc[i][j] = tf32r(acc[i][j]);
    }
#pragma unroll
    for (int nt = 0; nt < 4; nt++) {
        int col = n0 + nc + nt * 8 + 2 * kq;
        *(float2*)&C[(m0 + mg + g) * NN + col]     = make_float2(acc[nt][0], acc[nt][1]);
        *(float2*)&C[(m0 + mg + g + 8) * NN + col] = make_float2(acc[nt][2], acc[nt][3]);
    }
}

// ---------------------------------------------------------------------------
// Kernel 4: flash attention v7 — P kept in registers.
// C-fragment of QK^T reused directly as A-fragment of PV under the key
// permutation pi=[0,2,4,6,1,3,5,7] per 8-key group; V B-fragments are loaded
// at keys (2kq, 2kq+1) via one float2 LDS.64. No P smem round-trip.
// Fixed-max softmax (exact, bounded logits). ky == kb identity used for bias.
// ---------------------------------------------------------------------------
#define KS_OFF  0            // [3][32][68]
#define VS_OFF  6528         // [3][32][68]
#define LUT_OFF 13056        // 128
#define LSM_OFF 13184        // 128
#define FLASH_SMEM_FLOATS 13312
#define M0BASE2 10.0f

__global__ __launch_bounds__(256, 2)
void flash_tc7(const float* __restrict__ beta_p)
{
    extern __shared__ float sm[];
    float* Lut = sm + LUT_OFF;
    float* Lsm = sm + LSM_OFF;

    int t = threadIdx.x, w = t >> 5, lane = t & 31;
    int g = lane >> 2, kq = lane & 3;
    int mg = (w & 3) * 32;
    int ch = w >> 2;
    int cb = ch * 32;
    int n0 = blockIdx.x * 128;
    int h  = blockIdx.y;

    const float LOG2E = 1.4426950408889634f;
    float invb = 1.0f / (fabsf(beta_p[0]) + 1e-6f);
    const float scale2 = 0.17677669529663687f * LOG2E;
    if (t < 127) Lut[t] = __expf(-(float)t * invb) * LOG2E - M0BASE2;

    const float* gq = g_q + h * HDIM * NN;
    const float* gk = g_k + h * HDIM * NN;
    const float* gv = g_v + h * HDIM * NN;

    int qy[4], qx[4];
#pragma unroll
    for (int rt = 0; rt < 2; rt++)
#pragma unroll
        for (int hf = 0; hf < 2; hf++) {
            int r = n0 + mg + rt * 16 + hf * 8 + g;
            qy[rt * 2 + hf] = r >> 6;
            qx[rt * 2 + hf] = r & 63;
        }

    uint32_t qa[2][4][4];
#pragma unroll
    for (int rt = 0; rt < 2; rt++) {
        int base = n0 + mg + rt * 16 + g;
#pragma unroll
        for (int kt = 0; kt < 4; kt++) {
            qa[rt][kt][0] = __float_as_uint(gq[(kt * 8 + kq) * NN + base]);
            qa[rt][kt][1] = __float_as_uint(gq[(kt * 8 + kq) * NN + base + 8]);
            qa[rt][kt][2] = __float_as_uint(gq[(kt * 8 + kq + 4) * NN + base]);
            qa[rt][kt][3] = __float_as_uint(gq[(kt * 8 + kq + 4) * NN + base + 8]);
        }
    }

    float o[2][4][4];
#pragma unroll
    for (int rt = 0; rt < 2; rt++)
#pragma unroll
        for (int i = 0; i < 4; i++)
#pragma unroll
            for (int j = 0; j < 4; j++) o[rt][i][j] = 0.f;
    float l[2][2] = {{0.f, 0.f}, {0.f, 0.f}};

    int id0 = t, id1 = t + 256;
    int d0f = id0 >> 4, c0f = (id0 & 15) << 2;
    int d1f = id1 >> 4, c1f = (id1 & 15) << 2;

#define PREFETCH(stage, kcol)                                                  \
    do {                                                                       \
        float* kbase = sm + KS_OFF + (stage) * 2176;                           \
        float* vbase = sm + VS_OFF + (stage) * 2176;                           \
        unsigned k0 = (unsigned)__cvta_generic_to_shared(&kbase[d0f * 68 + c0f]); \
        unsigned k1 = (unsigned)__cvta_generic_to_shared(&kbase[d1f * 68 + c1f]); \
        unsigned v0 = (unsigned)__cvta_generic_to_shared(&vbase[d0f * 68 + c0f]); \
        unsigned v1 = (unsigned)__cvta_generic_to_shared(&vbase[d1f * 68 + c1f]); \
        CP16(k0, &gk[d0f * NN + (kcol) + c0f]);                                \
        CP16(k1, &gk[d1f * NN + (kcol) + c1f]);                                \
        CP16(v0, &gv[d0f * NN + (kcol) + c0f]);                                \
        CP16(v1, &gv[d1f * NN + (kcol) + c1f]);                                \
    } while (0)

    PREFETCH(0, 0);   CP_COMMIT();
    PREFETCH(1, 64);  CP_COMMIT();

    for (int kb = 0; kb < 64; kb++) {
        int st = kb - (kb / 3) * 3;
        if (kb < 63) CP_WAIT1(); else CP_WAIT0();
        __syncthreads();
        if (kb < 62) {
            int st2 = kb + 2; st2 -= (st2 / 3) * 3;
            PREFETCH(st2, (kb + 2) * 64);
            CP_COMMIT();
        }

        const float* Ksb = sm + KS_OFF + st * 2176;
        const float* Vsb = sm + VS_OFF + st * 2176;

        // ---- S = Q K^T ----
        float s[2][4][4];
#pragma unroll
        for (int rt = 0; rt < 2; rt++)
#pragma unroll
            for (int i = 0; i < 4; i++)
#pragma unroll
                for (int j = 0; j < 4; j++) s[rt][i][j] = 0.f;
#pragma unroll
        for (int kt = 0; kt < 4; kt++) {
#pragma unroll
            for (int nt = 0; nt < 4; nt++) {
                uint32_t b0 = __float_as_uint(Ksb[(kt * 8 + kq) * 68 + cb + nt * 8 + g]);
                uint32_t b1 = __float_as_uint(Ksb[(kt * 8 + kq + 4) * 68 + cb + nt * 8 + g]);
                mma_tf32(s[0][nt], qa[0][kt], b0, b1);
                mma_tf32(s[1][nt], qa[1][kt], b0, b1);
            }
        }

        // ---- p = 2^(s*scale2 + LUT[dist]); key y == kb for all keys ----
#pragma unroll
        for (int rt = 0; rt < 2; rt++) {
            int dyA = abs(qy[rt * 2]     - kb);
            int dyB = abs(qy[rt * 2 + 1] - kb);
            int qxA = qx[rt * 2], qxB = qx[rt * 2 + 1];
#pragma unroll
            for (int nt = 0; nt < 4; nt++) {
                int ccb = cb + nt * 8 + 2 * kq;
#pragma unroll
                for (int e = 0; e < 2; e++) {
                    int cc = ccb + e;
                    float p0 = ex2f(s[rt][nt][e]     * scale2 + Lut[dyA + abs(qxA - cc)]);
                    float p1 = ex2f(s[rt][nt][e + 2] * scale2 + Lut[dyB + abs(qxB - cc)]);
                    l[rt][0] += p0;
                    l[rt][1] += p1;
                    s[rt][nt][e]     = tf32r(p0);
                    s[rt][nt][e + 2] = tf32r(p1);
                }
            }
        }

        // ---- O += P V : P stays in registers (pi-permuted A-frag),
        //      V rows loaded at keys (2kq, 2kq+1) as one float2 ----
#pragma unroll
        for (int kt2 = 0; kt2 < 4; kt2++) {
            uint32_t a0[4], a1[4];
            a0[0] = __float_as_uint(s[0][kt2][0]);
            a0[1] = __float_as_uint(s[0][kt2][2]);
            a0[2] = __float_as_uint(s[0][kt2][1]);
            a0[3] = __float_as_uint(s[0][kt2][3]);
            a1[0] = __float_as_uint(s[1][kt2][0]);
            a1[1] = __float_as_uint(s[1][kt2][2]);
            a1[2] = __float_as_uint(s[1][kt2][1]);
            a1[3] = __float_as_uint(s[1][kt2][3]);
#pragma unroll
            for (int nt2 = 0; nt2 < 4; nt2++) {
                float2 b01 = *(const float2*)&Vsb[(nt2 * 8 + g) * 68 + cb + kt2 * 8 + 2 * kq];
                uint32_t b0 = __float_as_uint(b01.x);
                uint32_t b1 = __float_as_uint(b01.y);
                mma_tf32(o[0][nt2], a0, b0, b1);
                mma_tf32(o[1][nt2], a1, b0, b1);
            }
        }
    }

    // ---- reduce l over the 4 kq lanes (once) ----
#pragma unroll
    for (int rt = 0; rt < 2; rt++)
#pragma unroll
        for (int hf = 0; hf < 2; hf++) {
            l[rt][hf] += __shfl_xor_sync(0xffffffffu, l[rt][hf], 1);
            l[rt][hf] += __shfl_xor_sync(0xffffffffu, l[rt][hf], 2);
        }

    // ---- merge split-K halves: O = (O_a + O_b) / (l_a + l_b) ----
    float* Om = sm;   // reuse KS region [128][36] (4608 <= 6528 floats)
    __syncthreads();
    if (ch == 1) {
#pragma unroll
        for (int rt = 0; rt < 2; rt++) {
            int rb_ = mg + rt * 16;
            Lsm[rb_ + g] = l[rt][0];  Lsm[rb_ + g + 8] = l[rt][1];
#pragma unroll
            for (int nt = 0; nt < 4; nt++) {
                int d0 = nt * 8 + 2 * kq;
                Om[(rb_ + g) * 36 + d0]         = o[rt][nt][0];
                Om[(rb_ + g) * 36 + d0 + 1]     = o[rt][nt][1];
                Om[(rb_ + g + 8) * 36 + d0]     = o[rt][nt][2];
                Om[(rb_ + g + 8) * 36 + d0 + 1] = o[rt][nt][3];
            }
        }
    }
    __syncthreads();
    if (ch == 0) {
#pragma unroll
        for (int rt = 0; rt < 2; rt++) {
            int rb_ = mg + rt * 16;
            float iL0 = 1.0f / (l[rt][0] + Lsm[rb_ + g]);
            float iL1 = 1.0f / (l[rt][1] + Lsm[rb_ + g + 8]);
#pragma unroll
            for (int nt = 0; nt < 4; nt++) {
                int d0 = nt * 8 + 2 * kq;
                Om[(rb_ + g) * 36 + d0]         = (o[rt][nt][0] + Om[(rb_ + g) * 36 + d0])     * iL0;
                Om[(rb_ + g) * 36 + d0 + 1]     = (o[rt][nt][1] + Om[(rb_ + g) * 36 + d0 + 1]) * iL0;
                Om[(rb_ + g + 8) * 36 + d0]     = (o[rt][nt][2] + Om[(rb_ + g + 8) * 36 + d0])     * iL1;
                Om[(rb_ + g + 8) * 36 + d0 + 1] = (o[rt][nt][3] + Om[(rb_ + g + 8) * 36 + d0 + 1]) * iL1;
            }
        }
    }
    __syncthreads();

    float* go = g_ao + h * HDIM * NN;
    for (int idx = t; idx < 4096; idx += 256) {
        int r = idx & 127, d = idx >> 7;
        go[d * NN + n0 + r] = Om[r * 36 + d];
    }
}

// ---------------------------------------------------------------------------
extern "C" void kernel_launch(void* const* d_in, const int* in_sizes, int n_in,
                              void* d_out, int out_size)
{
    const float* x   = (const float*)d_in[0];
    const float* ow  = (const float*)d_in[1];
    const float* w3  = (const float*)d_in[2];
    const float* w5  = (const float*)d_in[3];
    const float* w7  = (const float*)d_in[4];
    const float* wop = (const float*)d_in[5];
    const float* wq  = (const float*)d_in[6];
    const float* wk  = (const float*)d_in[7];
    const float* wv  = (const float*)d_in[8];
    const float* wo  = (const float*)d_in[9];
    const float* beta = (const float*)d_in[10];
    float* out = (float*)d_out;

    static int smem_set = 0;
    if (!smem_set) {
        cudaFuncSetAttribute(flash_tc7, cudaFuncAttributeMaxDynamicSharedMemorySize,
                             FLASH_SMEM_FLOATS * 4);
        smem_set = 1;
    }

    conv_offset_fused<<<dim3(16, 8), 256>>>(x, ow, w3, w5, w7, wop);    // 1
    sample_kernel<<<dim3(16, 256), 256>>>(x);                           // 2
    tcgemm<<<dim3(64, 4, 3), 256>>>(wq, wk, wv, 3, x, nullptr);         // 3: q,k,v
    flash_tc7<<<dim3(32, 8), 256, FLASH_SMEM_FLOATS * 4>>>(beta);       // 4 (profiled)
    tcgemm<<<dim3(64, 4, 1), 256>>>(wo, nullptr, nullptr, 2, nullptr, out); // 5
}

// round 8
// speedup vs baseline: 4.0526x; 1.0076x over previous
#include <cuda_runtime.h>
#include <math.h>
#include <stdint.h>

// Problem constants
#define HH 64
#define WW 64
#define NN 4096            // H*W
#define CC 256
#define NHEADS 8
#define HDIM 32

// ---------------- scratch (device globals; no allocation allowed) ----------
__device__ float g_part[8 * 2 * NN];
__device__ int   g_ctr[16];
__device__ float g_ixy[2 * NN];
__device__ float g_xs[CC * NN];
__device__ float g_q[CC * NN];   // [d][N], tf32-rounded
__device__ float g_k[CC * NN];   // TRANSPOSED: [head][N][32], tf32-rounded
__device__ float g_v[CC * NN];   // [d][N], tf32-rounded
__device__ float g_ao[CC * NN];

__device__ __forceinline__ float tf32r(float x) {
    asm("cvt.rna.tf32.f32 %0, %0;" : "+f"(x));
    return x;
}
__device__ __forceinline__ float4 tf32r4(float4 v) {
    v.x = tf32r(v.x); v.y = tf32r(v.y); v.z = tf32r(v.z); v.w = tf32r(v.w);
    return v;
}
__device__ __forceinline__ float ex2f(float x) {
    float y;
    asm("ex2.approx.ftz.f32 %0, %1;" : "=f"(y) : "f"(x));
    return y;
}
__device__ __forceinline__ void mma_tf32(float c[4], const uint32_t a[4],
                                         uint32_t b0, uint32_t b1) {
    asm volatile(
        "mma.sync.aligned.m16n8k8.row.col.f32.tf32.tf32.f32 "
        "{%0,%1,%2,%3},{%4,%5,%6,%7},{%8,%9},{%0,%1,%2,%3};"
        : "+f"(c[0]), "+f"(c[1]), "+f"(c[2]), "+f"(c[3])
        : "r"(a[0]), "r"(a[1]), "r"(a[2]), "r"(a[3]), "r"(b0), "r"(b1));
}
#define CP16(dst, src) \
    asm volatile("cp.async.ca.shared.global [%0], [%1], 16;" \
                 :: "r"(dst), "l"(src))
#define CP_COMMIT() asm volatile("cp.async.commit_group;")
#define CP_WAIT1()  asm volatile("cp.async.wait_group 1;")
#define CP_WAIT0()  asm volatile("cp.async.wait_group 0;")

// ---------------------------------------------------------------------------
// Kernel 1: depthwise conv -> relu -> offset proj, fused reduction + coords
// ---------------------------------------------------------------------------
__global__ __launch_bounds__(256)
void conv_offset_fused(const float* __restrict__ x,
                       const float* __restrict__ ow,
                       const float* __restrict__ w3,
                       const float* __restrict__ w5,
                       const float* __restrict__ w7,
                       const float* __restrict__ wproj)
{
    __shared__ float swc[32 * 49];
    __shared__ float swp[2][32];
    __shared__ int isLast;
    int t = threadIdx.x;
    int cz = blockIdx.y * 32;
    float ow0 = ow[0], ow1 = ow[1], ow2 = ow[2];

    for (int idx = t; idx < 32 * 49; idx += 256) {
        int c = idx / 49, ji = idx % 49;
        int j = ji / 7, i = ji % 7;
        float v = w7[(cz + c) * 49 + ji] * ow2;
        if (j >= 1 && j <= 5 && i >= 1 && i <= 5)
            v += w5[(cz + c) * 25 + (j - 1) * 5 + (i - 1)] * ow1;
        if (j >= 2 && j <= 4 && i >= 2 && i <= 4)
            v += w3[(cz + c) * 9 + (j - 2) * 3 + (i - 2)] * ow0;
        swc[idx] = v;
    }
    if (t < 32) {
        swp[0][t] = wproj[cz + t];
        swp[1][t] = wproj[CC + cz + t];
    }
    __syncthreads();

    int p = blockIdx.x * 256 + t;
    int py = p >> 6, px = p & 63;

    float a0 = 0.f, a1 = 0.f;
    for (int c = 0; c < 32; c++) {
        const float* xc = x + (cz + c) * NN;
        const float* wc = swc + c * 49;
        float feat = 0.f;
#pragma unroll
        for (int j = 0; j < 7; j++) {
            int yy = py + j - 3;
            bool yok = (yy >= 0) & (yy < HH);
#pragma unroll
            for (int i = 0; i < 7; i++) {
                int xx = px + i - 3;
                float v = (yok && xx >= 0 && xx < WW) ? xc[yy * WW + xx] : 0.f;
                feat += v * wc[j * 7 + i];
            }
        }
        feat = fmaxf(feat, 0.f);
        a0 += feat * swp[0][c];
        a1 += feat * swp[1][c];
    }
    g_part[(blockIdx.y * 2 + 0) * NN + p] = a0;
    g_part[(blockIdx.y * 2 + 1) * NN + p] = a1;

    __threadfence();
    if (t == 0) {
        int old = atomicAdd(&g_ctr[blockIdx.x], 1);
        isLast = (old == 7);
    }
    __syncthreads();
    if (isLast) {
        __threadfence();
        float offy = 0.f, offx = 0.f;
#pragma unroll
        for (int g = 0; g < 8; g++) {
            offy += g_part[(g * 2 + 0) * NN + p];
            offx += g_part[(g * 2 + 1) * NN + p];
        }
        float refy = ((py + 0.5f) / 63.0f) * 2.0f - 1.0f;
        float refx = ((px + 0.5f) / 63.0f) * 2.0f - 1.0f;
        float gy = fminf(fmaxf(refy + tanhf(offy) * 2.0f, -1.0f), 1.0f);
        float gx = fminf(fmaxf(refx + tanhf(offx) * 2.0f, -1.0f), 1.0f);
        g_ixy[p]      = (gx + 1.0f) * 0.5f * 63.0f;
        g_ixy[NN + p] = (gy + 1.0f) * 0.5f * 63.0f;
        if (t == 0) g_ctr[blockIdx.x] = 0;
    }
}

// ---------------------------------------------------------------------------
// Kernel 2: bilinear grid sample
// ---------------------------------------------------------------------------
__global__ __launch_bounds__(256)
void sample_kernel(const float* __restrict__ x)
{
    int p = blockIdx.x * 256 + threadIdx.x;
    int c = blockIdx.y;
    float ix = g_ixy[p], iy = g_ixy[NN + p];
    float x0f = floorf(ix), y0f = floorf(iy);
    float fx = ix - x0f, fy = iy - y0f;
    int x0 = min(max((int)x0f, 0), WW - 1);
    int x1 = min(x0 + 1, WW - 1);
    int y0 = min(max((int)y0f, 0), HH - 1);
    int y1 = min(y0 + 1, HH - 1);
    const float* xc = x + c * NN;
    float v00 = xc[y0 * WW + x0], v01 = xc[y0 * WW + x1];
    float v10 = xc[y1 * WW + x0], v11 = xc[y1 * WW + x1];
    g_xs[c * NN + p] = v00 * (1.f - fx) * (1.f - fy) + v01 * fx * (1.f - fy)
                     + v10 * (1.f - fx) * fy + v11 * fx * fy;
}

// ---------------------------------------------------------------------------
// Kernel 3: tf32 tensor-core GEMM  C[256,4096] = A[256,256] * B[256,4096]
// mode 3 z=0: wq@x  -> g_q [d][N]
//        z=1: wk@xs -> g_k TRANSPOSED [head][N][32]
//        z=2: wv@xs -> g_v [d][N]
// mode 2: wo@g_ao -> Cext
// ---------------------------------------------------------------------------
__global__ __launch_bounds__(256)
void tcgemm(const float* __restrict__ A0, const float* __restrict__ A1,
            const float* __restrict__ A2, int mode,
            const float* __restrict__ Bext, float* __restrict__ Cext)
{
    const float* A; const float* B; float* C; bool rnd;
    int z = blockIdx.z;
    if (mode == 3) {
        A = (z == 0) ? A0 : (z == 1) ? A1 : A2;
        B = (z == 0) ? Bext : g_xs;
        C = (z == 0) ? g_q : (z == 1) ? g_k : g_v;
        rnd = true;
    } else {
        A = A0; B = g_ao; C = Cext; rnd = false;
    }

    __shared__ float As[2][64][36];
    __shared__ float Bs[2][32][72];

    int t = threadIdx.x, w = t >> 5, lane = t & 31;
    int g = lane >> 2, kq = lane & 3;
    int mg = (w >> 1) * 16, nc = (w & 1) * 32;
    int m0 = blockIdx.y * 64, n0 = blockIdx.x * 64;

    float acc[4][4];
#pragma unroll
    for (int i = 0; i < 4; i++)
#pragma unroll
        for (int j = 0; j < 4; j++) acc[i][j] = 0.f;

    int am[2], ak;  ak = (t & 7) * 4;
    am[0] = t >> 3; am[1] = (t >> 3) + 32;
    int bk[2], bn;  bn = (t & 15) * 4;
    bk[0] = t >> 4; bk[1] = (t >> 4) + 16;

    float4 ra[2], rb[2];
#pragma unroll
    for (int j = 0; j < 2; j++) {
        ra[j] = tf32r4(*(const float4*)&A[(m0 + am[j]) * 256 + ak]);
        rb[j] = tf32r4(*(const float4*)&B[bk[j] * NN + n0 + bn]);
    }

    for (int ki = 0; ki < 8; ki++) {
        int b = ki & 1;
#pragma unroll
        for (int j = 0; j < 2; j++) {
            *(float4*)&As[b][am[j]][ak] = ra[j];
            *(float4*)&Bs[b][bk[j]][bn] = rb[j];
        }
        __syncthreads();
        if (ki < 7) {
            int k0 = (ki + 1) * 32;
#pragma unroll
            for (int j = 0; j < 2; j++) {
                ra[j] = tf32r4(*(const float4*)&A[(m0 + am[j]) * 256 + k0 + ak]);
                rb[j] = tf32r4(*(const float4*)&B[(k0 + bk[j]) * NN + n0 + bn]);
            }
        }
#pragma unroll
        for (int kt = 0; kt < 4; kt++) {
            uint32_t a[4];
            a[0] = __float_as_uint(As[b][mg + g][kt * 8 + kq]);
            a[1] = __float_as_uint(As[b][mg + g + 8][kt * 8 + kq]);
            a[2] = __float_as_uint(As[b][mg + g][kt * 8 + kq + 4]);
            a[3] = __float_as_uint(As[b][mg + g + 8][kt * 8 + kq + 4]);
#pragma unroll
            for (int nt = 0; nt < 4; nt++) {
                uint32_t b0 = __float_as_uint(Bs[b][kt * 8 + kq][nc + nt * 8 + g]);
                uint32_t b1 = __float_as_uint(Bs[b][kt * 8 + kq + 4][nc + nt * 8 + g]);
                mma_tf32(acc[nt], a, b0, b1);
            }
        }
    }

    if (rnd) {
#pragma unroll
        for (int i = 0; i < 4; i++)
#pragma unroll
            for (int j = 0; j < 4; j++) acc[i][j] = tf32r(acc[i][j]);
    }

    if (mode == 3 && z == 1) {
        // transposed store: g_k[head][n][dh], head=m>>5, dh=m&31
        int m1 = m0 + mg + g, m2 = m1 + 8;
        float* b1p = C + (m1 >> 5) * (NN * 32) + (m1 & 31);
        float* b2p = C + (m2 >> 5) * (NN * 32) + (m2 & 31);
#pragma unroll
        for (int nt = 0; nt < 4; nt++) {
            int col = n0 + nc + nt * 8 + 2 * kq;
            b1p[col * 32]       = acc[nt][0];
            b1p[(col + 1) * 32] = acc[nt][1];
            b2p[col * 32]       = acc[nt][2];
            b2p[(col + 1) * 32] = acc[nt][3];
        }
    } else {
#pragma unroll
        for (int nt = 0; nt < 4; nt++) {
            int col = n0 + nc + nt * 8 + 2 * kq;
            *(float2*)&C[(m0 + mg + g) * NN + col]     = make_float2(acc[nt][0], acc[nt][1]);
            *(float2*)&C[(m0 + mg + g + 8) * NN + col] = make_float2(acc[nt][2], acc[nt][3]);
        }
    }
}

// ---------------------------------------------------------------------------
// Kernel 4: flash attention v8.
// K smem [64 keys][40] (from transposed g_k) -> K-frag = one LDS.64 (Q d-slots
// permuted to match). V smem [32 d][72] -> conflict-free LDS.64.
// P stays in registers (pi-permutation). Fixed-max base-2 softmax + LUT.
// ---------------------------------------------------------------------------
#define KST 40
#define VST 72
#define KS_STAGE (64 * KST)          // 2560
#define VS_STAGE (32 * VST)          // 2304
#define KS_OFF  0                    // 3 stages: 7680
#define VS_OFF  (3 * KS_STAGE)       // 7680 .. 14592
#define LUT_OFF (VS_OFF + 3 * VS_STAGE)   // 14592
#define LSM_OFF (LUT_OFF + 128)           // 14720
#define FLASH_SMEM_FLOATS (LSM_OFF + 128) // 14848
#define M0BASE2 10.0f

__global__ __launch_bounds__(256, 2)
void flash_tc8(const float* __restrict__ beta_p)
{
    extern __shared__ float sm[];
    float* Lut = sm + LUT_OFF;
    float* Lsm = sm + LSM_OFF;

    int t = threadIdx.x, w = t >> 5, lane = t & 31;
    int g = lane >> 2, kq = lane & 3;
    int mg = (w & 3) * 32;
    int ch = w >> 2;
    int cb = ch * 32;
    int n0 = blockIdx.x * 128;
    int h  = blockIdx.y;

    const float LOG2E = 1.4426950408889634f;
    float invb = 1.0f / (fabsf(beta_p[0]) + 1e-6f);
    const float scale2 = 0.17677669529663687f * LOG2E;
    if (t < 127) Lut[t] = __expf(-(float)t * invb) * LOG2E - M0BASE2;

    const float* gq  = g_q + h * HDIM * NN;
    const float* gkT = g_k + h * (NN * 32);   // [N][32]
    const float* gv  = g_v + h * HDIM * NN;

    int qy[4], qx[4];
#pragma unroll
    for (int rt = 0; rt < 2; rt++)
#pragma unroll
        for (int hf = 0; hf < 2; hf++) {
            int r = n0 + mg + rt * 16 + hf * 8 + g;
            qy[rt * 2 + hf] = r >> 6;
            qx[rt * 2 + hf] = r & 63;
        }

    // Q fragments with d-permutation: A-slot kq <-> d=kt*8+2kq, kq+4 <-> +1
    uint32_t qa[2][4][4];
#pragma unroll
    for (int rt = 0; rt < 2; rt++) {
        int base = n0 + mg + rt * 16 + g;
#pragma unroll
        for (int kt = 0; kt < 4; kt++) {
            int dlo = kt * 8 + 2 * kq;
            qa[rt][kt][0] = __float_as_uint(gq[dlo * NN + base]);
            qa[rt][kt][1] = __float_as_uint(gq[dlo * NN + base + 8]);
            qa[rt][kt][2] = __float_as_uint(gq[(dlo + 1) * NN + base]);
            qa[rt][kt][3] = __float_as_uint(gq[(dlo + 1) * NN + base + 8]);
        }
    }

    float o[2][4][4];
#pragma unroll
    for (int rt = 0; rt < 2; rt++)
#pragma unroll
        for (int i = 0; i < 4; i++)
#pragma unroll
            for (int j = 0; j < 4; j++) o[rt][i][j] = 0.f;
    float l[2][2] = {{0.f, 0.f}, {0.f, 0.f}};

    // fill mappings:
    // K: 512 chunks, row=id>>3 (0..63), cd=(id&7)*4
    // V: 512 chunks, row=id>>4 (0..31), cv=(id&15)*4
    int kr0 = t >> 3,  kc0 = (t & 7) * 4;
    int kr1 = kr0 + 32;
    int vr0 = t >> 4,  vc0 = (t & 15) * 4;
    int vr1 = vr0 + 16;

#define PREFETCH(stage, kcol)                                                  \
    do {                                                                       \
        float* kbase = sm + KS_OFF + (stage) * KS_STAGE;                       \
        float* vbase = sm + VS_OFF + (stage) * VS_STAGE;                       \
        unsigned dk0 = (unsigned)__cvta_generic_to_shared(&kbase[kr0 * KST + kc0]); \
        unsigned dk1 = (unsigned)__cvta_generic_to_shared(&kbase[kr1 * KST + kc0]); \
        unsigned dv0 = (unsigned)__cvta_generic_to_shared(&vbase[vr0 * VST + vc0]); \
        unsigned dv1 = (unsigned)__cvta_generic_to_shared(&vbase[vr1 * VST + vc0]); \
        CP16(dk0, &gkT[((kcol) + kr0) * 32 + kc0]);                            \
        CP16(dk1, &gkT[((kcol) + kr1) * 32 + kc0]);                            \
        CP16(dv0, &gv[vr0 * NN + (kcol) + vc0]);                               \
        CP16(dv1, &gv[vr1 * NN + (kcol) + vc0]);                               \
    } while (0)

    PREFETCH(0, 0);   CP_COMMIT();
    PREFETCH(1, 64);  CP_COMMIT();

    for (int kb = 0; kb < 64; kb++) {
        int st = kb - (kb / 3) * 3;
        if (kb < 63) CP_WAIT1(); else CP_WAIT0();
        __syncthreads();
        if (kb < 62) {
            int st2 = kb + 2; st2 -= (st2 / 3) * 3;
            PREFETCH(st2, (kb + 2) * 64);
            CP_COMMIT();
        }

        const float* Ksb = sm + KS_OFF + st * KS_STAGE;
        const float* Vsb = sm + VS_OFF + st * VS_STAGE;

        // ---- S = Q K^T : K-frag is one float2 (keys are rows now) ----
        float s[2][4][4];
#pragma unroll
        for (int rt = 0; rt < 2; rt++)
#pragma unroll
            for (int i = 0; i < 4; i++)
#pragma unroll
                for (int j = 0; j < 4; j++) s[rt][i][j] = 0.f;
#pragma unroll
        for (int kt = 0; kt < 4; kt++) {
#pragma unroll
            for (int nt = 0; nt < 4; nt++) {
                float2 kk = *(const float2*)&Ksb[(cb + nt * 8 + g) * KST + kt * 8 + 2 * kq];
                uint32_t b0 = __float_as_uint(kk.x);
                uint32_t b1 = __float_as_uint(kk.y);
                mma_tf32(s[0][nt], qa[0][kt], b0, b1);
                mma_tf32(s[1][nt], qa[1][kt], b0, b1);
            }
        }

        // ---- p = 2^(s*scale2 + LUT[dist]); key y == kb ----
#pragma unroll
        for (int rt = 0; rt < 2; rt++) {
            int dyA = abs(qy[rt * 2]     - kb);
            int dyB = abs(qy[rt * 2 + 1] - kb);
            int qxA = qx[rt * 2], qxB = qx[rt * 2 + 1];
#pragma unroll
            for (int nt = 0; nt < 4; nt++) {
                int ccb = cb + nt * 8 + 2 * kq;
#pragma unroll
                for (int e = 0; e < 2; e++) {
                    int cc = ccb + e;
                    float p0 = ex2f(s[rt][nt][e]     * scale2 + Lut[dyA + abs(qxA - cc)]);
                    float p1 = ex2f(s[rt][nt][e + 2] * scale2 + Lut[dyB + abs(qxB - cc)]);
                    l[rt][0] += p0;
                    l[rt][1] += p1;
                    s[rt][nt][e]     = tf32r(p0);
                    s[rt][nt][e + 2] = tf32r(p1);
                }
            }
        }

        // ---- O += P V (pi-permuted A-frag; V rows (2kq,2kq+1) via float2) ----
#pragma unroll
        for (int kt2 = 0; kt2 < 4; kt2++) {
            uint32_t a0[4], a1[4];
            a0[0] = __float_as_uint(s[0][kt2][0]);
            a0[1] = __float_as_uint(s[0][kt2][2]);
            a0[2] = __float_as_uint(s[0][kt2][1]);
            a0[3] = __float_as_uint(s[0][kt2][3]);
            a1[0] = __float_as_uint(s[1][kt2][0]);
            a1[1] = __float_as_uint(s[1][kt2][2]);
            a1[2] = __float_as_uint(s[1][kt2][1]);
            a1[3] = __float_as_uint(s[1][kt2][3]);
#pragma unroll
            for (int nt2 = 0; nt2 < 4; nt2++) {
                float2 b01 = *(const float2*)&Vsb[(nt2 * 8 + g) * VST + cb + kt2 * 8 + 2 * kq];
                uint32_t b0 = __float_as_uint(b01.x);
                uint32_t b1 = __float_as_uint(b01.y);
                mma_tf32(o[0][nt2], a0, b0, b1);
                mma_tf32(o[1][nt2], a1, b0, b1);
            }
        }
    }

    // ---- reduce l over the 4 kq lanes ----
#pragma unroll
    for (int rt = 0; rt < 2; rt++)
#pragma unroll
        for (int hf = 0; hf < 2; hf++) {
            l[rt][hf] += __shfl_xor_sync(0xffffffffu, l[rt][hf], 1);
            l[rt][hf] += __shfl_xor_sync(0xffffffffu, l[rt][hf], 2);
        }

    // ---- merge split-K halves: O = (O_a + O_b) / (l_a + l_b) ----
    float* Om = sm;   // reuse K region [128][36]
    __syncthreads();
    if (ch == 1) {
#pragma unroll
        for (int rt = 0; rt < 2; rt++) {
            int rb_ = mg + rt * 16;
            Lsm[rb_ + g] = l[rt][0];  Lsm[rb_ + g + 8] = l[rt][1];
#pragma unroll
            for (int nt = 0; nt < 4; nt++) {
                int d0 = nt * 8 + 2 * kq;
                Om[(rb_ + g) * 36 + d0]         = o[rt][nt][0];
                Om[(rb_ + g) * 36 + d0 + 1]     = o[rt][nt][1];
                Om[(rb_ + g + 8) * 36 + d0]     = o[rt][nt][2];
                Om[(rb_ + g + 8) * 36 + d0 + 1] = o[rt][nt][3];
            }
        }
    }
    __syncthreads();
    if (ch == 0) {
#pragma unroll
        for (int rt = 0; rt < 2; rt++) {
            int rb_ = mg + rt * 16;
            float iL0 = 1.0f / (l[rt][0] + Lsm[rb_ + g]);
            float iL1 = 1.0f / (l[rt][1] + Lsm[rb_ + g + 8]);
#pragma unroll
            for (int nt = 0; nt < 4; nt++) {
                int d0 = nt * 8 + 2 * kq;
                Om[(rb_ + g) * 36 + d0]         = (o[rt][nt][0] + Om[(rb_ + g) * 36 + d0])     * iL0;
                Om[(rb_ + g) * 36 + d0 + 1]     = (o[rt][nt][1] + Om[(rb_ + g) * 36 + d0 + 1]) * iL0;
                Om[(rb_ + g + 8) * 36 + d0]     = (o[rt][nt][2] + Om[(rb_ + g + 8) * 36 + d0])     * iL1;
                Om[(rb_ + g + 8) * 36 + d0 + 1] = (o[rt][nt][3] + Om[(rb_ + g + 8) * 36 + d0 + 1]) * iL1;
            }
        }
    }
    __syncthreads();

    float* go = g_ao + h * HDIM * NN;
    for (int idx = t; idx < 4096; idx += 256) {
        int r = idx & 127, d = idx >> 7;
        go[d * NN + n0 + r] = Om[r * 36 + d];
    }
}

// ---------------------------------------------------------------------------
extern "C" void kernel_launch(void* const* d_in, const int* in_sizes, int n_in,
                              void* d_out, int out_size)
{
    const float* x   = (const float*)d_in[0];
    const float* ow  = (const float*)d_in[1];
    const float* w3  = (const float*)d_in[2];
    const float* w5  = (const float*)d_in[3];
    const float* w7  = (const float*)d_in[4];
    const float* wop = (const float*)d_in[5];
    const float* wq  = (const float*)d_in[6];
    const float* wk  = (const float*)d_in[7];
    const float* wv  = (const float*)d_in[8];
    const float* wo  = (const float*)d_in[9];
    const float* beta = (const float*)d_in[10];
    float* out = (float*)d_out;

    static int smem_set = 0;
    if (!smem_set) {
        cudaFuncSetAttribute(flash_tc8, cudaFuncAttributeMaxDynamicSharedMemorySize,
                             FLASH_SMEM_FLOATS * 4);
        smem_set = 1;
    }

    conv_offset_fused<<<dim3(16, 8), 256>>>(x, ow, w3, w5, w7, wop);    // 1
    sample_kernel<<<dim3(16, 256), 256>>>(x);                           // 2
    tcgemm<<<dim3(64, 4, 3), 256>>>(wq, wk, wv, 3, x, nullptr);         // 3: q,k,v
    flash_tc8<<<dim3(32, 8), 256, FLASH_SMEM_FLOATS * 4>>>(beta);       // 4 (profiled)
    tcgemm<<<dim3(64, 4, 1), 256>>>(wo, nullptr, nullptr, 2, nullptr, out); // 5
}

// round 9
// speedup vs baseline: 4.3397x; 1.0708x over previous
#include <cuda_runtime.h>
#include <math.h>
#include <stdint.h>

// Problem constants
#define HH 64
#define WW 64
#define NN 4096            // H*W
#define CC 256
#define NHEADS 8
#define HDIM 32

// ---------------- scratch (device globals; no allocation allowed) ----------
__device__ float g_part[8 * 2 * NN];
__device__ int   g_ctr[64];
__device__ float g_ixy[2 * NN];
__device__ float g_xs[CC * NN];
__device__ float g_q[CC * NN];   // [d][N], tf32-rounded
__device__ float g_k[CC * NN];   // TRANSPOSED: [head][N][32], tf32-rounded
__device__ float g_v[CC * NN];   // [d][N], tf32-rounded
__device__ float g_ao[CC * NN];

__device__ __forceinline__ float tf32r(float x) {
    asm("cvt.rna.tf32.f32 %0, %0;" : "+f"(x));
    return x;
}
__device__ __forceinline__ float4 tf32r4(float4 v) {
    v.x = tf32r(v.x); v.y = tf32r(v.y); v.z = tf32r(v.z); v.w = tf32r(v.w);
    return v;
}
__device__ __forceinline__ float ex2f(float x) {
    float y;
    asm("ex2.approx.ftz.f32 %0, %1;" : "=f"(y) : "f"(x));
    return y;
}
__device__ __forceinline__ void mma_tf32(float c[4], const uint32_t a[4],
                                         uint32_t b0, uint32_t b1) {
    asm volatile(
        "mma.sync.aligned.m16n8k8.row.col.f32.tf32.tf32.f32 "
        "{%0,%1,%2,%3},{%4,%5,%6,%7},{%8,%9},{%0,%1,%2,%3};"
        : "+f"(c[0]), "+f"(c[1]), "+f"(c[2]), "+f"(c[3])
        : "r"(a[0]), "r"(a[1]), "r"(a[2]), "r"(a[3]), "r"(b0), "r"(b1));
}
#define CP16(dst, src) \
    asm volatile("cp.async.ca.shared.global [%0], [%1], 16;" \
                 :: "r"(dst), "l"(src))
#define CP_COMMIT() asm volatile("cp.async.commit_group;")
#define CP_WAIT1()  asm volatile("cp.async.wait_group 1;")
#define CP_WAIT0()  asm volatile("cp.async.wait_group 0;")

// ---------------------------------------------------------------------------
// Kernel 1: smem-tiled depthwise conv -> relu -> offset proj, fused
// cross-group reduction + coords (last block per pixel row).
// grid (64 rows, 8 ch-groups) x 256 threads. Dynamic smem ~71 KB.
// Layout (floats): sxt[32][7][70] @0 (15680), swc[32*49] @15680 (1568),
//                  swp[2][32] @17248 (64), red[4][2][64] @17312 (512)
// ---------------------------------------------------------------------------
#define CONV_SMEM_FLOATS 17824

__global__ __launch_bounds__(256)
void conv_offset_fused(const float* __restrict__ x,
                       const float* __restrict__ ow,
                       const float* __restrict__ w3,
                       const float* __restrict__ w5,
                       const float* __restrict__ w7,
                       const float* __restrict__ wproj)
{
    extern __shared__ float cs[];
    float* sxt = cs;                 // [32][7][70]
    float* swc = cs + 15680;         // [32][49]
    float* swp = cs + 17248;         // [2][32]
    float* red = cs + 17312;         // [4][2][64]
    __shared__ int isLast;

    int t = threadIdx.x;
    int row = blockIdx.x;            // pixel row 0..63
    int cz = blockIdx.y * 32;
    float ow0 = ow[0], ow1 = ow[1], ow2 = ow[2];

    // combined depthwise weights
    for (int idx = t; idx < 32 * 49; idx += 256) {
        int c = idx / 49, ji = idx % 49;
        int j = ji / 7, i = ji % 7;
        float v = w7[(cz + c) * 49 + ji] * ow2;
        if (j >= 1 && j <= 5 && i >= 1 && i <= 5)
            v += w5[(cz + c) * 25 + (j - 1) * 5 + (i - 1)] * ow1;
        if (j >= 2 && j <= 4 && i >= 2 && i <= 4)
            v += w3[(cz + c) * 9 + (j - 2) * 3 + (i - 2)] * ow0;
        swc[idx] = v;
    }
    if (t < 32) {
        swp[t]      = wproj[cz + t];
        swp[32 + t] = wproj[CC + cz + t];
    }

    // x tile: rows row-3..row+3, cols -3..66 (zero padded)
    for (int idx = t; idx < 15680; idx += 256) {
        int c = idx / 490, r2 = idx % 490;
        int j = r2 / 70, col = r2 % 70 - 3;
        int yy = row + j - 3;
        float v = 0.f;
        if (yy >= 0 && yy < HH && col >= 0 && col < WW)
            v = x[(cz + c) * NN + yy * WW + col];
        sxt[idx] = v;
    }
    __syncthreads();

    int px = t & 63, cg = t >> 6;
    float a0 = 0.f, a1 = 0.f;
#pragma unroll 1
    for (int c8 = 0; c8 < 8; c8++) {
        int c = cg * 8 + c8;
        const float* xc = sxt + c * 490;
        const float* wc = swc + c * 49;
        float feat = 0.f;
#pragma unroll
        for (int j = 0; j < 7; j++)
#pragma unroll
            for (int i = 0; i < 7; i++)
                feat += xc[j * 70 + px + i] * wc[j * 7 + i];
        feat = fmaxf(feat, 0.f);
        a0 += feat * swp[c];
        a1 += feat * swp[32 + c];
    }
    red[(cg * 2 + 0) * 64 + px] = a0;
    red[(cg * 2 + 1) * 64 + px] = a1;
    __syncthreads();

    if (t < 64) {
        float s0 = red[t]      + red[128 + t] + red[256 + t] + red[384 + t];
        float s1 = red[64 + t] + red[192 + t] + red[320 + t] + red[448 + t];
        int p = row * 64 + t;
        g_part[(blockIdx.y * 2 + 0) * NN + p] = s0;
        g_part[(blockIdx.y * 2 + 1) * NN + p] = s1;
    }
    __threadfence();
    __syncthreads();
    if (t == 0) {
        int old = atomicAdd(&g_ctr[row], 1);
        isLast = (old == 7);
    }
    __syncthreads();
    if (isLast) {
        __threadfence();
        if (t < 64) {
            int p = row * 64 + t;
            float offy = 0.f, offx = 0.f;
#pragma unroll
            for (int g = 0; g < 8; g++) {
                offy += g_part[(g * 2 + 0) * NN + p];
                offx += g_part[(g * 2 + 1) * NN + p];
            }
            float refy = ((row + 0.5f) / 63.0f) * 2.0f - 1.0f;
            float refx = ((t + 0.5f) / 63.0f) * 2.0f - 1.0f;
            float gy = fminf(fmaxf(refy + tanhf(offy) * 2.0f, -1.0f), 1.0f);
            float gx = fminf(fmaxf(refx + tanhf(offx) * 2.0f, -1.0f), 1.0f);
            g_ixy[p]      = (gx + 1.0f) * 0.5f * 63.0f;
            g_ixy[NN + p] = (gy + 1.0f) * 0.5f * 63.0f;
        }
        if (t == 0) g_ctr[row] = 0;
    }
}

// ---------------------------------------------------------------------------
// Kernel 2: bilinear grid sample
// ---------------------------------------------------------------------------
__global__ __launch_bounds__(256)
void sample_kernel(const float* __restrict__ x)
{
    int p = blockIdx.x * 256 + threadIdx.x;
    int c = blockIdx.y;
    float ix = g_ixy[p], iy = g_ixy[NN + p];
    float x0f = floorf(ix), y0f = floorf(iy);
    float fx = ix - x0f, fy = iy - y0f;
    int x0 = min(max((int)x0f, 0), WW - 1);
    int x1 = min(x0 + 1, WW - 1);
    int y0 = min(max((int)y0f, 0), HH - 1);
    int y1 = min(y0 + 1, HH - 1);
    const float* xc = x + c * NN;
    float v00 = xc[y0 * WW + x0], v01 = xc[y0 * WW + x1];
    float v10 = xc[y1 * WW + x0], v11 = xc[y1 * WW + x1];
    g_xs[c * NN + p] = v00 * (1.f - fx) * (1.f - fy) + v01 * fx * (1.f - fy)
                     + v10 * (1.f - fx) * fy + v11 * fx * fy;
}

// ---------------------------------------------------------------------------
// Kernel 3: tf32 tensor-core GEMM  C[256,4096] = A[256,256] * B[256,4096]
// mode 3 z=0: wq@x  -> g_q [d][N]
//        z=1: wk@xs -> g_k TRANSPOSED [head][N][32]
//        z=2: wv@xs -> g_v [d][N]
// mode 2: wo@g_ao -> Cext
// ---------------------------------------------------------------------------
__global__ __launch_bounds__(256)
void tcgemm(const float* __restrict__ A0, const float* __restrict__ A1,
            const float* __restrict__ A2, int mode,
            const float* __restrict__ Bext, float* __restrict__ Cext)
{
    const float* A; const float* B; float* C; bool rnd;
    int z = blockIdx.z;
    if (mode == 3) {
        A = (z == 0) ? A0 : (z == 1) ? A1 : A2;
        B = (z == 0) ? Bext : g_xs;
        C = (z == 0) ? g_q : (z == 1) ? g_k : g_v;
        rnd = true;
    } else {
        A = A0; B = g_ao; C = Cext; rnd = false;
    }

    __shared__ float As[2][64][36];
    __shared__ float Bs[2][32][72];

    int t = threadIdx.x, w = t >> 5, lane = t & 31;
    int g = lane >> 2, kq = lane & 3;
    int mg = (w >> 1) * 16, nc = (w & 1) * 32;
    int m0 = blockIdx.y * 64, n0 = blockIdx.x * 64;

    float acc[4][4];
#pragma unroll
    for (int i = 0; i < 4; i++)
#pragma unroll
        for (int j = 0; j < 4; j++) acc[i][j] = 0.f;

    int am[2], ak;  ak = (t & 7) * 4;
    am[0] = t >> 3; am[1] = (t >> 3) + 32;
    int bk[2], bn;  bn = (t & 15) * 4;
    bk[0] = t >> 4; bk[1] = (t >> 4) + 16;

    float4 ra[2], rb[2];
#pragma unroll
    for (int j = 0; j < 2; j++) {
        ra[j] = tf32r4(*(const float4*)&A[(m0 + am[j]) * 256 + ak]);
        rb[j] = tf32r4(*(const float4*)&B[bk[j] * NN + n0 + bn]);
    }

    for (int ki = 0; ki < 8; ki++) {
        int b = ki & 1;
#pragma unroll
        for (int j = 0; j < 2; j++) {
            *(float4*)&As[b][am[j]][ak] = ra[j];
            *(float4*)&Bs[b][bk[j]][bn] = rb[j];
        }
        __syncthreads();
        if (ki < 7) {
            int k0 = (ki + 1) * 32;
#pragma unroll
            for (int j = 0; j < 2; j++) {
                ra[j] = tf32r4(*(const float4*)&A[(m0 + am[j]) * 256 + k0 + ak]);
                rb[j] = tf32r4(*(const float4*)&B[(k0 + bk[j]) * NN + n0 + bn]);
            }
        }
#pragma unroll
        for (int kt = 0; kt < 4; kt++) {
            uint32_t a[4];
            a[0] = __float_as_uint(As[b][mg + g][kt * 8 + kq]);
            a[1] = __float_as_uint(As[b][mg + g + 8][kt * 8 + kq]);
            a[2] = __float_as_uint(As[b][mg + g][kt * 8 + kq + 4]);
            a[3] = __float_as_uint(As[b][mg + g + 8][kt * 8 + kq + 4]);
#pragma unroll
            for (int nt = 0; nt < 4; nt++) {
                uint32_t b0 = __float_as_uint(Bs[b][kt * 8 + kq][nc + nt * 8 + g]);
                uint32_t b1 = __float_as_uint(Bs[b][kt * 8 + kq + 4][nc + nt * 8 + g]);
                mma_tf32(acc[nt], a, b0, b1);
            }
        }
    }

    if (rnd) {
#pragma unroll
        for (int i = 0; i < 4; i++)
#pragma unroll
            for (int j = 0; j < 4; j++) acc[i][j] = tf32r(acc[i][j]);
    }

    if (mode == 3 && z == 1) {
        int m1 = m0 + mg + g, m2 = m1 + 8;
        float* b1p = C + (m1 >> 5) * (NN * 32) + (m1 & 31);
        float* b2p = C + (m2 >> 5) * (NN * 32) + (m2 & 31);
#pragma unroll
        for (int nt = 0; nt < 4; nt++) {
            int col = n0 + nc + nt * 8 + 2 * kq;
            b1p[col * 32]       = acc[nt][0];
            b1p[(col + 1) * 32] = acc[nt][1];
            b2p[col * 32]       = acc[nt][2];
            b2p[(col + 1) * 32] = acc[nt][3];
        }
    } else {
#pragma unroll
        for (int nt = 0; nt < 4; nt++) {
            int col = n0 + nc + nt * 8 + 2 * kq;
            *(float2*)&C[(m0 + mg + g) * NN + col]     = make_float2(acc[nt][0], acc[nt][1]);
            *(float2*)&C[(m0 + mg + g + 8) * NN + col] = make_float2(acc[nt][2], acc[nt][3]);
        }
    }
}

// ---------------------------------------------------------------------------
// Kernel 4: flash attention v9.
// Duplicated-pair bias LUT: Lut2[i] = {Lut[i], Lut[i+1]} -> one aligned
// LDS.64 + selects per column pair (distances to cc and cc+1 always differ
// by exactly 1). K [key][40] one-LDS.64 frags; V [d][72] conflict-free.
// P in registers (pi-permutation). Fixed-max base-2 softmax.
// ---------------------------------------------------------------------------
#define KST 40
#define VST 72
#define KS_STAGE (64 * KST)          // 2560
#define VS_STAGE (32 * VST)          // 2304
#define KS_OFF  0
#define VS_OFF  (3 * KS_STAGE)              // 7680
#define LUT_OFF (VS_OFF + 3 * VS_STAGE)     // 14592 (float2[128] = 256 floats)
#define LSM_OFF (LUT_OFF + 256)             // 14848
#define FLASH_SMEM_FLOATS (LSM_OFF + 128)   // 14976
#define M0BASE2 10.0f

__global__ __launch_bounds__(256, 2)
void flash_tc9(const float* __restrict__ beta_p)
{
    extern __shared__ float sm[];
    float2* Lut2 = (float2*)(sm + LUT_OFF);
    float* Lsm = sm + LSM_OFF;

    int t = threadIdx.x, w = t >> 5, lane = t & 31;
    int g = lane >> 2, kq = lane & 3;
    int mg = (w & 3) * 32;
    int ch = w >> 2;
    int cb = ch * 32;
    int n0 = blockIdx.x * 128;
    int h  = blockIdx.y;

    const float LOG2E = 1.4426950408889634f;
    float invb = 1.0f / (fabsf(beta_p[0]) + 1e-6f);
    const float scale2 = 0.17677669529663687f * LOG2E;
    if (t < 127) {
        float e0 = __expf(-(float)t * invb) * LOG2E - M0BASE2;
        float e1 = __expf(-(float)(t + 1) * invb) * LOG2E - M0BASE2;
        Lut2[t] = make_float2(e0, e1);
    }

    const float* gq  = g_q + h * HDIM * NN;
    const float* gkT = g_k + h * (NN * 32);   // [N][32]
    const float* gv  = g_v + h * HDIM * NN;

    int qy[4], qx[4];
#pragma unroll
    for (int rt = 0; rt < 2; rt++)
#pragma unroll
        for (int hf = 0; hf < 2; hf++) {
            int r = n0 + mg + rt * 16 + hf * 8 + g;
            qy[rt * 2 + hf] = r >> 6;
            qx[rt * 2 + hf] = r & 63;
        }

    // Q fragments with d-permutation (A-slot kq <-> d=kt*8+2kq, kq+4 <-> +1)
    uint32_t qa[2][4][4];
#pragma unroll
    for (int rt = 0; rt < 2; rt++) {
        int base = n0 + mg + rt * 16 + g;
#pragma unroll
        for (int kt = 0; kt < 4; kt++) {
            int dlo = kt * 8 + 2 * kq;
            qa[rt][kt][0] = __float_as_uint(gq[dlo * NN + base]);
            qa[rt][kt][1] = __float_as_uint(gq[dlo * NN + base + 8]);
            qa[rt][kt][2] = __float_as_uint(gq[(dlo + 1) * NN + base]);
            qa[rt][kt][3] = __float_as_uint(gq[(dlo + 1) * NN + base + 8]);
        }
    }

    float o[2][4][4];
#pragma unroll
    for (int rt = 0; rt < 2; rt++)
#pragma unroll
        for (int i = 0; i < 4; i++)
#pragma unroll
            for (int j = 0; j < 4; j++) o[rt][i][j] = 0.f;
    float l[2][2] = {{0.f, 0.f}, {0.f, 0.f}};

    int kr0 = t >> 3,  kc0 = (t & 7) * 4;
    int kr1 = kr0 + 32;
    int vr0 = t >> 4,  vc0 = (t & 15) * 4;
    int vr1 = vr0 + 16;

#define PREFETCH(stage, kcol)                                                  \
    do {                                                                       \
        float* kbase = sm + KS_OFF + (stage) * KS_STAGE;                       \
        float* vbase = sm + VS_OFF + (stage) * VS_STAGE;                       \
        unsigned dk0 = (unsigned)__cvta_generic_to_shared(&kbase[kr0 * KST + kc0]); \
        unsigned dk1 = (unsigned)__cvta_generic_to_shared(&kbase[kr1 * KST + kc0]); \
        unsigned dv0 = (unsigned)__cvta_generic_to_shared(&vbase[vr0 * VST + vc0]); \
        unsigned dv1 = (unsigned)__cvta_generic_to_shared(&vbase[vr1 * VST + vc0]); \
        CP16(dk0, &gkT[((kcol) + kr0) * 32 + kc0]);                            \
        CP16(dk1, &gkT[((kcol) + kr1) * 32 + kc0]);                            \
        CP16(dv0, &gv[vr0 * NN + (kcol) + vc0]);                               \
        CP16(dv1, &gv[vr1 * NN + (kcol) + vc0]);                               \
    } while (0)

    PREFETCH(0, 0);   CP_COMMIT();
    PREFETCH(1, 64);  CP_COMMIT();

    for (int kb = 0; kb < 64; kb++) {
        int st = kb - (kb / 3) * 3;
        if (kb < 63) CP_WAIT1(); else CP_WAIT0();
        __syncthreads();
        if (kb < 62) {
            int st2 = kb + 2; st2 -= (st2 / 3) * 3;
            PREFETCH(st2, (kb + 2) * 64);
            CP_COMMIT();
        }

        const float* Ksb = sm + KS_OFF + st * KS_STAGE;
        const float* Vsb = sm + VS_OFF + st * VS_STAGE;

        // ---- S = Q K^T ----
        float s[2][4][4];
#pragma unroll
        for (int rt = 0; rt < 2; rt++)
#pragma unroll
            for (int i = 0; i < 4; i++)
#pragma unroll
                for (int j = 0; j < 4; j++) s[rt][i][j] = 0.f;
#pragma unroll
        for (int kt = 0; kt < 4; kt++) {
#pragma unroll
            for (int nt = 0; nt < 4; nt++) {
                float2 kk = *(const float2*)&Ksb[(cb + nt * 8 + g) * KST + kt * 8 + 2 * kq];
                uint32_t b0 = __float_as_uint(kk.x);
                uint32_t b1 = __float_as_uint(kk.y);
                mma_tf32(s[0][nt], qa[0][kt], b0, b1);
                mma_tf32(s[1][nt], qa[1][kt], b0, b1);
            }
        }

        // ---- softmax: bias via paired LUT (one LDS.64 per row-pair) ----
#pragma unroll
        for (int rt = 0; rt < 2; rt++) {
            int dyA = abs(qy[rt * 2]     - kb);
            int dyB = abs(qy[rt * 2 + 1] - kb);
            int qxA = qx[rt * 2], qxB = qx[rt * 2 + 1];
#pragma unroll
            for (int nt = 0; nt < 4; nt++) {
                int cc = cb + nt * 8 + 2 * kq;
                bool gA = qxA > cc;
                int iA = dyA + (gA ? qxA - cc - 1 : cc - qxA);
                float2 LA = Lut2[iA];
                float bA0 = gA ? LA.y : LA.x;
                float bA1 = gA ? LA.x : LA.y;
                bool gB = qxB > cc;
                int iB = dyB + (gB ? qxB - cc - 1 : cc - qxB);
                float2 LB = Lut2[iB];
                float bB0 = gB ? LB.y : LB.x;
                float bB1 = gB ? LB.x : LB.y;
                float p0 = ex2f(s[rt][nt][0] * scale2 + bA0);
                float p1 = ex2f(s[rt][nt][1] * scale2 + bA1);
                float p2 = ex2f(s[rt][nt][2] * scale2 + bB0);
                float p3 = ex2f(s[rt][nt][3] * scale2 + bB1);
                l[rt][0] += p0 + p1;
                l[rt][1] += p2 + p3;
                s[rt][nt][0] = tf32r(p0);
                s[rt][nt][1] = tf32r(p1);
                s[rt][nt][2] = tf32r(p2);
                s[rt][nt][3] = tf32r(p3);
            }
        }

        // ---- O += P V (pi-permuted A-frag; V rows (2kq,2kq+1) via float2) ----
#pragma unroll
        for (int kt2 = 0; kt2 < 4; kt2++) {
            uint32_t a0[4], a1[4];
            a0[0] = __float_as_uint(s[0][kt2][0]);
            a0[1] = __float_as_uint(s[0][kt2][2]);
            a0[2] = __float_as_uint(s[0][kt2][1]);
            a0[3] = __float_as_uint(s[0][kt2][3]);
            a1[0] = __float_as_uint(s[1][kt2][0]);
            a1[1] = __float_as_uint(s[1][kt2][2]);
            a1[2] = __float_as_uint(s[1][kt2][1]);
            a1[3] = __float_as_uint(s[1][kt2][3]);
#pragma unroll
            for (int nt2 = 0; nt2 < 4; nt2++) {
                float2 b01 = *(const float2*)&Vsb[(nt2 * 8 + g) * VST + cb + kt2 * 8 + 2 * kq];
                uint32_t b0 = __float_as_uint(b01.x);
                uint32_t b1 = __float_as_uint(b01.y);
                mma_tf32(o[0][nt2], a0, b0, b1);
                mma_tf32(o[1][nt2], a1, b0, b1);
            }
        }
    }

    // ---- reduce l over the 4 kq lanes ----
#pragma unroll
    for (int rt = 0; rt < 2; rt++)
#pragma unroll
        for (int hf = 0; hf < 2; hf++) {
            l[rt][hf] += __shfl_xor_sync(0xffffffffu, l[rt][hf], 1);
            l[rt][hf] += __shfl_xor_sync(0xffffffffu, l[rt][hf], 2);
        }

    // ---- merge split-K halves: O = (O_a + O_b) / (l_a + l_b) ----
    float* Om = sm;   // reuse K region [128][36]
    __syncthreads();
    if (ch == 1) {
#pragma unroll
        for (int rt = 0; rt < 2; rt++) {
            int rb_ = mg + rt * 16;
            Lsm[rb_ + g] = l[rt][0];  Lsm[rb_ + g + 8] = l[rt][1];
#pragma unroll
            for (int nt = 0; nt < 4; nt++) {
                int d0 = nt * 8 + 2 * kq;
                Om[(rb_ + g) * 36 + d0]         = o[rt][nt][0];
                Om[(rb_ + g) * 36 + d0 + 1]     = o[rt][nt][1];
                Om[(rb_ + g + 8) * 36 + d0]     = o[rt][nt][2];
                Om[(rb_ + g + 8) * 36 + d0 + 1] = o[rt][nt][3];
            }
        }
    }
    __syncthreads();
    if (ch == 0) {
#pragma unroll
        for (int rt = 0; rt < 2; rt++) {
            int rb_ = mg + rt * 16;
            float iL0 = 1.0f / (l[rt][0] + Lsm[rb_ + g]);
            float iL1 = 1.0f / (l[rt][1] + Lsm[rb_ + g + 8]);
#pragma unroll
            for (int nt = 0; nt < 4; nt++) {
                int d0 = nt * 8 + 2 * kq;
                Om[(rb_ + g) * 36 + d0]         = (o[rt][nt][0] + Om[(rb_ + g) * 36 + d0])     * iL0;
                Om[(rb_ + g) * 36 + d0 + 1]     = (o[rt][nt][1] + Om[(rb_ + g) * 36 + d0 + 1]) * iL0;
                Om[(rb_ + g + 8) * 36 + d0]     = (o[rt][nt][2] + Om[(rb_ + g + 8) * 36 + d0])     * iL1;
                Om[(rb_ + g + 8) * 36 + d0 + 1] = (o[rt][nt][3] + Om[(rb_ + g + 8) * 36 + d0 + 1]) * iL1;
            }
        }
    }
    __syncthreads();

    float* go = g_ao + h * HDIM * NN;
    for (int idx = t; idx < 4096; idx += 256) {
        int r = idx & 127, d = idx >> 7;
        go[d * NN + n0 + r] = Om[r * 36 + d];
    }
}

// ---------------------------------------------------------------------------
extern "C" void kernel_launch(void* const* d_in, const int* in_sizes, int n_in,
                              void* d_out, int out_size)
{
    const float* x   = (const float*)d_in[0];
    const float* ow  = (const float*)d_in[1];
    const float* w3  = (const float*)d_in[2];
    const float* w5  = (const float*)d_in[3];
    const float* w7  = (const float*)d_in[4];
    const float* wop = (const float*)d_in[5];
    const float* wq  = (const float*)d_in[6];
    const float* wk  = (const float*)d_in[7];
    const float* wv  = (const float*)d_in[8];
    const float* wo  = (const float*)d_in[9];
    const float* beta = (const float*)d_in[10];
    float* out = (float*)d_out;

    static int smem_set = 0;
    if (!smem_set) {
        cudaFuncSetAttribute(flash_tc9, cudaFuncAttributeMaxDynamicSharedMemorySize,
                             FLASH_SMEM_FLOATS * 4);
        cudaFuncSetAttribute(conv_offset_fused, cudaFuncAttributeMaxDynamicSharedMemorySize,
                             CONV_SMEM_FLOATS * 4);
        smem_set = 1;
    }

    conv_offset_fused<<<dim3(64, 8), 256, CONV_SMEM_FLOATS * 4>>>(x, ow, w3, w5, w7, wop);
    sample_kernel<<<dim3(16, 256), 256>>>(x);
    tcgemm<<<dim3(64, 4, 3), 256>>>(wq, wk, wv, 3, x, nullptr);
    flash_tc9<<<dim3(32, 8), 256, FLASH_SMEM_FLOATS * 4>>>(beta);
    tcgemm<<<dim3(64, 4, 1), 256>>>(wo, nullptr, nullptr, 2, nullptr, out);
}

// round 11
// speedup vs baseline: 4.3796x; 1.0092x over previous
#include <cuda_runtime.h>
#include <math.h>
#include <stdint.h>

// Problem constants
#define HH 64
#define WW 64
#define NN 4096            // H*W
#define CC 256
#define NHEADS 8
#define HDIM 32

// ---------------- scratch (device globals; no allocation allowed) ----------
__device__ float g_part[8 * 2 * NN];
__device__ int   g_ctr[64];
__device__ float g_ixy[2 * NN];
__device__ float g_xs[CC * NN];
__device__ float g_q[CC * NN];   // [d][N], tf32-rounded
__device__ float g_k[CC * NN];   // TRANSPOSED: [head][N][32], tf32-rounded
__device__ float g_v[CC * NN];   // [d][N], tf32-rounded
__device__ float g_ao[CC * NN];

__device__ __forceinline__ float tf32r(float x) {
    asm("cvt.rna.tf32.f32 %0, %0;" : "+f"(x));
    return x;
}
__device__ __forceinline__ float4 tf32r4(float4 v) {
    v.x = tf32r(v.x); v.y = tf32r(v.y); v.z = tf32r(v.z); v.w = tf32r(v.w);
    return v;
}
__device__ __forceinline__ float ex2f(float x) {
    float y;
    asm("ex2.approx.ftz.f32 %0, %1;" : "=f"(y) : "f"(x));
    return y;
}
__device__ __forceinline__ void mma_tf32(float c[4], const uint32_t a[4],
                                         uint32_t b0, uint32_t b1) {
    asm volatile(
        "mma.sync.aligned.m16n8k8.row.col.f32.tf32.tf32.f32 "
        "{%0,%1,%2,%3},{%4,%5,%6,%7},{%8,%9},{%0,%1,%2,%3};"
        : "+f"(c[0]), "+f"(c[1]), "+f"(c[2]), "+f"(c[3])
        : "r"(a[0]), "r"(a[1]), "r"(a[2]), "r"(a[3]), "r"(b0), "r"(b1));
}
#define CP16(dst, src) \
    asm volatile("cp.async.ca.shared.global [%0], [%1], 16;" \
                 :: "r"(dst), "l"(src))
#define CP_COMMIT() asm volatile("cp.async.commit_group;")
#define CP_WAIT1()  asm volatile("cp.async.wait_group 1;")
#define CP_WAIT0()  asm volatile("cp.async.wait_group 0;")

// ---------------------------------------------------------------------------
// Kernel 1: smem-tiled depthwise conv -> relu -> offset proj, fused
// cross-group reduction + coords (last block per pixel row).
// ---------------------------------------------------------------------------
#define CONV_SMEM_FLOATS 17824

__global__ __launch_bounds__(256)
void conv_offset_fused(const float* __restrict__ x,
                       const float* __restrict__ ow,
                       const float* __restrict__ w3,
                       const float* __restrict__ w5,
                       const float* __restrict__ w7,
                       const float* __restrict__ wproj)
{
    extern __shared__ float cs[];
    float* sxt = cs;                 // [32][7][70]
    float* swc = cs + 15680;         // [32][49]
    float* swp = cs + 17248;         // [2][32]
    float* red = cs + 17312;         // [4][2][64]
    __shared__ int isLast;

    int t = threadIdx.x;
    int row = blockIdx.x;
    int cz = blockIdx.y * 32;
    float ow0 = ow[0], ow1 = ow[1], ow2 = ow[2];

    for (int idx = t; idx < 32 * 49; idx += 256) {
        int c = idx / 49, ji = idx % 49;
        int j = ji / 7, i = ji % 7;
        float v = w7[(cz + c) * 49 + ji] * ow2;
        if (j >= 1 && j <= 5 && i >= 1 && i <= 5)
            v += w5[(cz + c) * 25 + (j - 1) * 5 + (i - 1)] * ow1;
        if (j >= 2 && j <= 4 && i >= 2 && i <= 4)
            v += w3[(cz + c) * 9 + (j - 2) * 3 + (i - 2)] * ow0;
        swc[idx] = v;
    }
    if (t < 32) {
        swp[t]      = wproj[cz + t];
        swp[32 + t] = wproj[CC + cz + t];
    }

    for (int idx = t; idx < 15680; idx += 256) {
        int c = idx / 490, r2 = idx % 490;
        int j = r2 / 70, col = r2 % 70 - 3;
        int yy = row + j - 3;
        float v = 0.f;
        if (yy >= 0 && yy < HH && col >= 0 && col < WW)
            v = x[(cz + c) * NN + yy * WW + col];
        sxt[idx] = v;
    }
    __syncthreads();

    int px = t & 63, cg = t >> 6;
    float a0 = 0.f, a1 = 0.f;
#pragma unroll 1
    for (int c8 = 0; c8 < 8; c8++) {
        int c = cg * 8 + c8;
        const float* xc = sxt + c * 490;
        const float* wc = swc + c * 49;
        float feat = 0.f;
#pragma unroll
        for (int j = 0; j < 7; j++)
#pragma unroll
            for (int i = 0; i < 7; i++)
                feat += xc[j * 70 + px + i] * wc[j * 7 + i];
        feat = fmaxf(feat, 0.f);
        a0 += feat * swp[c];
        a1 += feat * swp[32 + c];
    }
    red[(cg * 2 + 0) * 64 + px] = a0;
    red[(cg * 2 + 1) * 64 + px] = a1;
    __syncthreads();

    if (t < 64) {
        float s0 = red[t]      + red[128 + t] + red[256 + t] + red[384 + t];
        float s1 = red[64 + t] + red[192 + t] + red[320 + t] + red[448 + t];
        int p = row * 64 + t;
        g_part[(blockIdx.y * 2 + 0) * NN + p] = s0;
        g_part[(blockIdx.y * 2 + 1) * NN + p] = s1;
    }
    __threadfence();
    __syncthreads();
    if (t == 0) {
        int old = atomicAdd(&g_ctr[row], 1);
        isLast = (old == 7);
    }
    __syncthreads();
    if (isLast) {
        __threadfence();
        if (t < 64) {
            int p = row * 64 + t;
            float offy = 0.f, offx = 0.f;
#pragma unroll
            for (int g = 0; g < 8; g++) {
                offy += g_part[(g * 2 + 0) * NN + p];
                offx += g_part[(g * 2 + 1) * NN + p];
            }
            float refy = ((row + 0.5f) / 63.0f) * 2.0f - 1.0f;
            float refx = ((t + 0.5f) / 63.0f) * 2.0f - 1.0f;
            float gy = fminf(fmaxf(refy + tanhf(offy) * 2.0f, -1.0f), 1.0f);
            float gx = fminf(fmaxf(refx + tanhf(offx) * 2.0f, -1.0f), 1.0f);
            g_ixy[p]      = (gx + 1.0f) * 0.5f * 63.0f;
            g_ixy[NN + p] = (gy + 1.0f) * 0.5f * 63.0f;
        }
        if (t == 0) g_ctr[row] = 0;
    }
}

// ---------------------------------------------------------------------------
// Kernel 2: bilinear grid sample — 4 channels per thread
// ---------------------------------------------------------------------------
__global__ __launch_bounds__(256)
void sample_kernel(const float* __restrict__ x)
{
    int p = blockIdx.x * 256 + threadIdx.x;
    int c0 = blockIdx.y * 4;
    float ix = g_ixy[p], iy = g_ixy[NN + p];
    float x0f = floorf(ix), y0f = floorf(iy);
    float fx = ix - x0f, fy = iy - y0f;
    int x0 = min(max((int)x0f, 0), WW - 1);
    int x1 = min(x0 + 1, WW - 1);
    int y0 = min(max((int)y0f, 0), HH - 1);
    int y1 = min(y0 + 1, HH - 1);
    int i00 = y0 * WW + x0, i01 = y0 * WW + x1;
    int i10 = y1 * WW + x0, i11 = y1 * WW + x1;
    float w00 = (1.f - fx) * (1.f - fy), w01 = fx * (1.f - fy);
    float w10 = (1.f - fx) * fy,         w11 = fx * fy;
#pragma unroll
    for (int cc = 0; cc < 4; cc++) {
        const float* xc = x + (c0 + cc) * NN;
        g_xs[(c0 + cc) * NN + p] = xc[i00] * w00 + xc[i01] * w01
                                 + xc[i10] * w10 + xc[i11] * w11;
    }
}

// ---------------------------------------------------------------------------
// Kernel 3: tf32 tensor-core GEMM  C[256,4096] = A[256,256] * B[256,4096]
// mode 3 z=0: wq@x -> g_q; z=1: wk@xs -> g_k TRANSPOSED; z=2: wv@xs -> g_v
// mode 2: wo@g_ao -> Cext
// ---------------------------------------------------------------------------
__global__ __launch_bounds__(256)
void tcgemm(const float* __restrict__ A0, const float* __restrict__ A1,
            const float* __restrict__ A2, int mode,
            const float* __restrict__ Bext, float* __restrict__ Cext)
{
    const float* A; const float* B; float* C; bool rnd;
    int z = blockIdx.z;
    if (mode == 3) {
        A = (z == 0) ? A0 : (z == 1) ? A1 : A2;
        B = (z == 0) ? Bext : g_xs;
        C = (z == 0) ? g_q : (z == 1) ? g_k : g_v;
        rnd = true;
    } else {
        A = A0; B = g_ao; C = Cext; rnd = false;
    }

    __shared__ float As[2][64][36];
    __shared__ float Bs[2][32][72];

    int t = threadIdx.x, w = t >> 5, lane = t & 31;
    int g = lane >> 2, kq = lane & 3;
    int mg = (w >> 1) * 16, nc = (w & 1) * 32;
    int m0 = blockIdx.y * 64, n0 = blockIdx.x * 64;

    float acc[4][4];
#pragma unroll
    for (int i = 0; i < 4; i++)
#pragma unroll
        for (int j = 0; j < 4; j++) acc[i][j] = 0.f;

    int am[2], ak;  ak = (t & 7) * 4;
    am[0] = t >> 3; am[1] = (t >> 3) + 32;
    int bk[2], bn;  bn = (t & 15) * 4;
    bk[0] = t >> 4; bk[1] = (t >> 4) + 16;

    float4 ra[2], rb[2];
#pragma unroll
    for (int j = 0; j < 2; j++) {
        ra[j] = tf32r4(*(const float4*)&A[(m0 + am[j]) * 256 + ak]);
        rb[j] = tf32r4(*(const float4*)&B[bk[j] * NN + n0 + bn]);
    }

    for (int ki = 0; ki < 8; ki++) {
        int b = ki & 1;
#pragma unroll
        for (int j = 0; j < 2; j++) {
            *(float4*)&As[b][am[j]][ak] = ra[j];
            *(float4*)&Bs[b][bk[j]][bn] = rb[j];
        }
        __syncthreads();
        if (ki < 7) {
            int k0 = (ki + 1) * 32;
#pragma unroll
            for (int j = 0; j < 2; j++) {
                ra[j] = tf32r4(*(const float4*)&A[(m0 + am[j]) * 256 + k0 + ak]);
                rb[j] = tf32r4(*(const float4*)&B[(k0 + bk[j]) * NN + n0 + bn]);
            }
        }
#pragma unroll
        for (int kt = 0; kt < 4; kt++) {
            uint32_t a[4];
            a[0] = __float_as_uint(As[b][mg + g][kt * 8 + kq]);
            a[1] = __float_as_uint(As[b][mg + g + 8][kt * 8 + kq]);
            a[2] = __float_as_uint(As[b][mg + g][kt * 8 + kq + 4]);
            a[3] = __float_as_uint(As[b][mg + g + 8][kt * 8 + kq + 4]);
#pragma unroll
            for (int nt = 0; nt < 4; nt++) {
                uint32_t b0 = __float_as_uint(Bs[b][kt * 8 + kq][nc + nt * 8 + g]);
                uint32_t b1 = __float_as_uint(Bs[b][kt * 8 + kq + 4][nc + nt * 8 + g]);
                mma_tf32(acc[nt], a, b0, b1);
            }
        }
    }

    if (rnd) {
#pragma unroll
        for (int i = 0; i < 4; i++)
#pragma unroll
            for (int j = 0; j < 4; j++) acc[i][j] = tf32r(acc[i][j]);
    }

    if (mode == 3 && z == 1) {
        int m1 = m0 + mg + g, m2 = m1 + 8;
        float* b1p = C + (m1 >> 5) * (NN * 32) + (m1 & 31);
        float* b2p = C + (m2 >> 5) * (NN * 32) + (m2 & 31);
#pragma unroll
        for (int nt = 0; nt < 4; nt++) {
            int col = n0 + nc + nt * 8 + 2 * kq;
            b1p[col * 32]       = acc[nt][0];
            b1p[(col + 1) * 32] = acc[nt][1];
            b2p[col * 32]       = acc[nt][2];
            b2p[(col + 1) * 32] = acc[nt][3];
        }
    } else {
#pragma unroll
        for (int nt = 0; nt < 4; nt++) {
            int col = n0 + nc + nt * 8 + 2 * kq;
            *(float2*)&C[(m0 + mg + g) * NN + col]     = make_float2(acc[nt][0], acc[nt][1]);
            *(float2*)&C[(m0 + mg + g + 8) * NN + col] = make_float2(acc[nt][2], acc[nt][3]);
        }
    }
}

// ---------------------------------------------------------------------------
// Kernel 4: flash attention v11 = v8 softmax (scalar LUT of the ADDITIVE
// decay exp(-d/beta)*log2e - M0, indexed by Manhattan distance; ky==kb hoist)
// + K [key][40] one-LDS.64 frags + V [d][72] conflict-free + P in registers.
// ---------------------------------------------------------------------------
#define KST 40
#define VST 72
#define KS_STAGE (64 * KST)          // 2560
#define VS_STAGE (32 * VST)          // 2304
#define KS_OFF  0
#define VS_OFF  (3 * KS_STAGE)              // 7680
#define LUT_OFF (VS_OFF + 3 * VS_STAGE)     // 14592
#define LSM_OFF (LUT_OFF + 128)             // 14720
#define FLASH_SMEM_FLOATS (LSM_OFF + 128)   // 14848
#define M0BASE2 10.0f

__global__ __launch_bounds__(256, 2)
void flash_tc11(const float* __restrict__ beta_p)
{
    extern __shared__ float sm[];
    float* Lut = sm + LUT_OFF;
    float* Lsm = sm + LSM_OFF;

    int t = threadIdx.x, w = t >> 5, lane = t & 31;
    int g = lane >> 2, kq = lane & 3;
    int mg = (w & 3) * 32;
    int ch = w >> 2;
    int cb = ch * 32;
    int n0 = blockIdx.x * 128;
    int h  = blockIdx.y;

    const float LOG2E = 1.4426950408889634f;
    float invb = 1.0f / (fabsf(beta_p[0]) + 1e-6f);
    const float scale2 = 0.17677669529663687f * LOG2E;
    // LUT[d] = exp(-d/|beta|)*log2e - M0  (additive decay, fixed max folded)
    if (t < 127) Lut[t] = __expf(-(float)t * invb) * LOG2E - M0BASE2;

    const float* gq  = g_q + h * HDIM * NN;
    const float* gkT = g_k + h * (NN * 32);   // [N][32]
    const float* gv  = g_v + h * HDIM * NN;

    int qy[4], qx[4];
#pragma unroll
    for (int rt = 0; rt < 2; rt++)
#pragma unroll
        for (int hf = 0; hf < 2; hf++) {
            int r = n0 + mg + rt * 16 + hf * 8 + g;
            qy[rt * 2 + hf] = r >> 6;
            qx[rt * 2 + hf] = r & 63;
        }

    // Q fragments with d-permutation (A-slot kq <-> d=kt*8+2kq, kq+4 <-> +1)
    uint32_t qa[2][4][4];
#pragma unroll
    for (int rt = 0; rt < 2; rt++) {
        int base = n0 + mg + rt * 16 + g;
#pragma unroll
        for (int kt = 0; kt < 4; kt++) {
            int dlo = kt * 8 + 2 * kq;
            qa[rt][kt][0] = __float_as_uint(gq[dlo * NN + base]);
            qa[rt][kt][1] = __float_as_uint(gq[dlo * NN + base + 8]);
            qa[rt][kt][2] = __float_as_uint(gq[(dlo + 1) * NN + base]);
            qa[rt][kt][3] = __float_as_uint(gq[(dlo + 1) * NN + base + 8]);
        }
    }

    float o[2][4][4];
#pragma unroll
    for (int rt = 0; rt < 2; rt++)
#pragma unroll
        for (int i = 0; i < 4; i++)
#pragma unroll
            for (int j = 0; j < 4; j++) o[rt][i][j] = 0.f;
    float l[2][2] = {{0.f, 0.f}, {0.f, 0.f}};

    int kr0 = t >> 3,  kc0 = (t & 7) * 4;
    int kr1 = kr0 + 32;
    int vr0 = t >> 4,  vc0 = (t & 15) * 4;
    int vr1 = vr0 + 16;

#define PREFETCH(stage, kcol)                                                  \
    do {                                                                       \
        float* kbase = sm + KS_OFF + (stage) * KS_STAGE;                       \
        float* vbase = sm + VS_OFF + (stage) * VS_STAGE;                       \
        unsigned dk0 = (unsigned)__cvta_generic_to_shared(&kbase[kr0 * KST + kc0]); \
        unsigned dk1 = (unsigned)__cvta_generic_to_shared(&kbase[kr1 * KST + kc0]); \
        unsigned dv0 = (unsigned)__cvta_generic_to_shared(&vbase[vr0 * VST + vc0]); \
        unsigned dv1 = (unsigned)__cvta_generic_to_shared(&vbase[vr1 * VST + vc0]); \
        CP16(dk0, &gkT[((kcol) + kr0) * 32 + kc0]);                            \
        CP16(dk1, &gkT[((kcol) + kr1) * 32 + kc0]);                            \
        CP16(dv0, &gv[vr0 * NN + (kcol) + vc0]);                               \
        CP16(dv1, &gv[vr1 * NN + (kcol) + vc0]);                               \
    } while (0)

    PREFETCH(0, 0);   CP_COMMIT();
    PREFETCH(1, 64);  CP_COMMIT();

    for (int kb = 0; kb < 64; kb++) {
        int st = kb - (kb / 3) * 3;
        if (kb < 63) CP_WAIT1(); else CP_WAIT0();
        __syncthreads();
        if (kb < 62) {
            int st2 = kb + 2; st2 -= (st2 / 3) * 3;
            PREFETCH(st2, (kb + 2) * 64);
            CP_COMMIT();
        }

        const float* Ksb = sm + KS_OFF + st * KS_STAGE;
        const float* Vsb = sm + VS_OFF + st * VS_STAGE;

        // ---- S = Q K^T ----
        float s[2][4][4];
#pragma unroll
        for (int rt = 0; rt < 2; rt++)
#pragma unroll
            for (int i = 0; i < 4; i++)
#pragma unroll
                for (int j = 0; j < 4; j++) s[rt][i][j] = 0.f;
#pragma unroll
        for (int kt = 0; kt < 4; kt++) {
#pragma unroll
            for (int nt = 0; nt < 4; nt++) {
                float2 kk = *(const float2*)&Ksb[(cb + nt * 8 + g) * KST + kt * 8 + 2 * kq];
                uint32_t b0 = __float_as_uint(kk.x);
                uint32_t b1 = __float_as_uint(kk.y);
                mma_tf32(s[0][nt], qa[0][kt], b0, b1);
                mma_tf32(s[1][nt], qa[1][kt], b0, b1);
            }
        }

        // ---- p = 2^(s*scale2 + LUT[dist]); key y == kb for all keys ----
#pragma unroll
        for (int rt = 0; rt < 2; rt++) {
            int dyA = abs(qy[rt * 2]     - kb);
            int dyB = abs(qy[rt * 2 + 1] - kb);
            int qxA = qx[rt * 2], qxB = qx[rt * 2 + 1];
#pragma unroll
            for (int nt = 0; nt < 4; nt++) {
                int ccb = cb + nt * 8 + 2 * kq;
#pragma unroll
                for (int e = 0; e < 2; e++) {
                    int cc = ccb + e;
                    float p0 = ex2f(fmaf(s[rt][nt][e],     scale2, Lut[dyA + abs(qxA - cc)]));
                    float p1 = ex2f(fmaf(s[rt][nt][e + 2], scale2, Lut[dyB + abs(qxB - cc)]));
                    l[rt][0] += p0;
                    l[rt][1] += p1;
                    s[rt][nt][e]     = tf32r(p0);
                    s[rt][nt][e + 2] = tf32r(p1);
                }
            }
        }

        // ---- O += P V (pi-permuted A-frag; V rows (2kq,2kq+1) via float2) ----
#pragma unroll
        for (int kt2 = 0; kt2 < 4; kt2++) {
            uint32_t a0[4], a1[4];
            a0[0] = __float_as_uint(s[0][kt2][0]);
            a0[1] = __float_as_uint(s[0][kt2][2]);
            a0[2] = __float_as_uint(s[0][kt2][1]);
            a0[3] = __float_as_uint(s[0][kt2][3]);
            a1[0] = __float_as_uint(s[1][kt2][0]);
            a1[1] = __float_as_uint(s[1][kt2][2]);
            a1[2] = __float_as_uint(s[1][kt2][1]);
            a1[3] = __float_as_uint(s[1][kt2][3]);
#pragma unroll
            for (int nt2 = 0; nt2 < 4; nt2++) {
                float2 b01 = *(const float2*)&Vsb[(nt2 * 8 + g) * VST + cb + kt2 * 8 + 2 * kq];
                uint32_t b0 = __float_as_uint(b01.x);
                uint32_t b1 = __float_as_uint(b01.y);
                mma_tf32(o[0][nt2], a0, b0, b1);
                mma_tf32(o[1][nt2], a1, b0, b1);
            }
        }
    }

    // ---- reduce l over the 4 kq lanes ----
#pragma unroll
    for (int rt = 0; rt < 2; rt++)
#pragma unroll
        for (int hf = 0; hf < 2; hf++) {
            l[rt][hf] += __shfl_xor_sync(0xffffffffu, l[rt][hf], 1);
            l[rt][hf] += __shfl_xor_sync(0xffffffffu, l[rt][hf], 2);
        }

    // ---- merge split-K halves: O = (O_a + O_b) / (l_a + l_b) ----
    float* Om = sm;   // reuse K region [128][36]
    __syncthreads();
    if (ch == 1) {
#pragma unroll
        for (int rt = 0; rt < 2; rt++) {
            int rb_ = mg + rt * 16;
            Lsm[rb_ + g] = l[rt][0];  Lsm[rb_ + g + 8] = l[rt][1];
#pragma unroll
            for (int nt = 0; nt < 4; nt++) {
                int d0 = nt * 8 + 2 * kq;
                Om[(rb_ + g) * 36 + d0]         = o[rt][nt][0];
                Om[(rb_ + g) * 36 + d0 + 1]     = o[rt][nt][1];
                Om[(rb_ + g + 8) * 36 + d0]     = o[rt][nt][2];
                Om[(rb_ + g + 8) * 36 + d0 + 1] = o[rt][nt][3];
            }
        }
    }
    __syncthreads();
    if (ch == 0) {
#pragma unroll
        for (int rt = 0; rt < 2; rt++) {
            int rb_ = mg + rt * 16;
            float iL0 = 1.0f / (l[rt][0] + Lsm[rb_ + g]);
            float iL1 = 1.0f / (l[rt][1] + Lsm[rb_ + g + 8]);
#pragma unroll
            for (int nt = 0; nt < 4; nt++) {
                int d0 = nt * 8 + 2 * kq;
                Om[(rb_ + g) * 36 + d0]         = (o[rt][nt][0] + Om[(rb_ + g) * 36 + d0])     * iL0;
                Om[(rb_ + g) * 36 + d0 + 1]     = (o[rt][nt][1] + Om[(rb_ + g) * 36 + d0 + 1]) * iL0;
                Om[(rb_ + g + 8) * 36 + d0]     = (o[rt][nt][2] + Om[(rb_ + g + 8) * 36 + d0])     * iL1;
                Om[(rb_ + g + 8) * 36 + d0 + 1] = (o[rt][nt][3] + Om[(rb_ + g + 8) * 36 + d0 + 1]) * iL1;
            }
        }
    }
    __syncthreads();

    float* go = g_ao + h * HDIM * NN;
    for (int idx = t; idx < 4096; idx += 256) {
        int r = idx & 127, d = idx >> 7;
        go[d * NN + n0 + r] = Om[r * 36 + d];
    }
}

// ---------------------------------------------------------------------------
extern "C" void kernel_launch(void* const* d_in, const int* in_sizes, int n_in,
                              void* d_out, int out_size)
{
    const float* x   = (const float*)d_in[0];
    const float* ow  = (const float*)d_in[1];
    const float* w3  = (const float*)d_in[2];
    const float* w5  = (const float*)d_in[3];
    const float* w7  = (const float*)d_in[4];
    const float* wop = (const float*)d_in[5];
    const float* wq  = (const float*)d_in[6];
    const float* wk  = (const float*)d_in[7];
    const float* wv  = (const float*)d_in[8];
    const float* wo  = (const float*)d_in[9];
    const float* beta = (const float*)d_in[10];
    float* out = (float*)d_out;

    static int smem_set = 0;
    if (!smem_set) {
        cudaFuncSetAttribute(flash_tc11, cudaFuncAttributeMaxDynamicSharedMemorySize,
                             FLASH_SMEM_FLOATS * 4);
        cudaFuncSetAttribute(conv_offset_fused, cudaFuncAttributeMaxDynamicSharedMemorySize,
                             CONV_SMEM_FLOATS * 4);
        smem_set = 1;
    }

    conv_offset_fused<<<dim3(64, 8), 256, CONV_SMEM_FLOATS * 4>>>(x, ow, w3, w5, w7, wop);
    sample_kernel<<<dim3(16, 64), 256>>>(x);
    tcgemm<<<dim3(64, 4, 3), 256>>>(wq, wk, wv, 3, x, nullptr);
    flash_tc11<<<dim3(32, 8), 256, FLASH_SMEM_FLOATS * 4>>>(beta);
    tcgemm<<<dim3(64, 4, 1), 256>>>(wo, nullptr, nullptr, 2, nullptr, out);
}

// round 12
// speedup vs baseline: 5.3344x; 1.2180x over previous
#include <cuda_runtime.h>
#include <math.h>
#include <stdint.h>

// Problem constants
#define HH 64
#define WW 64
#define NN 4096            // H*W
#define CC 256
#define NHEADS 8
#define HDIM 32

// ---------------- scratch (device globals; no allocation allowed) ----------
__device__ float g_part[8 * 2 * NN];
__device__ int   g_ctr[64];
__device__ float g_ixy[2 * NN];
__device__ float g_xs[CC * NN];
__device__ float g_q[CC * NN];   // [d][N], PRE-SCALED by scale*log2e, tf32-rounded
__device__ float g_k[CC * NN];   // TRANSPOSED: [head][N][32], tf32-rounded
__device__ float g_v[CC * NN];   // [d][N], tf32-rounded
__device__ float g_ao[CC * NN];

__device__ __forceinline__ float tf32r(float x) {
    asm("cvt.rna.tf32.f32 %0, %0;" : "+f"(x));
    return x;
}
__device__ __forceinline__ float4 tf32r4(float4 v) {
    v.x = tf32r(v.x); v.y = tf32r(v.y); v.z = tf32r(v.z); v.w = tf32r(v.w);
    return v;
}
__device__ __forceinline__ float ex2f(float x) {
    float y;
    asm("ex2.approx.ftz.f32 %0, %1;" : "=f"(y) : "f"(x));
    return y;
}
__device__ __forceinline__ void mma_tf32(float c[4], const uint32_t a[4],
                                         uint32_t b0, uint32_t b1) {
    asm volatile(
        "mma.sync.aligned.m16n8k8.row.col.f32.tf32.tf32.f32 "
        "{%0,%1,%2,%3},{%4,%5,%6,%7},{%8,%9},{%0,%1,%2,%3};"
        : "+f"(c[0]), "+f"(c[1]), "+f"(c[2]), "+f"(c[3])
        : "r"(a[0]), "r"(a[1]), "r"(a[2]), "r"(a[3]), "r"(b0), "r"(b1));
}
#define CP16(dst, src) \
    asm volatile("cp.async.ca.shared.global [%0], [%1], 16;" \
                 :: "r"(dst), "l"(src))
#define CP_COMMIT() asm volatile("cp.async.commit_group;")
#define CP_WAIT1()  asm volatile("cp.async.wait_group 1;")
#define CP_WAIT0()  asm volatile("cp.async.wait_group 0;")

// scale2 = 32^-0.5 * log2(e), folded into Q at projection time
#define QSCALE2 0.2550434571f

// ---------------------------------------------------------------------------
// Kernel 1: smem-tiled depthwise conv -> relu -> offset proj, fused
// cross-group reduction + coords (last block per pixel row).
// ---------------------------------------------------------------------------
#define CONV_SMEM_FLOATS 17824

__global__ __launch_bounds__(256)
void conv_offset_fused(const float* __restrict__ x,
                       const float* __restrict__ ow,
                       const float* __restrict__ w3,
                       const float* __restrict__ w5,
                       const float* __restrict__ w7,
                       const float* __restrict__ wproj)
{
    extern __shared__ float cs[];
    float* sxt = cs;                 // [32][7][70]
    float* swc = cs + 15680;         // [32][49]
    float* swp = cs + 17248;         // [2][32]
    float* red = cs + 17312;         // [4][2][64]
    __shared__ int isLast;

    int t = threadIdx.x;
    int row = blockIdx.x;
    int cz = blockIdx.y * 32;
    float ow0 = ow[0], ow1 = ow[1], ow2 = ow[2];

    for (int idx = t; idx < 32 * 49; idx += 256) {
        int c = idx / 49, ji = idx % 49;
        int j = ji / 7, i = ji % 7;
        float v = w7[(cz + c) * 49 + ji] * ow2;
        if (j >= 1 && j <= 5 && i >= 1 && i <= 5)
            v += w5[(cz + c) * 25 + (j - 1) * 5 + (i - 1)] * ow1;
        if (j >= 2 && j <= 4 && i >= 2 && i <= 4)
            v += w3[(cz + c) * 9 + (j - 2) * 3 + (i - 2)] * ow0;
        swc[idx] = v;
    }
    if (t < 32) {
        swp[t]      = wproj[cz + t];
        swp[32 + t] = wproj[CC + cz + t];
    }

    for (int idx = t; idx < 15680; idx += 256) {
        int c = idx / 490, r2 = idx % 490;
        int j = r2 / 70, col = r2 % 70 - 3;
        int yy = row + j - 3;
        float v = 0.f;
        if (yy >= 0 && yy < HH && col >= 0 && col < WW)
            v = x[(cz + c) * NN + yy * WW + col];
        sxt[idx] = v;
    }
    __syncthreads();

    int px = t & 63, cg = t >> 6;
    float a0 = 0.f, a1 = 0.f;
#pragma unroll 1
    for (int c8 = 0; c8 < 8; c8++) {
        int c = cg * 8 + c8;
        const float* xc = sxt + c * 490;
        const float* wc = swc + c * 49;
        float feat = 0.f;
#pragma unroll
        for (int j = 0; j < 7; j++)
#pragma unroll
            for (int i = 0; i < 7; i++)
                feat += xc[j * 70 + px + i] * wc[j * 7 + i];
        feat = fmaxf(feat, 0.f);
        a0 += feat * swp[c];
        a1 += feat * swp[32 + c];
    }
    red[(cg * 2 + 0) * 64 + px] = a0;
    red[(cg * 2 + 1) * 64 + px] = a1;
    __syncthreads();

    if (t < 64) {
        float s0 = red[t]      + red[128 + t] + red[256 + t] + red[384 + t];
        float s1 = red[64 + t] + red[192 + t] + red[320 + t] + red[448 + t];
        int p = row * 64 + t;
        g_part[(blockIdx.y * 2 + 0) * NN + p] = s0;
        g_part[(blockIdx.y * 2 + 1) * NN + p] = s1;
    }
    __threadfence();
    __syncthreads();
    if (t == 0) {
        int old = atomicAdd(&g_ctr[row], 1);
        isLast = (old == 7);
    }
    __syncthreads();
    if (isLast) {
        __threadfence();
        if (t < 64) {
            int p = row * 64 + t;
            float offy = 0.f, offx = 0.f;
#pragma unroll
            for (int g = 0; g < 8; g++) {
                offy += g_part[(g * 2 + 0) * NN + p];
                offx += g_part[(g * 2 + 1) * NN + p];
            }
            float refy = ((row + 0.5f) / 63.0f) * 2.0f - 1.0f;
            float refx = ((t + 0.5f) / 63.0f) * 2.0f - 1.0f;
            float gy = fminf(fmaxf(refy + tanhf(offy) * 2.0f, -1.0f), 1.0f);
            float gx = fminf(fmaxf(refx + tanhf(offx) * 2.0f, -1.0f), 1.0f);
            g_ixy[p]      = (gx + 1.0f) * 0.5f * 63.0f;
            g_ixy[NN + p] = (gy + 1.0f) * 0.5f * 63.0f;
        }
        if (t == 0) g_ctr[row] = 0;
    }
}

// ---------------------------------------------------------------------------
// Kernel 2: bilinear grid sample — 4 channels per thread
// ---------------------------------------------------------------------------
__global__ __launch_bounds__(256)
void sample_kernel(const float* __restrict__ x)
{
    int p = blockIdx.x * 256 + threadIdx.x;
    int c0 = blockIdx.y * 4;
    float ix = g_ixy[p], iy = g_ixy[NN + p];
    float x0f = floorf(ix), y0f = floorf(iy);
    float fx = ix - x0f, fy = iy - y0f;
    int x0 = min(max((int)x0f, 0), WW - 1);
    int x1 = min(x0 + 1, WW - 1);
    int y0 = min(max((int)y0f, 0), HH - 1);
    int y1 = min(y0 + 1, HH - 1);
    int i00 = y0 * WW + x0, i01 = y0 * WW + x1;
    int i10 = y1 * WW + x0, i11 = y1 * WW + x1;
    float w00 = (1.f - fx) * (1.f - fy), w01 = fx * (1.f - fy);
    float w10 = (1.f - fx) * fy,         w11 = fx * fy;
#pragma unroll
    for (int cc = 0; cc < 4; cc++) {
        const float* xc = x + (c0 + cc) * NN;
        g_xs[(c0 + cc) * NN + p] = xc[i00] * w00 + xc[i01] * w01
                                 + xc[i10] * w10 + xc[i11] * w11;
    }
}

// ---------------------------------------------------------------------------
// Kernel 3: tf32 tensor-core GEMM  C[256,4096] = A[256,256] * B[256,4096]
// mode 3 z=0: wq@x -> g_q (PRE-SCALED by QSCALE2); z=1: wk@xs -> g_k
// TRANSPOSED; z=2: wv@xs -> g_v.  mode 2: wo@g_ao -> Cext
// ---------------------------------------------------------------------------
__global__ __launch_bounds__(256)
void tcgemm(const float* __restrict__ A0, const float* __restrict__ A1,
            const float* __restrict__ A2, int mode,
            const float* __restrict__ Bext, float* __restrict__ Cext)
{
    const float* A; const float* B; float* C; bool rnd;
    int z = blockIdx.z;
    if (mode == 3) {
        A = (z == 0) ? A0 : (z == 1) ? A1 : A2;
        B = (z == 0) ? Bext : g_xs;
        C = (z == 0) ? g_q : (z == 1) ? g_k : g_v;
        rnd = true;
    } else {
        A = A0; B = g_ao; C = Cext; rnd = false;
    }

    __shared__ float As[2][64][36];
    __shared__ float Bs[2][32][72];

    int t = threadIdx.x, w = t >> 5, lane = t & 31;
    int g = lane >> 2, kq = lane & 3;
    int mg = (w >> 1) * 16, nc = (w & 1) * 32;
    int m0 = blockIdx.y * 64, n0 = blockIdx.x * 64;

    float acc[4][4];
#pragma unroll
    for (int i = 0; i < 4; i++)
#pragma unroll
        for (int j = 0; j < 4; j++) acc[i][j] = 0.f;

    int am[2], ak;  ak = (t & 7) * 4;
    am[0] = t >> 3; am[1] = (t >> 3) + 32;
    int bk[2], bn;  bn = (t & 15) * 4;
    bk[0] = t >> 4; bk[1] = (t >> 4) + 16;

    float4 ra[2], rb[2];
#pragma unroll
    for (int j = 0; j < 2; j++) {
        ra[j] = tf32r4(*(const float4*)&A[(m0 + am[j]) * 256 + ak]);
        rb[j] = tf32r4(*(const float4*)&B[bk[j] * NN + n0 + bn]);
    }

    for (int ki = 0; ki < 8; ki++) {
        int b = ki & 1;
#pragma unroll
        for (int j = 0; j < 2; j++) {
            *(float4*)&As[b][am[j]][ak] = ra[j];
            *(float4*)&Bs[b][bk[j]][bn] = rb[j];
        }
        __syncthreads();
        if (ki < 7) {
            int k0 = (ki + 1) * 32;
#pragma unroll
            for (int j = 0; j < 2; j++) {
                ra[j] = tf32r4(*(const float4*)&A[(m0 + am[j]) * 256 + k0 + ak]);
                rb[j] = tf32r4(*(const float4*)&B[(k0 + bk[j]) * NN + n0 + bn]);
            }
        }
#pragma unroll
        for (int kt = 0; kt < 4; kt++) {
            uint32_t a[4];
            a[0] = __float_as_uint(As[b][mg + g][kt * 8 + kq]);
            a[1] = __float_as_uint(As[b][mg + g + 8][kt * 8 + kq]);
            a[2] = __float_as_uint(As[b][mg + g][kt * 8 + kq + 4]);
            a[3] = __float_as_uint(As[b][mg + g + 8][kt * 8 + kq + 4]);
#pragma unroll
            for (int nt = 0; nt < 4; nt++) {
                uint32_t b0 = __float_as_uint(Bs[b][kt * 8 + kq][nc + nt * 8 + g]);
                uint32_t b1 = __float_as_uint(Bs[b][kt * 8 + kq + 4][nc + nt * 8 + g]);
                mma_tf32(acc[nt], a, b0, b1);
            }
        }
    }

    if (mode == 3 && z == 0) {
        // fold softmax scale * log2e into Q
#pragma unroll
        for (int i = 0; i < 4; i++)
#pragma unroll
            for (int j = 0; j < 4; j++) acc[i][j] *= QSCALE2;
    }
    if (rnd) {
#pragma unroll
        for (int i = 0; i < 4; i++)
#pragma unroll
            for (int j = 0; j < 4; j++) acc[i][j] = tf32r(acc[i][j]);
    }

    if (mode == 3 && z == 1) {
        int m1 = m0 + mg + g, m2 = m1 + 8;
        float* b1p = C + (m1 >> 5) * (NN * 32) + (m1 & 31);
        float* b2p = C + (m2 >> 5) * (NN * 32) + (m2 & 31);
#pragma unroll
        for (int nt = 0; nt < 4; nt++) {
            int col = n0 + nc + nt * 8 + 2 * kq;
            b1p[col * 32]       = acc[nt][0];
            b1p[(col + 1) * 32] = acc[nt][1];
            b2p[col * 32]       = acc[nt][2];
            b2p[(col + 1) * 32] = acc[nt][3];
        }
    } else {
#pragma unroll
        for (int nt = 0; nt < 4; nt++) {
            int col = n0 + nc + nt * 8 + 2 * kq;
            *(float2*)&C[(m0 + mg + g) * NN + col]     = make_float2(acc[nt][0], acc[nt][1]);
            *(float2*)&C[(m0 + mg + g + 8) * NN + col] = make_float2(acc[nt][2], acc[nt][3]);
        }
    }
}

// ---------------------------------------------------------------------------
// Kernel 4: flash attention v12 — FACTORIZED decay bias (exact):
// exp(-(dy+dx)/b) = Ey * Ex.  dx is kb-invariant -> per-thread ExL table
// (32 floats, conflict-free LDS.128); dy is warp-uniform -> 1 broadcast LDS
// per kb.  Q pre-scaled by scale*log2e -> exponent = fma(Ey, ExL, s).
// No M0 (values bounded; normalization exact).
// ---------------------------------------------------------------------------
#define KST 40
#define VST 72
#define KS_STAGE (64 * KST)          // 2560
#define VS_STAGE (32 * VST)          // 2304
#define KS_OFF  0
#define VS_OFF  (3 * KS_STAGE)              // 7680
#define EXS_OFF (VS_OFF + 3 * VS_STAGE)     // 14592 (8 groups x 256 thr x float4)
#define EYL_OFF (EXS_OFF + 8192)            // 22784 (64)
#define LSM_OFF (EYL_OFF + 64)              // 22848 (128)
#define FLASH_SMEM_FLOATS (LSM_OFF + 128)   // 22976

__global__ __launch_bounds__(256, 2)
void flash_tc12(const float* __restrict__ beta_p)
{
    extern __shared__ float sm[];
    float4* ExS4 = (float4*)(sm + EXS_OFF);
    float* EyL = sm + EYL_OFF;
    float* Lsm = sm + LSM_OFF;

    int t = threadIdx.x, w = t >> 5, lane = t & 31;
    int g = lane >> 2, kq = lane & 3;
    int mg = (w & 3) * 32;
    int ch = w >> 2;
    int cb = ch * 32;
    int n0 = blockIdx.x * 128;
    int h  = blockIdx.y;

    const float LOG2E = 1.4426950408889634f;
    float invb = 1.0f / (fabsf(beta_p[0]) + 1e-6f);
    float cdec = invb * LOG2E;

    // Ey LUT: exp(-d/|beta|) for d in 0..63
    if (t < 64) EyL[t] = ex2f(-(float)t * cdec);

    // per-thread Ex table: ExL = exp(-dx/|beta|)*log2e for the 32 slots
    int qyw = (n0 + mg) >> 6;   // warp-uniform row y
#pragma unroll
    for (int rt = 0; rt < 2; rt++) {
#pragma unroll
        for (int nt = 0; nt < 4; nt++) {
            int cc  = cb + nt * 8 + 2 * kq;
            int qxA = (mg + rt * 16 + g) & 63;
            int qxB = (mg + rt * 16 + 8 + g) & 63;
            float4 ex;
            ex.x = ex2f(-(float)abs(qxA - cc)       * cdec) * LOG2E;
            ex.y = ex2f(-(float)abs(qxA - cc - 1)   * cdec) * LOG2E;
            ex.z = ex2f(-(float)abs(qxB - cc)       * cdec) * LOG2E;
            ex.w = ex2f(-(float)abs(qxB - cc - 1)   * cdec) * LOG2E;
            ExS4[(rt * 4 + nt) * 256 + t] = ex;
        }
    }

    const float* gq  = g_q + h * HDIM * NN;   // pre-scaled by QSCALE2
    const float* gkT = g_k + h * (NN * 32);   // [N][32]
    const float* gv  = g_v + h * HDIM * NN;

    // Q fragments with d-permutation (A-slot kq <-> d=kt*8+2kq, kq+4 <-> +1)
    uint32_t qa[2][4][4];
#pragma unroll
    for (int rt = 0; rt < 2; rt++) {
        int base = n0 + mg + rt * 16 + g;
#pragma unroll
        for (int kt = 0; kt < 4; kt++) {
            int dlo = kt * 8 + 2 * kq;
            qa[rt][kt][0] = __float_as_uint(gq[dlo * NN + base]);
            qa[rt][kt][1] = __float_as_uint(gq[dlo * NN + base + 8]);
            qa[rt][kt][2] = __float_as_uint(gq[(dlo + 1) * NN + base]);
            qa[rt][kt][3] = __float_as_uint(gq[(dlo + 1) * NN + base + 8]);
        }
    }

    float o[2][4][4];
#pragma unroll
    for (int rt = 0; rt < 2; rt++)
#pragma unroll
        for (int i = 0; i < 4; i++)
#pragma unroll
            for (int j = 0; j < 4; j++) o[rt][i][j] = 0.f;
    float l[2][2] = {{0.f, 0.f}, {0.f, 0.f}};

    int kr0 = t >> 3,  kc0 = (t & 7) * 4;
    int kr1 = kr0 + 32;
    int vr0 = t >> 4,  vc0 = (t & 15) * 4;
    int vr1 = vr0 + 16;

#define PREFETCH(stage, kcol)                                                  \
    do {                                                                       \
        float* kbase = sm + KS_OFF + (stage) * KS_STAGE;                       \
        float* vbase = sm + VS_OFF + (stage) * VS_STAGE;                       \
        unsigned dk0 = (unsigned)__cvta_generic_to_shared(&kbase[kr0 * KST + kc0]); \
        unsigned dk1 = (unsigned)__cvta_generic_to_shared(&kbase[kr1 * KST + kc0]); \
        unsigned dv0 = (unsigned)__cvta_generic_to_shared(&vbase[vr0 * VST + vc0]); \
        unsigned dv1 = (unsigned)__cvta_generic_to_shared(&vbase[vr1 * VST + vc0]); \
        CP16(dk0, &gkT[((kcol) + kr0) * 32 + kc0]);                            \
        CP16(dk1, &gkT[((kcol) + kr1) * 32 + kc0]);                            \
        CP16(dv0, &gv[vr0 * NN + (kcol) + vc0]);                               \
        CP16(dv1, &gv[vr1 * NN + (kcol) + vc0]);                               \
    } while (0)

    PREFETCH(0, 0);   CP_COMMIT();
    PREFETCH(1, 64);  CP_COMMIT();

    for (int kb = 0; kb < 64; kb++) {
        int st = kb - (kb / 3) * 3;
        if (kb < 63) CP_WAIT1(); else CP_WAIT0();
        __syncthreads();
        if (kb < 62) {
            int st2 = kb + 2; st2 -= (st2 / 3) * 3;
            PREFETCH(st2, (kb + 2) * 64);
            CP_COMMIT();
        }

        const float* Ksb = sm + KS_OFF + st * KS_STAGE;
        const float* Vsb = sm + VS_OFF + st * VS_STAGE;

        // ---- S = Q K^T (Q pre-scaled) ----
        float s[2][4][4];
#pragma unroll
        for (int rt = 0; rt < 2; rt++)
#pragma unroll
            for (int i = 0; i < 4; i++)
#pragma unroll
                for (int j = 0; j < 4; j++) s[rt][i][j] = 0.f;
#pragma unroll
        for (int kt = 0; kt < 4; kt++) {
#pragma unroll
            for (int nt = 0; nt < 4; nt++) {
                float2 kk = *(const float2*)&Ksb[(cb + nt * 8 + g) * KST + kt * 8 + 2 * kq];
                uint32_t b0 = __float_as_uint(kk.x);
                uint32_t b1 = __float_as_uint(kk.y);
                mma_tf32(s[0][nt], qa[0][kt], b0, b1);
                mma_tf32(s[1][nt], qa[1][kt], b0, b1);
            }
        }

        // ---- p = 2^(s + Ey*ExL) ; Ey warp-uniform per kb ----
        float ey = EyL[abs(qyw - kb)];
#pragma unroll
        for (int rt = 0; rt < 2; rt++) {
#pragma unroll
            for (int nt = 0; nt < 4; nt++) {
                float4 ex = ExS4[(rt * 4 + nt) * 256 + t];
                float p0 = ex2f(fmaf(ey, ex.x, s[rt][nt][0]));
                float p1 = ex2f(fmaf(ey, ex.y, s[rt][nt][1]));
                float p2 = ex2f(fmaf(ey, ex.z, s[rt][nt][2]));
                float p3 = ex2f(fmaf(ey, ex.w, s[rt][nt][3]));
                l[rt][0] += p0 + p1;
                l[rt][1] += p2 + p3;
                s[rt][nt][0] = tf32r(p0);
                s[rt][nt][1] = tf32r(p1);
                s[rt][nt][2] = tf32r(p2);
                s[rt][nt][3] = tf32r(p3);
            }
        }

        // ---- O += P V (pi-permuted A-frag; V rows (2kq,2kq+1) via float2) ----
#pragma unroll
        for (int kt2 = 0; kt2 < 4; kt2++) {
            uint32_t a0[4], a1[4];
            a0[0] = __float_as_uint(s[0][kt2][0]);
            a0[1] = __float_as_uint(s[0][kt2][2]);
            a0[2] = __float_as_uint(s[0][kt2][1]);
            a0[3] = __float_as_uint(s[0][kt2][3]);
            a1[0] = __float_as_uint(s[1][kt2][0]);
            a1[1] = __float_as_uint(s[1][kt2][2]);
            a1[2] = __float_as_uint(s[1][kt2][1]);
            a1[3] = __float_as_uint(s[1][kt2][3]);
#pragma unroll
            for (int nt2 = 0; nt2 < 4; nt2++) {
                float2 b01 = *(const float2*)&Vsb[(nt2 * 8 + g) * VST + cb + kt2 * 8 + 2 * kq];
                uint32_t b0 = __float_as_uint(b01.x);
                uint32_t b1 = __float_as_uint(b01.y);
                mma_tf32(o[0][nt2], a0, b0, b1);
                mma_tf32(o[1][nt2], a1, b0, b1);
            }
        }
    }

    // ---- reduce l over the 4 kq lanes ----
#pragma unroll
    for (int rt = 0; rt < 2; rt++)
#pragma unroll
        for (int hf = 0; hf < 2; hf++) {
            l[rt][hf] += __shfl_xor_sync(0xffffffffu, l[rt][hf], 1);
            l[rt][hf] += __shfl_xor_sync(0xffffffffu, l[rt][hf], 2);
        }

    // ---- merge split-K halves: O = (O_a + O_b) / (l_a + l_b) ----
    float* Om = sm;   // reuse K region [128][36]
    __syncthreads();
    if (ch == 1) {
#pragma unroll
        for (int rt = 0; rt < 2; rt++) {
            int rb_ = mg + rt * 16;
            Lsm[rb_ + g] = l[rt][0];  Lsm[rb_ + g + 8] = l[rt][1];
#pragma unroll
            for (int nt = 0; nt < 4; nt++) {
                int d0 = nt * 8 + 2 * kq;
                Om[(rb_ + g) * 36 + d0]         = o[rt][nt][0];
                Om[(rb_ + g) * 36 + d0 + 1]     = o[rt][nt][1];
                Om[(rb_ + g + 8) * 36 + d0]     = o[rt][nt][2];
                Om[(rb_ + g + 8) * 36 + d0 + 1] = o[rt][nt][3];
            }
        }
    }
    __syncthreads();
    if (ch == 0) {
#pragma unroll
        for (int rt = 0; rt < 2; rt++) {
            int rb_ = mg + rt * 16;
            float iL0 = 1.0f / (l[rt][0] + Lsm[rb_ + g]);
            float iL1 = 1.0f / (l[rt][1] + Lsm[rb_ + g + 8]);
#pragma unroll
            for (int nt = 0; nt < 4; nt++) {
                int d0 = nt * 8 + 2 * kq;
                Om[(rb_ + g) * 36 + d0]         = (o[rt][nt][0] + Om[(rb_ + g) * 36 + d0])     * iL0;
                Om[(rb_ + g) * 36 + d0 + 1]     = (o[rt][nt][1] + Om[(rb_ + g) * 36 + d0 + 1]) * iL0;
                Om[(rb_ + g + 8) * 36 + d0]     = (o[rt][nt][2] + Om[(rb_ + g + 8) * 36 + d0])     * iL1;
                Om[(rb_ + g + 8) * 36 + d0 + 1] = (o[rt][nt][3] + Om[(rb_ + g + 8) * 36 + d0 + 1]) * iL1;
            }
        }
    }
    __syncthreads();

    float* go = g_ao + h * HDIM * NN;
    for (int idx = t; idx < 4096; idx += 256) {
        int r = idx & 127, d = idx >> 7;
        go[d * NN + n0 + r] = Om[r * 36 + d];
    }
}

// ---------------------------------------------------------------------------
extern "C" void kernel_launch(void* const* d_in, const int* in_sizes, int n_in,
                              void* d_out, int out_size)
{
    const float* x   = (const float*)d_in[0];
    const float* ow  = (const float*)d_in[1];
    const float* w3  = (const float*)d_in[2];
    const float* w5  = (const float*)d_in[3];
    const float* w7  = (const float*)d_in[4];
    const float* wop = (const float*)d_in[5];
    const float* wq  = (const float*)d_in[6];
    const float* wk  = (const float*)d_in[7];
    const float* wv  = (const float*)d_in[8];
    const float* wo  = (const float*)d_in[9];
    const float* beta = (const float*)d_in[10];
    float* out = (float*)d_out;

    static int smem_set = 0;
    if (!smem_set) {
        cudaFuncSetAttribute(flash_tc12, cudaFuncAttributeMaxDynamicSharedMemorySize,
                             FLASH_SMEM_FLOATS * 4);
        cudaFuncSetAttribute(conv_offset_fused, cudaFuncAttributeMaxDynamicSharedMemorySize,
                             CONV_SMEM_FLOATS * 4);
        smem_set = 1;
    }

    conv_offset_fused<<<dim3(64, 8), 256, CONV_SMEM_FLOATS * 4>>>(x, ow, w3, w5, w7, wop);
    sample_kernel<<<dim3(16, 64), 256>>>(x);
    tcgemm<<<dim3(64, 4, 3), 256>>>(wq, wk, wv, 3, x, nullptr);
    flash_tc12<<<dim3(32, 8), 256, FLASH_SMEM_FLOATS * 4>>>(beta);
    tcgemm<<<dim3(64, 4, 1), 256>>>(wo, nullptr, nullptr, 2, nullptr, out);
}